// round 1
// baseline (speedup 1.0000x reference)
#include <cuda_runtime.h>
#include <math.h>

// Problem constants
#define T_STEPS 64
#define BATCH   64
#define HID     1024
#define EMB     512
#define VOCAB   32000
#define G4      4096        // 4*HID
#define M_ROWS  4032        // (T-1)*BATCH
#define NCHUNK  500         // VOCAB / 64

// ---------------- device scratch (no allocations allowed) ----------------
__device__ float g_pre  [M_ROWS * G4];      // x@W_ih^T + b_ih + b_hh, all steps (66 MB)
__device__ float g_hs   [M_ROWS * HID];     // h for every step (16.5 MB)
__device__ float g_c    [BATCH * HID];      // cell state
__device__ float g_gpart[2 * BATCH * G4];   // split-K partials for recurrent GEMM
__device__ float g_pmax [M_ROWS * NCHUNK];  // per-(row, vocab-chunk) max
__device__ int   g_parg [M_ROWS * NCHUNK];  // per-chunk argmax (global col)
__device__ float g_psum [M_ROWS * NCHUNK];  // per-chunk sum exp(l - chunkmax)
__device__ float g_plab [M_ROWS * NCHUNK];  // label logit if in chunk, else -1e30
__device__ float g_nll  [M_ROWS];

// ---------------- init: copy c0 into mutable cell state ----------------
__global__ void init_c_kernel(const float* __restrict__ c0) {
    int i = blockIdx.x * blockDim.x + threadIdx.x;
    if (i < BATCH * HID) g_c[i] = c0[i];
}

// ---------------- K1: pre-gates GEMM ----------------
// g_pre[m][n] = b_ih[n] + b_hh[n] + sum_e emb[ids[m]][e] * W_ih[n][e]
// M=4032, N=4096, K=512. grid=(63 m-tiles, 64 n-tiles), 256 thr, 64x64 tile, 4x4/thread.
__global__ void pre_gemm_kernel(const int* __restrict__ ot,
                                const float* __restrict__ emb,
                                const float* __restrict__ Wih,
                                const float* __restrict__ bih,
                                const float* __restrict__ bhh) {
    __shared__ float As[16][68];
    __shared__ float Bs[16][68];
    __shared__ int   ids[64];

    const int mblk = blockIdx.x * 64;
    const int nblk = blockIdx.y * 64;
    const int tid  = threadIdx.x;
    const int tx = tid & 15, ty = tid >> 4;

    if (tid < 64) ids[tid] = ot[mblk + tid];
    __syncthreads();

    float acc[4][4];
#pragma unroll
    for (int i = 0; i < 4; i++)
#pragma unroll
        for (int j = 0; j < 4; j++) acc[i][j] = 0.f;

    const int lm  = tid >> 2;          // 0..63
    const int lk4 = (tid & 3) * 4;     // 0,4,8,12

    for (int k0 = 0; k0 < EMB; k0 += 16) {
        float4 av = *(const float4*)(emb + (long)ids[lm] * EMB + k0 + lk4);
        float4 bv = *(const float4*)(Wih + (long)(nblk + lm) * EMB + k0 + lk4);
        As[lk4 + 0][lm] = av.x; As[lk4 + 1][lm] = av.y;
        As[lk4 + 2][lm] = av.z; As[lk4 + 3][lm] = av.w;
        Bs[lk4 + 0][lm] = bv.x; Bs[lk4 + 1][lm] = bv.y;
        Bs[lk4 + 2][lm] = bv.z; Bs[lk4 + 3][lm] = bv.w;
        __syncthreads();
#pragma unroll
        for (int k = 0; k < 16; k++) {
            float a[4], b[4];
            *(float4*)a = *(const float4*)&As[k][ty * 4];
            *(float4*)b = *(const float4*)&Bs[k][tx * 4];
#pragma unroll
            for (int i = 0; i < 4; i++)
#pragma unroll
                for (int j = 0; j < 4; j++) acc[i][j] += a[i] * b[j];
        }
        __syncthreads();
    }

#pragma unroll
    for (int i = 0; i < 4; i++) {
        const long m = mblk + ty * 4 + i;
#pragma unroll
        for (int j = 0; j < 4; j++) {
            const int n = nblk + tx * 4 + j;
            g_pre[m * G4 + n] = acc[i][j] + bih[n] + bhh[n];
        }
    }
}

// ---------------- K2a: recurrent gates GEMM (split-K=2) ----------------
// part[ks][b][n] = sum_{k in half ks} h_prev[b][k] * W_hh[n][k]
// M=64, N=4096 (32-col tiles), K=512 per split. grid=(128, 2), 256 thr, 4x2/thread.
__global__ void gates_gemm_kernel(int t, const float* __restrict__ h0,
                                  const float* __restrict__ Whh) {
    __shared__ float As[16][68];
    __shared__ float Bs[16][36];

    const float* hprev = (t == 0) ? h0 : (g_hs + (long)(t - 1) * BATCH * HID);
    const int nblk   = blockIdx.x * 32;
    const int k_base = blockIdx.y * 512;
    const int tid = threadIdx.x;
    const int tx = tid & 15, ty = tid >> 4;

    float acc[4][2];
#pragma unroll
    for (int i = 0; i < 4; i++) { acc[i][0] = 0.f; acc[i][1] = 0.f; }

    const int lm  = tid >> 2;
    const int lk4 = (tid & 3) * 4;

    for (int k0 = 0; k0 < 512; k0 += 16) {
        float4 av = *(const float4*)(hprev + (long)lm * HID + k_base + k0 + lk4);
        As[lk4 + 0][lm] = av.x; As[lk4 + 1][lm] = av.y;
        As[lk4 + 2][lm] = av.z; As[lk4 + 3][lm] = av.w;
        if (tid < 128) {
            float4 bv = *(const float4*)(Whh + (long)(nblk + lm) * HID + k_base + k0 + lk4);
            Bs[lk4 + 0][lm] = bv.x; Bs[lk4 + 1][lm] = bv.y;
            Bs[lk4 + 2][lm] = bv.z; Bs[lk4 + 3][lm] = bv.w;
        }
        __syncthreads();
#pragma unroll
        for (int k = 0; k < 16; k++) {
            float a[4];
            *(float4*)a = *(const float4*)&As[k][ty * 4];
            const float b0 = Bs[k][tx * 2 + 0];
            const float b1 = Bs[k][tx * 2 + 1];
#pragma unroll
            for (int i = 0; i < 4; i++) {
                acc[i][0] += a[i] * b0;
                acc[i][1] += a[i] * b1;
            }
        }
        __syncthreads();
    }

    float* dst = g_gpart + (long)blockIdx.y * BATCH * G4;
#pragma unroll
    for (int i = 0; i < 4; i++)
#pragma unroll
        for (int j = 0; j < 2; j++)
            dst[(long)(ty * 4 + i) * G4 + nblk + tx * 2 + j] = acc[i][j];
}

// ---------------- K2b: LSTM elementwise update ----------------
__global__ void lstm_update_kernel(int t) {
    const int idx = blockIdx.x * blockDim.x + threadIdx.x;   // 0..65535
    if (idx >= BATCH * HID) return;
    const int b  = idx >> 10;
    const int hh = idx & 1023;

    const float* pre = g_pre + (long)(t * BATCH + b) * G4;
    const float* p0  = g_gpart + (long)b * G4;
    const float* p1  = g_gpart + (long)(BATCH + b) * G4;

    const float gi = pre[hh]        + p0[hh]        + p1[hh];
    const float gf = pre[hh + 1024] + p0[hh + 1024] + p1[hh + 1024];
    const float gg = pre[hh + 2048] + p0[hh + 2048] + p1[hh + 2048];
    const float go = pre[hh + 3072] + p0[hh + 3072] + p1[hh + 3072];

    const float i_ = 1.f / (1.f + expf(-gi));
    const float f_ = 1.f / (1.f + expf(-gf));
    const float g_ = tanhf(gg);
    const float o_ = 1.f / (1.f + expf(-go));

    const float c = f_ * g_c[idx] + i_ * g_;
    g_c[idx] = c;
    g_hs[(long)t * BATCH * HID + idx] = o_ * tanhf(c);
}

// ---------------- K3: logits GEMM fused with softmax stats ----------------
// For each 64-row x 64-vocab tile: compute logits, then per-row chunk
// max/argmax/sumexp/label-logit partials. grid=(63 m-tiles, 500 vocab-tiles).
__global__ void logits_kernel(const float* __restrict__ Wout,
                              const float* __restrict__ bout,
                              const int* __restrict__ ot) {
    __shared__ float As[16][68];
    __shared__ float Bs[16][68];
    __shared__ float rmax[64][17];
    __shared__ int   rarg[64][17];
    __shared__ float rsum[64][17];
    __shared__ float rowmax[64];
    __shared__ float lablog[64];
    __shared__ int   labels_s[64];

    const int mblk = blockIdx.x * 64;
    const int nblk = blockIdx.y * 64;
    const int tid = threadIdx.x;
    const int tx = tid & 15, ty = tid >> 4;

    if (tid < 64) {
        labels_s[tid] = ot[mblk + tid + 64];   // labels = output_tensor[1:T]
        lablog[tid]   = -1e30f;
    }
    __syncthreads();

    float acc[4][4];
#pragma unroll
    for (int i = 0; i < 4; i++)
#pragma unroll
        for (int j = 0; j < 4; j++) acc[i][j] = 0.f;

    const int lm  = tid >> 2;
    const int lk4 = (tid & 3) * 4;

    for (int k0 = 0; k0 < HID; k0 += 16) {
        float4 av = *(const float4*)(g_hs + (long)(mblk + lm) * HID + k0 + lk4);
        float4 bv = *(const float4*)(Wout + (long)(nblk + lm) * HID + k0 + lk4);
        As[lk4 + 0][lm] = av.x; As[lk4 + 1][lm] = av.y;
        As[lk4 + 2][lm] = av.z; As[lk4 + 3][lm] = av.w;
        Bs[lk4 + 0][lm] = bv.x; Bs[lk4 + 1][lm] = bv.y;
        Bs[lk4 + 2][lm] = bv.z; Bs[lk4 + 3][lm] = bv.w;
        __syncthreads();
#pragma unroll
        for (int k = 0; k < 16; k++) {
            float a[4], b[4];
            *(float4*)a = *(const float4*)&As[k][ty * 4];
            *(float4*)b = *(const float4*)&Bs[k][tx * 4];
#pragma unroll
            for (int i = 0; i < 4; i++)
#pragma unroll
                for (int j = 0; j < 4; j++) acc[i][j] += a[i] * b[j];
        }
        __syncthreads();
    }

    // add output bias -> logit values for this 4x4 micro-tile
    float lv[4][4];
    float bj[4];
#pragma unroll
    for (int j = 0; j < 4; j++) bj[j] = bout[nblk + tx * 4 + j];
#pragma unroll
    for (int i = 0; i < 4; i++)
#pragma unroll
        for (int j = 0; j < 4; j++) lv[i][j] = acc[i][j] + bj[j];

    // phase 1: local max/argmax (first-index tie-break) + label capture
#pragma unroll
    for (int i = 0; i < 4; i++) {
        const int row = ty * 4 + i;
        float mv = lv[i][0]; int ma = 0;
#pragma unroll
        for (int j = 1; j < 4; j++)
            if (lv[i][j] > mv) { mv = lv[i][j]; ma = j; }
        rmax[row][tx] = mv;
        rarg[row][tx] = nblk + tx * 4 + ma;

        const int lc = labels_s[row] - nblk;
        if (lc >= 0 && lc < 64 && (lc >> 2) == tx) lablog[row] = lv[i][lc & 3];
    }
    __syncthreads();

    if (tid < 64) {
        float mv = rmax[tid][0]; int ma = rarg[tid][0];
#pragma unroll
        for (int x = 1; x < 16; x++)
            if (rmax[tid][x] > mv) { mv = rmax[tid][x]; ma = rarg[tid][x]; }
        rowmax[tid] = mv;
        const long p = (long)(mblk + tid) * NCHUNK + blockIdx.y;
        g_pmax[p] = mv;
        g_parg[p] = ma;
    }
    __syncthreads();

    // phase 2: sum exp(l - chunkmax)
#pragma unroll
    for (int i = 0; i < 4; i++) {
        const int row = ty * 4 + i;
        const float rm = rowmax[row];
        rsum[row][tx] = expf(lv[i][0] - rm) + expf(lv[i][1] - rm)
                      + expf(lv[i][2] - rm) + expf(lv[i][3] - rm);
    }
    __syncthreads();

    if (tid < 64) {
        float s = 0.f;
#pragma unroll
        for (int x = 0; x < 16; x++) s += rsum[tid][x];
        const long p = (long)(mblk + tid) * NCHUNK + blockIdx.y;
        g_psum[p] = s;
        g_plab[p] = lablog[tid];
    }
}

// ---------------- K4: per-row cross-chunk reduction ----------------
__global__ void reduce_rows_kernel(float* __restrict__ out) {
    const int m = blockIdx.x;
    const int tid = threadIdx.x;
    const long base = (long)m * NCHUNK;

    float mv = -1e30f; int ma = 0x7fffffff;
    for (int c = tid; c < NCHUNK; c += 128) {
        const float v = g_pmax[base + c];
        const int   a = g_parg[base + c];
        if (v > mv || (v == mv && a < ma)) { mv = v; ma = a; }
    }
    __shared__ float sv[128]; __shared__ int sa[128];
    sv[tid] = mv; sa[tid] = ma;
    __syncthreads();
    for (int off = 64; off > 0; off >>= 1) {
        if (tid < off) {
            const float v = sv[tid + off]; const int a = sa[tid + off];
            if (v > sv[tid] || (v == sv[tid] && a < sa[tid])) { sv[tid] = v; sa[tid] = a; }
        }
        __syncthreads();
    }
    const float gmax = sv[0];
    const int   garg = sa[0];
    __syncthreads();

    float ssum = 0.f, lab = -1e30f;
    for (int c = tid; c < NCHUNK; c += 128) {
        ssum += g_psum[base + c] * expf(g_pmax[base + c] - gmax);
        lab = fmaxf(lab, g_plab[base + c]);
    }
    __shared__ float s2[128]; __shared__ float s3[128];
    s2[tid] = ssum; s3[tid] = lab;
    __syncthreads();
    for (int off = 64; off > 0; off >>= 1) {
        if (tid < off) {
            s2[tid] += s2[tid + off];
            s3[tid] = fmaxf(s3[tid], s3[tid + off]);
        }
        __syncthreads();
    }

    if (tid == 0) {
        const float lse = gmax + logf(s2[0]);
        g_nll[m] = lse - s3[0];
        // row m = t*64+b -> result row t+1 -> out[1 + (t+1)*64 + b] = out[65 + m]
        out[65 + m] = (float)garg;
    }
}

// ---------------- K5: loss assembly + first result row ----------------
__global__ void finalize_kernel(const int* __restrict__ ot, float* __restrict__ out) {
    const int tid = threadIdx.x;
    __shared__ float ps[64];
    if (tid < 64) out[1 + tid] = 1.0f;   // result row 0 = ones
    if (tid < 63) {
        float s = 0.f, cnt = 0.f;
        for (int b = 0; b < 64; b++) {
            const int lbl = ot[(tid + 1) * 64 + b];
            if (lbl != 0) { s += g_nll[tid * 64 + b]; cnt += 1.f; }
        }
        ps[tid] = s / fmaxf(cnt, 1.f);
    }
    __syncthreads();
    if (tid == 0) {
        float loss = 0.f;
        for (int t = 0; t < 63; t++) loss += ps[t];
        out[0] = loss;
    }
}

// ---------------- entry point ----------------
extern "C" void kernel_launch(void* const* d_in, const int* in_sizes, int n_in,
                              void* d_out, int out_size) {
    const int*   ot   = (const int*)  d_in[0];   // output_tensor (T,B) int32
    // d_in[1] encoder_hidden_states: unused by reference
    // d_in[2] input_mask: unused except batch size (static)
    const float* h0   = (const float*)d_in[3];   // (1,B,H)
    const float* c0   = (const float*)d_in[4];   // (1,B,H)
    const float* emb  = (const float*)d_in[5];   // (V,E)
    const float* Wih  = (const float*)d_in[6];   // (4H,E)
    const float* Whh  = (const float*)d_in[7];   // (4H,H)
    const float* bih  = (const float*)d_in[8];   // (4H,)
    const float* bhh  = (const float*)d_in[9];   // (4H,)
    const float* Wout = (const float*)d_in[10];  // (V,H)
    const float* bout = (const float*)d_in[11];  // (V,)
    float* out = (float*)d_out;

    init_c_kernel<<<64, 1024>>>(c0);
    pre_gemm_kernel<<<dim3(63, 64), 256>>>(ot, emb, Wih, bih, bhh);

    for (int t = 0; t < 63; t++) {
        gates_gemm_kernel<<<dim3(128, 2), 256>>>(t, h0, Whh);
        lstm_update_kernel<<<256, 256>>>(t);
    }

    logits_kernel<<<dim3(63, 500), 256>>>(Wout, bout, ot);
    reduce_rows_kernel<<<4032, 128>>>(out);
    finalize_kernel<<<1, 64>>>(ot, out);
}

// round 2
// speedup vs baseline: 2.7097x; 2.7097x over previous
#include <cuda_runtime.h>
#include <cuda_fp16.h>
#include <math.h>
#include <stdint.h>

// Problem constants
#define T_STEPS 64
#define BATCH   64
#define HID     1024
#define EMB     512
#define VOCAB   32000
#define G4      4096        // 4*HID
#define M_ROWS  4032        // (T-1)*BATCH
#define NCHUNK  250         // VOCAB / 128

#define SCALE_A 256.0f
#define SCALE_B 1024.0f
#define INV_SCALE (1.0f / (256.0f * 1024.0f))

// ---------------- device scratch (no allocations allowed) ----------------
__device__ float  g_pre  [M_ROWS * G4];      // x@W_ih^T + b_ih + b_hh
__device__ float  g_hs   [M_ROWS * HID];     // h for every step
__device__ float  g_c    [BATCH * HID];      // cell state
__device__ float  g_gpart[2 * BATCH * G4];   // split-K partials
__device__ __half g_Ah   [M_ROWS * HID];     // hi split of 256*hs
__device__ __half g_Al   [M_ROWS * HID];     // lo split
__device__ __half g_Bh   [VOCAB * HID];      // hi split of 1024*W_out
__device__ __half g_Bl   [VOCAB * HID];      // lo split
__device__ float  g_pmax [M_ROWS * NCHUNK];
__device__ int    g_parg [M_ROWS * NCHUNK];
__device__ float  g_psum [M_ROWS * NCHUNK];
__device__ float  g_plab [M_ROWS * NCHUNK];
__device__ float  g_nll  [M_ROWS];

// ---------------- PTX helpers ----------------
__device__ __forceinline__ void cp16(void* dst, const void* src) {
    uint32_t d = (uint32_t)__cvta_generic_to_shared(dst);
    asm volatile("cp.async.cg.shared.global [%0], [%1], 16;\n" :: "r"(d), "l"(src));
}
__device__ __forceinline__ void cp_commit() {
    asm volatile("cp.async.commit_group;\n");
}
template <int N>
__device__ __forceinline__ void cp_wait() {
    asm volatile("cp.async.wait_group %0;\n" :: "n"(N));
}
__device__ __forceinline__ void ldm4(uint32_t& r0, uint32_t& r1, uint32_t& r2, uint32_t& r3,
                                     const void* p) {
    uint32_t a = (uint32_t)__cvta_generic_to_shared(p);
    asm volatile("ldmatrix.sync.aligned.m8n8.x4.shared.b16 {%0,%1,%2,%3}, [%4];\n"
                 : "=r"(r0), "=r"(r1), "=r"(r2), "=r"(r3) : "r"(a));
}
__device__ __forceinline__ void mma16816(float* c, const uint32_t* a, const uint32_t* b) {
    asm volatile("mma.sync.aligned.m16n8k16.row.col.f32.f16.f16.f32 "
                 "{%0,%1,%2,%3}, {%4,%5,%6,%7}, {%8,%9}, {%0,%1,%2,%3};\n"
                 : "+f"(c[0]), "+f"(c[1]), "+f"(c[2]), "+f"(c[3])
                 : "r"(a[0]), "r"(a[1]), "r"(a[2]), "r"(a[3]), "r"(b[0]), "r"(b[1]));
}

// ---------------- init: copy c0 into mutable cell state ----------------
__global__ void init_c_kernel(const float* __restrict__ c0) {
    int i = blockIdx.x * blockDim.x + threadIdx.x;
    if (i < BATCH * HID) g_c[i] = c0[i];
}

// ---------------- split kernels (fp32 -> scaled fp16 hi/lo) ----------------
__global__ void split_w_kernel(const float* __restrict__ Wout) {
    long i = (long)blockIdx.x * blockDim.x + threadIdx.x;
    if (i < (long)VOCAB * HID) {
        float a = Wout[i] * SCALE_B;
        __half h = __float2half_rn(a);
        g_Bh[i] = h;
        g_Bl[i] = __float2half_rn(a - __half2float(h));
    }
}
__global__ void split_hs_kernel() {
    long i = (long)blockIdx.x * blockDim.x + threadIdx.x;
    if (i < (long)M_ROWS * HID) {
        float a = g_hs[i] * SCALE_A;
        __half h = __float2half_rn(a);
        g_Ah[i] = h;
        g_Al[i] = __float2half_rn(a - __half2float(h));
    }
}

// ---------------- K1: pre-gates GEMM (fp32 scalar) ----------------
__global__ void pre_gemm_kernel(const int* __restrict__ ot,
                                const float* __restrict__ emb,
                                const float* __restrict__ Wih,
                                const float* __restrict__ bih,
                                const float* __restrict__ bhh) {
    __shared__ float As[16][68];
    __shared__ float Bs[16][68];
    __shared__ int   ids[64];

    const int mblk = blockIdx.x * 64;
    const int nblk = blockIdx.y * 64;
    const int tid  = threadIdx.x;
    const int tx = tid & 15, ty = tid >> 4;

    if (tid < 64) ids[tid] = ot[mblk + tid];
    __syncthreads();

    float acc[4][4];
#pragma unroll
    for (int i = 0; i < 4; i++)
#pragma unroll
        for (int j = 0; j < 4; j++) acc[i][j] = 0.f;

    const int lm  = tid >> 2;
    const int lk4 = (tid & 3) * 4;

    for (int k0 = 0; k0 < EMB; k0 += 16) {
        float4 av = *(const float4*)(emb + (long)ids[lm] * EMB + k0 + lk4);
        float4 bv = *(const float4*)(Wih + (long)(nblk + lm) * EMB + k0 + lk4);
        As[lk4 + 0][lm] = av.x; As[lk4 + 1][lm] = av.y;
        As[lk4 + 2][lm] = av.z; As[lk4 + 3][lm] = av.w;
        Bs[lk4 + 0][lm] = bv.x; Bs[lk4 + 1][lm] = bv.y;
        Bs[lk4 + 2][lm] = bv.z; Bs[lk4 + 3][lm] = bv.w;
        __syncthreads();
#pragma unroll
        for (int k = 0; k < 16; k++) {
            float a[4], b[4];
            *(float4*)a = *(const float4*)&As[k][ty * 4];
            *(float4*)b = *(const float4*)&Bs[k][tx * 4];
#pragma unroll
            for (int i = 0; i < 4; i++)
#pragma unroll
                for (int j = 0; j < 4; j++) acc[i][j] += a[i] * b[j];
        }
        __syncthreads();
    }

#pragma unroll
    for (int i = 0; i < 4; i++) {
        const long m = mblk + ty * 4 + i;
#pragma unroll
        for (int j = 0; j < 4; j++) {
            const int n = nblk + tx * 4 + j;
            g_pre[m * G4 + n] = acc[i][j] + bih[n] + bhh[n];
        }
    }
}

// ---------------- K2a: recurrent gates GEMM (split-K=2, fp32 scalar) ----------------
__global__ void gates_gemm_kernel(int t, const float* __restrict__ h0,
                                  const float* __restrict__ Whh) {
    __shared__ float As[16][68];
    __shared__ float Bs[16][36];

    const float* hprev = (t == 0) ? h0 : (g_hs + (long)(t - 1) * BATCH * HID);
    const int nblk   = blockIdx.x * 32;
    const int k_base = blockIdx.y * 512;
    const int tid = threadIdx.x;
    const int tx = tid & 15, ty = tid >> 4;

    float acc[4][2];
#pragma unroll
    for (int i = 0; i < 4; i++) { acc[i][0] = 0.f; acc[i][1] = 0.f; }

    const int lm  = tid >> 2;
    const int lk4 = (tid & 3) * 4;

    for (int k0 = 0; k0 < 512; k0 += 16) {
        float4 av = *(const float4*)(hprev + (long)lm * HID + k_base + k0 + lk4);
        As[lk4 + 0][lm] = av.x; As[lk4 + 1][lm] = av.y;
        As[lk4 + 2][lm] = av.z; As[lk4 + 3][lm] = av.w;
        if (tid < 128) {
            float4 bv = *(const float4*)(Whh + (long)(nblk + lm) * HID + k_base + k0 + lk4);
            Bs[lk4 + 0][lm] = bv.x; Bs[lk4 + 1][lm] = bv.y;
            Bs[lk4 + 2][lm] = bv.z; Bs[lk4 + 3][lm] = bv.w;
        }
        __syncthreads();
#pragma unroll
        for (int k = 0; k < 16; k++) {
            float a[4];
            *(float4*)a = *(const float4*)&As[k][ty * 4];
            const float b0 = Bs[k][tx * 2 + 0];
            const float b1 = Bs[k][tx * 2 + 1];
#pragma unroll
            for (int i = 0; i < 4; i++) {
                acc[i][0] += a[i] * b0;
                acc[i][1] += a[i] * b1;
            }
        }
        __syncthreads();
    }

    float* dst = g_gpart + (long)blockIdx.y * BATCH * G4;
#pragma unroll
    for (int i = 0; i < 4; i++)
#pragma unroll
        for (int j = 0; j < 2; j++)
            dst[(long)(ty * 4 + i) * G4 + nblk + tx * 2 + j] = acc[i][j];
}

// ---------------- K2b: LSTM elementwise update ----------------
__global__ void lstm_update_kernel(int t) {
    const int idx = blockIdx.x * blockDim.x + threadIdx.x;
    if (idx >= BATCH * HID) return;
    const int b  = idx >> 10;
    const int hh = idx & 1023;

    const float* pre = g_pre + (long)(t * BATCH + b) * G4;
    const float* p0  = g_gpart + (long)b * G4;
    const float* p1  = g_gpart + (long)(BATCH + b) * G4;

    const float gi = pre[hh]        + p0[hh]        + p1[hh];
    const float gf = pre[hh + 1024] + p0[hh + 1024] + p1[hh + 1024];
    const float gg = pre[hh + 2048] + p0[hh + 2048] + p1[hh + 2048];
    const float go = pre[hh + 3072] + p0[hh + 3072] + p1[hh + 3072];

    const float i_ = 1.f / (1.f + expf(-gi));
    const float f_ = 1.f / (1.f + expf(-gf));
    const float g_ = tanhf(gg);
    const float o_ = 1.f / (1.f + expf(-go));

    const float c = f_ * g_c[idx] + i_ * g_;
    g_c[idx] = c;
    g_hs[(long)t * BATCH * HID + idx] = o_ * tanhf(c);
}

// ---------------- K3: logits GEMM via fp16-split mma.sync, fused softmax stats --------
// Block tile 64(M) x 128(N), K=1024.  8 warps in 2(M) x 4(N) grid, warp tile 32x32.
// 4 products (Ah*Bh + Ah*Bl + Al*Bh + Al*Bl) accumulate into the same fp32 acc.
__global__ __launch_bounds__(256, 2)
void logits_mma_kernel(const float* __restrict__ bout, const int* __restrict__ ot) {
    __shared__ __align__(16) __half As_h[2][64][24];
    __shared__ __align__(16) __half As_l[2][64][24];
    __shared__ __align__(16) __half Bs_h[2][128][24];
    __shared__ __align__(16) __half Bs_l[2][128][24];
    __shared__ float wmax[64][4];
    __shared__ int   warg[64][4];
    __shared__ float wsum[64][4];
    __shared__ float wlab[64][4];
    __shared__ float rowmax_s[64];
    __shared__ int   labels_s[64];

    const int tid   = threadIdx.x;
    const int lane  = tid & 31;
    const int warp  = tid >> 5;
    const int wm    = warp >> 2;        // 0..1
    const int wn    = warp & 3;         // 0..3
    const int mblk  = blockIdx.x * 64;
    const int nblk  = blockIdx.y * 128;

    if (tid < 64) labels_s[tid] = ot[64 + mblk + tid];

    // ---- per-thread cp.async chunk assignment (3 chunks of 16B each) ----
    const __half* src[3];
    __half* dst0[3];
    __half* dst1[3];
#pragma unroll
    for (int s = 0; s < 3; s++) {
        int c = tid + s * 256;
        if (c < 128) {
            int row = c >> 1, col = (c & 1) * 8;
            src[s]  = g_Ah + (long)(mblk + row) * HID + col;
            dst0[s] = &As_h[0][row][col]; dst1[s] = &As_h[1][row][col];
        } else if (c < 256) {
            int r = c - 128, row = r >> 1, col = (r & 1) * 8;
            src[s]  = g_Al + (long)(mblk + row) * HID + col;
            dst0[s] = &As_l[0][row][col]; dst1[s] = &As_l[1][row][col];
        } else if (c < 512) {
            int r = c - 256, row = r >> 1, col = (r & 1) * 8;
            src[s]  = g_Bh + (long)(nblk + row) * HID + col;
            dst0[s] = &Bs_h[0][row][col]; dst1[s] = &Bs_h[1][row][col];
        } else {
            int r = c - 512, row = r >> 1, col = (r & 1) * 8;
            src[s]  = g_Bl + (long)(nblk + row) * HID + col;
            dst0[s] = &Bs_l[0][row][col]; dst1[s] = &Bs_l[1][row][col];
        }
    }

    // ---- ldmatrix lane addressing ----
    const int q = lane >> 3, r8 = lane & 7;
    const int rowA = (q & 1) * 8 + r8;       // within 16-row m-tile
    const int colA = (q >> 1) * 8;
    const int rowB = (q >> 1) * 8 + r8;      // within 16-row n-slab
    const int colB = (q & 1) * 8;

    float acc[2][4][4];
#pragma unroll
    for (int i = 0; i < 2; i++)
#pragma unroll
        for (int j = 0; j < 4; j++)
#pragma unroll
            for (int k = 0; k < 4; k++) acc[i][j][k] = 0.f;

    // ---- prologue: stage 0 ----
#pragma unroll
    for (int s = 0; s < 3; s++) cp16(dst0[s], src[s]);
    cp_commit();

    // ---- main loop over K ----
    for (int kk = 0; kk < 64; kk++) {
        const int st = kk & 1;
        if (kk < 63) {
#pragma unroll
            for (int s = 0; s < 3; s++)
                cp16((kk & 1) ? dst0[s] : dst1[s], src[s] + (kk + 1) * 16);
            cp_commit();
            cp_wait<1>();
        } else {
            cp_wait<0>();
        }
        __syncthreads();

        uint32_t aH[2][4], aL[2][4], bH[4][2], bL[4][2];
#pragma unroll
        for (int i = 0; i < 2; i++) {
            ldm4(aH[i][0], aH[i][1], aH[i][2], aH[i][3],
                 &As_h[st][wm * 32 + i * 16 + rowA][colA]);
            ldm4(aL[i][0], aL[i][1], aL[i][2], aL[i][3],
                 &As_l[st][wm * 32 + i * 16 + rowA][colA]);
        }
#pragma unroll
        for (int j2 = 0; j2 < 2; j2++) {
            ldm4(bH[j2 * 2][0], bH[j2 * 2][1], bH[j2 * 2 + 1][0], bH[j2 * 2 + 1][1],
                 &Bs_h[st][wn * 32 + j2 * 16 + rowB][colB]);
            ldm4(bL[j2 * 2][0], bL[j2 * 2][1], bL[j2 * 2 + 1][0], bL[j2 * 2 + 1][1],
                 &Bs_l[st][wn * 32 + j2 * 16 + rowB][colB]);
        }
#pragma unroll
        for (int i = 0; i < 2; i++)
#pragma unroll
            for (int j = 0; j < 4; j++) {
                mma16816(acc[i][j], aH[i], bH[j]);
                mma16816(acc[i][j], aH[i], bL[j]);
                mma16816(acc[i][j], aL[i], bH[j]);
                mma16816(acc[i][j], aL[i], bL[j]);
            }
        __syncthreads();
    }

    // ---- epilogue: bias + softmax stats ----
    const int groupRow = lane >> 2;   // 0..7
    const int colPos   = lane & 3;    // 0..3

    float bcol[4][2];
#pragma unroll
    for (int j = 0; j < 4; j++)
#pragma unroll
        for (int kb = 0; kb < 2; kb++)
            bcol[j][kb] = bout[nblk + wn * 32 + j * 8 + colPos * 2 + kb];

    float vals[2][2][4][2];   // [i][half][j][kb]

#pragma unroll
    for (int i = 0; i < 2; i++) {
#pragma unroll
        for (int half = 0; half < 2; half++) {
            const int row_local = wm * 32 + i * 16 + groupRow + half * 8;
            const int lbl = labels_s[row_local];
            float mv = -1e30f; int ma = 0x7fffffff; float lv = -1e30f;
#pragma unroll
            for (int j = 0; j < 4; j++) {
#pragma unroll
                for (int kb = 0; kb < 2; kb++) {
                    const int colg = nblk + wn * 32 + j * 8 + colPos * 2 + kb;
                    const float v = acc[i][j][half * 2 + kb] * INV_SCALE + bcol[j][kb];
                    vals[i][half][j][kb] = v;
                    if (v > mv) { mv = v; ma = colg; }
                    if (colg == lbl) lv = v;
                }
            }
            // reduce across the 4 lanes sharing this row (lane bits 0-1)
#pragma unroll
            for (int m = 1; m < 4; m <<= 1) {
                const float ov = __shfl_xor_sync(0xffffffffu, mv, m);
                const int   oa = __shfl_xor_sync(0xffffffffu, ma, m);
                const float ol = __shfl_xor_sync(0xffffffffu, lv, m);
                if (ov > mv || (ov == mv && oa < ma)) { mv = ov; ma = oa; }
                lv = fmaxf(lv, ol);
            }
            if (colPos == 0) {
                wmax[row_local][wn] = mv;
                warg[row_local][wn] = ma;
                wlab[row_local][wn] = lv;
            }
        }
    }
    __syncthreads();

    if (tid < 64) {
        float mv = wmax[tid][0]; int ma = warg[tid][0]; float lv = wlab[tid][0];
#pragma unroll
        for (int x = 1; x < 4; x++) {
            const float v = wmax[tid][x]; const int a = warg[tid][x];
            if (v > mv || (v == mv && a < ma)) { mv = v; ma = a; }
            lv = fmaxf(lv, wlab[tid][x]);
        }
        rowmax_s[tid] = mv;
        const long p = (long)(mblk + tid) * NCHUNK + blockIdx.y;
        g_pmax[p] = mv;
        g_parg[p] = ma;
        g_plab[p] = lv;
    }
    __syncthreads();

#pragma unroll
    for (int i = 0; i < 2; i++) {
#pragma unroll
        for (int half = 0; half < 2; half++) {
            const int row_local = wm * 32 + i * 16 + groupRow + half * 8;
            const float rm = rowmax_s[row_local];
            float s = 0.f;
#pragma unroll
            for (int j = 0; j < 4; j++)
#pragma unroll
                for (int kb = 0; kb < 2; kb++)
                    s += expf(vals[i][half][j][kb] - rm);
#pragma unroll
            for (int m = 1; m < 4; m <<= 1)
                s += __shfl_xor_sync(0xffffffffu, s, m);
            if (colPos == 0) wsum[row_local][wn] = s;
        }
    }
    __syncthreads();

    if (tid < 64) {
        float s = wsum[tid][0] + wsum[tid][1] + wsum[tid][2] + wsum[tid][3];
        g_psum[(long)(mblk + tid) * NCHUNK + blockIdx.y] = s;
    }
}

// ---------------- K4: per-row cross-chunk reduction ----------------
__global__ void reduce_rows_kernel(float* __restrict__ out) {
    const int m = blockIdx.x;
    const int tid = threadIdx.x;
    const long base = (long)m * NCHUNK;

    float mv = -1e30f; int ma = 0x7fffffff;
    for (int c = tid; c < NCHUNK; c += 128) {
        const float v = g_pmax[base + c];
        const int   a = g_parg[base + c];
        if (v > mv || (v == mv && a < ma)) { mv = v; ma = a; }
    }
    __shared__ float sv[128]; __shared__ int sa[128];
    sv[tid] = mv; sa[tid] = ma;
    __syncthreads();
    for (int off = 64; off > 0; off >>= 1) {
        if (tid < off) {
            const float v = sv[tid + off]; const int a = sa[tid + off];
            if (v > sv[tid] || (v == sv[tid] && a < sa[tid])) { sv[tid] = v; sa[tid] = a; }
        }
        __syncthreads();
    }
    const float gmax = sv[0];
    const int   garg = sa[0];
    __syncthreads();

    float ssum = 0.f, lab = -1e30f;
    for (int c = tid; c < NCHUNK; c += 128) {
        ssum += g_psum[base + c] * expf(g_pmax[base + c] - gmax);
        lab = fmaxf(lab, g_plab[base + c]);
    }
    __shared__ float s2[128]; __shared__ float s3[128];
    s2[tid] = ssum; s3[tid] = lab;
    __syncthreads();
    for (int off = 64; off > 0; off >>= 1) {
        if (tid < off) {
            s2[tid] += s2[tid + off];
            s3[tid] = fmaxf(s3[tid], s3[tid + off]);
        }
        __syncthreads();
    }

    if (tid == 0) {
        const float lse = gmax + logf(s2[0]);
        g_nll[m] = lse - s3[0];
        out[65 + m] = (float)garg;
    }
}

// ---------------- K5: loss assembly + first result row ----------------
__global__ void finalize_kernel(const int* __restrict__ ot, float* __restrict__ out) {
    const int tid = threadIdx.x;
    __shared__ float ps[64];
    if (tid < 64) out[1 + tid] = 1.0f;
    if (tid < 63) {
        float s = 0.f, cnt = 0.f;
        for (int b = 0; b < 64; b++) {
            const int lbl = ot[(tid + 1) * 64 + b];
            if (lbl != 0) { s += g_nll[tid * 64 + b]; cnt += 1.f; }
        }
        ps[tid] = s / fmaxf(cnt, 1.f);
    }
    __syncthreads();
    if (tid == 0) {
        float loss = 0.f;
        for (int t = 0; t < 63; t++) loss += ps[t];
        out[0] = loss;
    }
}

// ---------------- entry point ----------------
extern "C" void kernel_launch(void* const* d_in, const int* in_sizes, int n_in,
                              void* d_out, int out_size) {
    const int*   ot   = (const int*)  d_in[0];
    const float* h0   = (const float*)d_in[3];
    const float* c0   = (const float*)d_in[4];
    const float* emb  = (const float*)d_in[5];
    const float* Wih  = (const float*)d_in[6];
    const float* Whh  = (const float*)d_in[7];
    const float* bih  = (const float*)d_in[8];
    const float* bhh  = (const float*)d_in[9];
    const float* Wout = (const float*)d_in[10];
    const float* bout = (const float*)d_in[11];
    float* out = (float*)d_out;

    init_c_kernel<<<64, 1024>>>(c0);
    split_w_kernel<<<(VOCAB * HID) / 256, 256>>>(Wout);
    pre_gemm_kernel<<<dim3(63, 64), 256>>>(ot, emb, Wih, bih, bhh);

    for (int t = 0; t < 63; t++) {
        gates_gemm_kernel<<<dim3(128, 2), 256>>>(t, h0, Whh);
        lstm_update_kernel<<<256, 256>>>(t);
    }

    split_hs_kernel<<<(M_ROWS * HID) / 256, 256>>>();
    logits_mma_kernel<<<dim3(63, 250), 256>>>(bout, ot);
    reduce_rows_kernel<<<4032, 128>>>(out);
    finalize_kernel<<<1, 64>>>(ot, out);
}

// round 3
// speedup vs baseline: 3.6290x; 1.3393x over previous
#include <cuda_runtime.h>
#include <cuda_fp16.h>
#include <math.h>
#include <stdint.h>

// Problem constants
#define T_STEPS 64
#define BATCH   64
#define HID     1024
#define EMB     512
#define VOCAB   32000
#define G4      4096
#define M_ROWS  4032
#define NCHUNK  250         // VOCAB / 128
#define NBLK    128         // persistent LSTM blocks (<= SM count, 1 CTA/SM)

#define SCALE_A 256.0f
#define SCALE_B 1024.0f
#define INV_SCALE (1.0f / (256.0f * 1024.0f))

// ---------------- device scratch ----------------
__device__ float  g_pre  [M_ROWS * G4];
__device__ __half g_Ah   [M_ROWS * HID];     // hi split of 256*h per step
__device__ __half g_Al   [M_ROWS * HID];
__device__ __half g_h0h  [BATCH * HID];      // split of 256*h0
__device__ __half g_h0l  [BATCH * HID];
__device__ __half g_Whh_h[G4 * HID];         // hi split of 1024*W_hh
__device__ __half g_Whh_l[G4 * HID];
__device__ __half g_Bh   [VOCAB * HID];      // hi split of 1024*W_out
__device__ __half g_Bl   [VOCAB * HID];
__device__ float  g_pmax [M_ROWS * NCHUNK];
__device__ int    g_parg [M_ROWS * NCHUNK];
__device__ float  g_psum [M_ROWS * NCHUNK];
__device__ float  g_plab [M_ROWS * NCHUNK];
__device__ float  g_nll  [M_ROWS];
__device__ unsigned g_bar;

// ---------------- PTX helpers ----------------
__device__ __forceinline__ void cp16(void* dst, const void* src) {
    uint32_t d = (uint32_t)__cvta_generic_to_shared(dst);
    asm volatile("cp.async.cg.shared.global [%0], [%1], 16;\n" :: "r"(d), "l"(src));
}
__device__ __forceinline__ void cp_commit() {
    asm volatile("cp.async.commit_group;\n");
}
template <int N>
__device__ __forceinline__ void cp_wait() {
    asm volatile("cp.async.wait_group %0;\n" :: "n"(N));
}
__device__ __forceinline__ void ldm4(uint32_t& r0, uint32_t& r1, uint32_t& r2, uint32_t& r3,
                                     const void* p) {
    uint32_t a = (uint32_t)__cvta_generic_to_shared(p);
    asm volatile("ldmatrix.sync.aligned.m8n8.x4.shared.b16 {%0,%1,%2,%3}, [%4];\n"
                 : "=r"(r0), "=r"(r1), "=r"(r2), "=r"(r3) : "r"(a));
}
__device__ __forceinline__ void mma16816(float* c, const uint32_t* a, const uint32_t* b) {
    asm volatile("mma.sync.aligned.m16n8k16.row.col.f32.f16.f16.f32 "
                 "{%0,%1,%2,%3}, {%4,%5,%6,%7}, {%8,%9}, {%0,%1,%2,%3};\n"
                 : "+f"(c[0]), "+f"(c[1]), "+f"(c[2]), "+f"(c[3])
                 : "r"(a[0]), "r"(a[1]), "r"(a[2]), "r"(a[3]), "r"(b[0]), "r"(b[1]));
}

// ---------------- init: reset barrier + split h0 ----------------
__global__ void init_kernel(const float* __restrict__ h0) {
    int i = blockIdx.x * blockDim.x + threadIdx.x;
    if (i == 0) g_bar = 0u;
    if (i < BATCH * HID) {
        float a = h0[i] * SCALE_A;
        __half h = __float2half_rn(a);
        g_h0h[i] = h;
        g_h0l[i] = __float2half_rn(a - __half2float(h));
    }
}

// ---------------- split kernels ----------------
__global__ void split_w_kernel(const float* __restrict__ Wout) {
    long i = (long)blockIdx.x * blockDim.x + threadIdx.x;
    if (i < (long)VOCAB * HID) {
        float a = Wout[i] * SCALE_B;
        __half h = __float2half_rn(a);
        g_Bh[i] = h;
        g_Bl[i] = __float2half_rn(a - __half2float(h));
    }
}
__global__ void split_whh_kernel(const float* __restrict__ Whh) {
    long i = (long)blockIdx.x * blockDim.x + threadIdx.x;
    if (i < (long)G4 * HID) {
        float a = Whh[i] * SCALE_B;
        __half h = __float2half_rn(a);
        g_Whh_h[i] = h;
        g_Whh_l[i] = __float2half_rn(a - __half2float(h));
    }
}

// ---------------- K1: pre-gates GEMM (fp32 scalar) ----------------
__global__ void pre_gemm_kernel(const int* __restrict__ ot,
                                const float* __restrict__ emb,
                                const float* __restrict__ Wih,
                                const float* __restrict__ bih,
                                const float* __restrict__ bhh) {
    __shared__ float As[16][68];
    __shared__ float Bs[16][68];
    __shared__ int   ids[64];

    const int mblk = blockIdx.x * 64;
    const int nblk = blockIdx.y * 64;
    const int tid  = threadIdx.x;
    const int tx = tid & 15, ty = tid >> 4;

    if (tid < 64) ids[tid] = ot[mblk + tid];
    __syncthreads();

    float acc[4][4];
#pragma unroll
    for (int i = 0; i < 4; i++)
#pragma unroll
        for (int j = 0; j < 4; j++) acc[i][j] = 0.f;

    const int lm  = tid >> 2;
    const int lk4 = (tid & 3) * 4;

    for (int k0 = 0; k0 < EMB; k0 += 16) {
        float4 av = *(const float4*)(emb + (long)ids[lm] * EMB + k0 + lk4);
        float4 bv = *(const float4*)(Wih + (long)(nblk + lm) * EMB + k0 + lk4);
        As[lk4 + 0][lm] = av.x; As[lk4 + 1][lm] = av.y;
        As[lk4 + 2][lm] = av.z; As[lk4 + 3][lm] = av.w;
        Bs[lk4 + 0][lm] = bv.x; Bs[lk4 + 1][lm] = bv.y;
        Bs[lk4 + 2][lm] = bv.z; Bs[lk4 + 3][lm] = bv.w;
        __syncthreads();
#pragma unroll
        for (int k = 0; k < 16; k++) {
            float a[4], b[4];
            *(float4*)a = *(const float4*)&As[k][ty * 4];
            *(float4*)b = *(const float4*)&Bs[k][tx * 4];
#pragma unroll
            for (int i = 0; i < 4; i++)
#pragma unroll
                for (int j = 0; j < 4; j++) acc[i][j] += a[i] * b[j];
        }
        __syncthreads();
    }

#pragma unroll
    for (int i = 0; i < 4; i++) {
        const long m = mblk + ty * 4 + i;
#pragma unroll
        for (int j = 0; j < 4; j++) {
            const int n = nblk + tx * 4 + j;
            g_pre[m * G4 + n] = acc[i][j] + bih[n] + bhh[n];
        }
    }
}

// ---------------- K2: persistent LSTM (all 63 steps, one kernel) ----------------
// 128 blocks, block j owns hidden units [j*8, j*8+8) -> 32 gate columns.
// W_hh slice (fp16 hi/lo) lives in smem for the whole kernel; cell state in smem.
// Per step: mma gates (3-product fp16 split), LSTM update, write split h, grid barrier.
__global__ __launch_bounds__(256, 1)
void lstm_persistent_kernel(const float* __restrict__ c0) {
    extern __shared__ __align__(16) char smem[];
    // carve: Ws_h[32][1032], Ws_l[32][1032], Hs[2buf][2split][64][72], Gs[64][33], Cs[512]
    __half* Ws_h = (__half*)smem;
    __half* Ws_l = Ws_h + 32 * 1032;
    __half* Hs   = Ws_l + 32 * 1032;
    float*  Gs   = (float*)(Hs + 2 * 2 * 64 * 72);
    float*  Cs   = Gs + 64 * 33;

    const int tid  = threadIdx.x;
    const int lane = tid & 31;
    const int warp = tid >> 5;
    const int mw   = warp & 3;          // m-tile (16 batch rows)
    const int nh   = warp >> 2;         // n-half (16 gate cols)
    const int blk  = blockIdx.x;

    // ---- load W_hh slice into smem (once) ----
    for (int c = tid; c < 8192; c += 256) {
        const int split = c >> 12;              // 0=hi, 1=lo
        const int rr    = (c >> 7) & 31;        // local gate row 0..31
        const int seg   = c & 127;              // 16B segment
        const long nglob = (long)((rr >> 3) * 1024 + blk * 8 + (rr & 7));
        const __half* src = (split ? g_Whh_l : g_Whh_h) + nglob * HID + seg * 8;
        float4 v = *(const float4*)src;
        *(float4*)((split ? Ws_l : Ws_h) + rr * 1032 + seg * 8) = v;
    }
    // ---- init cell state slice ----
    for (int cell = tid; cell < 512; cell += 256) {
        const int b = cell >> 3, u = cell & 7;
        Cs[cell] = c0[b * HID + blk * 8 + u];
    }
    __syncthreads();

    // ldmatrix lane addressing
    const int q = lane >> 3, r8 = lane & 7;
    const int rowA = (q & 1) * 8 + r8;
    const int colA = (q >> 1) * 8;
    const int rowB = (q >> 1) * 8 + r8;
    const int colB = (q & 1) * 8;
    const int groupRow = lane >> 2;
    const int colPos   = lane & 3;

    for (int t = 0; t < 63; t++) {
        const __half* pAh = t ? (g_Ah + (size_t)(t - 1) * BATCH * HID) : g_h0h;
        const __half* pAl = t ? (g_Al + (size_t)(t - 1) * BATCH * HID) : g_h0l;

        float acc[2][4];
#pragma unroll
        for (int i = 0; i < 2; i++)
#pragma unroll
            for (int k = 0; k < 4; k++) acc[i][k] = 0.f;

        // prologue: chunk 0 -> buf 0
        {
#pragma unroll
            for (int s = 0; s < 4; s++) {
                const int id = tid + 256 * s;
                const int split = id >> 9, r = id & 511, row = r >> 3, seg = r & 7;
                const __half* src = (split ? pAl : pAh) + (size_t)row * HID + seg * 8;
                cp16(Hs + ((0 * 2 + split) * 64 + row) * 72 + seg * 8, src);
            }
            cp_commit();
        }

        for (int c = 0; c < 16; c++) {
            const int buf = c & 1;
            if (c < 15) {
#pragma unroll
                for (int s = 0; s < 4; s++) {
                    const int id = tid + 256 * s;
                    const int split = id >> 9, r = id & 511, row = r >> 3, seg = r & 7;
                    const __half* src = (split ? pAl : pAh) + (size_t)row * HID
                                        + (c + 1) * 64 + seg * 8;
                    cp16(Hs + (((buf ^ 1) * 2 + split) * 64 + row) * 72 + seg * 8, src);
                }
                cp_commit();
                cp_wait<1>();
            } else {
                cp_wait<0>();
            }
            __syncthreads();

#pragma unroll
            for (int k16 = 0; k16 < 4; k16++) {
                uint32_t aH[4], aL[4], bH[2][2], bL[2][2];
                ldm4(aH[0], aH[1], aH[2], aH[3],
                     Hs + ((buf * 2 + 0) * 64 + mw * 16 + rowA) * 72 + k16 * 16 + colA);
                ldm4(aL[0], aL[1], aL[2], aL[3],
                     Hs + ((buf * 2 + 1) * 64 + mw * 16 + rowA) * 72 + k16 * 16 + colA);
                ldm4(bH[0][0], bH[0][1], bH[1][0], bH[1][1],
                     Ws_h + (nh * 16 + rowB) * 1032 + c * 64 + k16 * 16 + colB);
                ldm4(bL[0][0], bL[0][1], bL[1][0], bL[1][1],
                     Ws_l + (nh * 16 + rowB) * 1032 + c * 64 + k16 * 16 + colB);
#pragma unroll
                for (int j = 0; j < 2; j++) {
                    mma16816(acc[j], aH, bH[j]);
                    mma16816(acc[j], aH, bL[j]);
                    mma16816(acc[j], aL, bH[j]);
                }
            }
            __syncthreads();
        }

        // write gates to smem
#pragma unroll
        for (int j = 0; j < 2; j++) {
            const int col = nh * 16 + j * 8 + colPos * 2;
            Gs[(mw * 16 + groupRow) * 33 + col]         = acc[j][0];
            Gs[(mw * 16 + groupRow) * 33 + col + 1]     = acc[j][1];
            Gs[(mw * 16 + groupRow + 8) * 33 + col]     = acc[j][2];
            Gs[(mw * 16 + groupRow + 8) * 33 + col + 1] = acc[j][3];
        }
        __syncthreads();

        // LSTM update for this block's 512 cells
        for (int cell = tid; cell < 512; cell += 256) {
            const int b = cell >> 3, u = cell & 7;
            const float* pre = g_pre + ((size_t)(t * 64 + b)) * G4 + blk * 8 + u;
            const float gi = Gs[b * 33 + u]      * INV_SCALE + pre[0];
            const float gf = Gs[b * 33 + 8 + u]  * INV_SCALE + pre[1024];
            const float gg = Gs[b * 33 + 16 + u] * INV_SCALE + pre[2048];
            const float go = Gs[b * 33 + 24 + u] * INV_SCALE + pre[3072];

            const float i_ = 1.f / (1.f + expf(-gi));
            const float f_ = 1.f / (1.f + expf(-gf));
            const float g_ = tanhf(gg);
            const float o_ = 1.f / (1.f + expf(-go));

            const float cN = f_ * Cs[cell] + i_ * g_;
            Cs[cell] = cN;
            const float h = o_ * tanhf(cN);

            const float a = h * SCALE_A;
            const __half hh = __float2half_rn(a);
            const __half hl = __float2half_rn(a - __half2float(hh));
            const size_t m = ((size_t)(t * 64 + b)) * HID + blk * 8 + u;
            g_Ah[m] = hh;
            g_Al[m] = hl;
        }

        // grid barrier (monotone counter)
        __syncthreads();
        if (tid == 0) {
            __threadfence();
            atomicAdd(&g_bar, 1u);
            volatile unsigned* p = &g_bar;
            const unsigned target = (unsigned)(t + 1) * NBLK;
            while (*p < target) { }
            __threadfence();
        }
        __syncthreads();
    }
}

// ---------------- K3: logits GEMM (fp16 split, 3 products) + fused softmax stats ------
__global__ __launch_bounds__(256, 2)
void logits_mma_kernel(const float* __restrict__ bout, const int* __restrict__ ot) {
    __shared__ __align__(16) __half As_h[2][64][24];
    __shared__ __align__(16) __half As_l[2][64][24];
    __shared__ __align__(16) __half Bs_h[2][128][24];
    __shared__ __align__(16) __half Bs_l[2][128][24];
    __shared__ float wmax[64][4];
    __shared__ int   warg[64][4];
    __shared__ float wsum[64][4];
    __shared__ float wlab[64][4];
    __shared__ float rowmax_s[64];
    __shared__ int   labels_s[64];

    const int tid   = threadIdx.x;
    const int lane  = tid & 31;
    const int warp  = tid >> 5;
    const int wm    = warp >> 2;
    const int wn    = warp & 3;
    const int mblk  = blockIdx.x * 64;
    const int nblk  = blockIdx.y * 128;

    if (tid < 64) labels_s[tid] = ot[64 + mblk + tid];

    const __half* src[3];
    __half* dst0[3];
    __half* dst1[3];
#pragma unroll
    for (int s = 0; s < 3; s++) {
        int c = tid + s * 256;
        if (c < 128) {
            int row = c >> 1, col = (c & 1) * 8;
            src[s]  = g_Ah + (long)(mblk + row) * HID + col;
            dst0[s] = &As_h[0][row][col]; dst1[s] = &As_h[1][row][col];
        } else if (c < 256) {
            int r = c - 128, row = r >> 1, col = (r & 1) * 8;
            src[s]  = g_Al + (long)(mblk + row) * HID + col;
            dst0[s] = &As_l[0][row][col]; dst1[s] = &As_l[1][row][col];
        } else if (c < 512) {
            int r = c - 256, row = r >> 1, col = (r & 1) * 8;
            src[s]  = g_Bh + (long)(nblk + row) * HID + col;
            dst0[s] = &Bs_h[0][row][col]; dst1[s] = &Bs_h[1][row][col];
        } else {
            int r = c - 512, row = r >> 1, col = (r & 1) * 8;
            src[s]  = g_Bl + (long)(nblk + row) * HID + col;
            dst0[s] = &Bs_l[0][row][col]; dst1[s] = &Bs_l[1][row][col];
        }
    }

    const int q = lane >> 3, r8 = lane & 7;
    const int rowA = (q & 1) * 8 + r8;
    const int colA = (q >> 1) * 8;
    const int rowB = (q >> 1) * 8 + r8;
    const int colB = (q & 1) * 8;

    float acc[2][4][4];
#pragma unroll
    for (int i = 0; i < 2; i++)
#pragma unroll
        for (int j = 0; j < 4; j++)
#pragma unroll
            for (int k = 0; k < 4; k++) acc[i][j][k] = 0.f;

#pragma unroll
    for (int s = 0; s < 3; s++) cp16(dst0[s], src[s]);
    cp_commit();

    for (int kk = 0; kk < 64; kk++) {
        const int st = kk & 1;
        if (kk < 63) {
#pragma unroll
            for (int s = 0; s < 3; s++)
                cp16((kk & 1) ? dst0[s] : dst1[s], src[s] + (kk + 1) * 16);
            cp_commit();
            cp_wait<1>();
        } else {
            cp_wait<0>();
        }
        __syncthreads();

        uint32_t aH[2][4], aL[2][4], bH[4][2], bL[4][2];
#pragma unroll
        for (int i = 0; i < 2; i++) {
            ldm4(aH[i][0], aH[i][1], aH[i][2], aH[i][3],
                 &As_h[st][wm * 32 + i * 16 + rowA][colA]);
            ldm4(aL[i][0], aL[i][1], aL[i][2], aL[i][3],
                 &As_l[st][wm * 32 + i * 16 + rowA][colA]);
        }
#pragma unroll
        for (int j2 = 0; j2 < 2; j2++) {
            ldm4(bH[j2 * 2][0], bH[j2 * 2][1], bH[j2 * 2 + 1][0], bH[j2 * 2 + 1][1],
                 &Bs_h[st][wn * 32 + j2 * 16 + rowB][colB]);
            ldm4(bL[j2 * 2][0], bL[j2 * 2][1], bL[j2 * 2 + 1][0], bL[j2 * 2 + 1][1],
                 &Bs_l[st][wn * 32 + j2 * 16 + rowB][colB]);
        }
#pragma unroll
        for (int i = 0; i < 2; i++)
#pragma unroll
            for (int j = 0; j < 4; j++) {
                mma16816(acc[i][j], aH[i], bH[j]);
                mma16816(acc[i][j], aH[i], bL[j]);
                mma16816(acc[i][j], aL[i], bH[j]);
            }
        __syncthreads();
    }

    const int groupRow = lane >> 2;
    const int colPos   = lane & 3;

    float bcol[4][2];
#pragma unroll
    for (int j = 0; j < 4; j++)
#pragma unroll
        for (int kb = 0; kb < 2; kb++)
            bcol[j][kb] = bout[nblk + wn * 32 + j * 8 + colPos * 2 + kb];

    float vals[2][2][4][2];

#pragma unroll
    for (int i = 0; i < 2; i++) {
#pragma unroll
        for (int half = 0; half < 2; half++) {
            const int row_local = wm * 32 + i * 16 + groupRow + half * 8;
            const int lbl = labels_s[row_local];
            float mv = -1e30f; int ma = 0x7fffffff; float lv = -1e30f;
#pragma unroll
            for (int j = 0; j < 4; j++) {
#pragma unroll
                for (int kb = 0; kb < 2; kb++) {
                    const int colg = nblk + wn * 32 + j * 8 + colPos * 2 + kb;
                    const float v = acc[i][j][half * 2 + kb] * INV_SCALE + bcol[j][kb];
                    vals[i][half][j][kb] = v;
                    if (v > mv) { mv = v; ma = colg; }
                    if (colg == lbl) lv = v;
                }
            }
#pragma unroll
            for (int m = 1; m < 4; m <<= 1) {
                const float ov = __shfl_xor_sync(0xffffffffu, mv, m);
                const int   oa = __shfl_xor_sync(0xffffffffu, ma, m);
                const float ol = __shfl_xor_sync(0xffffffffu, lv, m);
                if (ov > mv || (ov == mv && oa < ma)) { mv = ov; ma = oa; }
                lv = fmaxf(lv, ol);
            }
            if (colPos == 0) {
                wmax[row_local][wn] = mv;
                warg[row_local][wn] = ma;
                wlab[row_local][wn] = lv;
            }
        }
    }
    __syncthreads();

    if (tid < 64) {
        float mv = wmax[tid][0]; int ma = warg[tid][0]; float lv = wlab[tid][0];
#pragma unroll
        for (int x = 1; x < 4; x++) {
            const float v = wmax[tid][x]; const int a = warg[tid][x];
            if (v > mv || (v == mv && a < ma)) { mv = v; ma = a; }
            lv = fmaxf(lv, wlab[tid][x]);
        }
        rowmax_s[tid] = mv;
        const long p = (long)(mblk + tid) * NCHUNK + blockIdx.y;
        g_pmax[p] = mv;
        g_parg[p] = ma;
        g_plab[p] = lv;
    }
    __syncthreads();

#pragma unroll
    for (int i = 0; i < 2; i++) {
#pragma unroll
        for (int half = 0; half < 2; half++) {
            const int row_local = wm * 32 + i * 16 + groupRow + half * 8;
            const float rm = rowmax_s[row_local];
            float s = 0.f;
#pragma unroll
            for (int j = 0; j < 4; j++)
#pragma unroll
                for (int kb = 0; kb < 2; kb++)
                    s += expf(vals[i][half][j][kb] - rm);
#pragma unroll
            for (int m = 1; m < 4; m <<= 1)
                s += __shfl_xor_sync(0xffffffffu, s, m);
            if (colPos == 0) wsum[row_local][wn] = s;
        }
    }
    __syncthreads();

    if (tid < 64) {
        float s = wsum[tid][0] + wsum[tid][1] + wsum[tid][2] + wsum[tid][3];
        g_psum[(long)(mblk + tid) * NCHUNK + blockIdx.y] = s;
    }
}

// ---------------- K4: per-row cross-chunk reduction ----------------
__global__ void reduce_rows_kernel(float* __restrict__ out) {
    const int m = blockIdx.x;
    const int tid = threadIdx.x;
    const long base = (long)m * NCHUNK;

    float mv = -1e30f; int ma = 0x7fffffff;
    for (int c = tid; c < NCHUNK; c += 128) {
        const float v = g_pmax[base + c];
        const int   a = g_parg[base + c];
        if (v > mv || (v == mv && a < ma)) { mv = v; ma = a; }
    }
    __shared__ float sv[128]; __shared__ int sa[128];
    sv[tid] = mv; sa[tid] = ma;
    __syncthreads();
    for (int off = 64; off > 0; off >>= 1) {
        if (tid < off) {
            const float v = sv[tid + off]; const int a = sa[tid + off];
            if (v > sv[tid] || (v == sv[tid] && a < sa[tid])) { sv[tid] = v; sa[tid] = a; }
        }
        __syncthreads();
    }
    const float gmax = sv[0];
    const int   garg = sa[0];
    __syncthreads();

    float ssum = 0.f, lab = -1e30f;
    for (int c = tid; c < NCHUNK; c += 128) {
        ssum += g_psum[base + c] * expf(g_pmax[base + c] - gmax);
        lab = fmaxf(lab, g_plab[base + c]);
    }
    __shared__ float s2[128]; __shared__ float s3[128];
    s2[tid] = ssum; s3[tid] = lab;
    __syncthreads();
    for (int off = 64; off > 0; off >>= 1) {
        if (tid < off) {
            s2[tid] += s2[tid + off];
            s3[tid] = fmaxf(s3[tid], s3[tid + off]);
        }
        __syncthreads();
    }

    if (tid == 0) {
        const float lse = gmax + logf(s2[0]);
        g_nll[m] = lse - s3[0];
        out[65 + m] = (float)garg;
    }
}

// ---------------- K5: loss assembly + first result row ----------------
__global__ void finalize_kernel(const int* __restrict__ ot, float* __restrict__ out) {
    const int tid = threadIdx.x;
    __shared__ float ps[64];
    if (tid < 64) out[1 + tid] = 1.0f;
    if (tid < 63) {
        float s = 0.f, cnt = 0.f;
        for (int b = 0; b < 64; b++) {
            const int lbl = ot[(tid + 1) * 64 + b];
            if (lbl != 0) { s += g_nll[tid * 64 + b]; cnt += 1.f; }
        }
        ps[tid] = s / fmaxf(cnt, 1.f);
    }
    __syncthreads();
    if (tid == 0) {
        float loss = 0.f;
        for (int t = 0; t < 63; t++) loss += ps[t];
        out[0] = loss;
    }
}

// ---------------- entry point ----------------
extern "C" void kernel_launch(void* const* d_in, const int* in_sizes, int n_in,
                              void* d_out, int out_size) {
    const int*   ot   = (const int*)  d_in[0];
    const float* h0   = (const float*)d_in[3];
    const float* c0   = (const float*)d_in[4];
    const float* emb  = (const float*)d_in[5];
    const float* Wih  = (const float*)d_in[6];
    const float* Whh  = (const float*)d_in[7];
    const float* bih  = (const float*)d_in[8];
    const float* bhh  = (const float*)d_in[9];
    const float* Wout = (const float*)d_in[10];
    const float* bout = (const float*)d_in[11];
    float* out = (float*)d_out;

    // persistent kernel smem: Ws 2*32*1032*2 + Hs 2*2*64*72*2 + Gs 64*33*4 + Cs 512*4
    const int lstm_smem = 32 * 1032 * 2 * 2 + 2 * 2 * 64 * 72 * 2 + 64 * 33 * 4 + 512 * 4;
    cudaFuncSetAttribute(lstm_persistent_kernel,
                         cudaFuncAttributeMaxDynamicSharedMemorySize, lstm_smem);

    init_kernel<<<64, 1024>>>(h0);
    split_whh_kernel<<<(G4 * HID) / 256, 256>>>(Whh);
    split_w_kernel<<<(VOCAB * HID) / 256, 256>>>(Wout);
    pre_gemm_kernel<<<dim3(63, 64), 256>>>(ot, emb, Wih, bih, bhh);

    lstm_persistent_kernel<<<NBLK, 256, lstm_smem>>>(c0);

    logits_mma_kernel<<<dim3(63, 250), 256>>>(bout, ot);
    reduce_rows_kernel<<<4032, 128>>>(out);
    finalize_kernel<<<1, 64>>>(ot, out);
}

// round 4
// speedup vs baseline: 4.0200x; 1.1077x over previous
#include <cuda_runtime.h>
#include <cuda_fp16.h>
#include <math.h>
#include <stdint.h>

// Problem constants
#define T_STEPS 64
#define BATCH   64
#define HID     1024
#define EMB     512
#define VOCAB   32000
#define G4      4096
#define M_ROWS  4032
#define NCHUNK  250         // VOCAB / 128
#define NBLK    128         // persistent LSTM blocks (1 CTA/SM)

#define SCALE_A 256.0f
#define SCALE_B 1024.0f
#define INV_SCALE (1.0f / (256.0f * 1024.0f))

// ---------------- device scratch ----------------
__device__ float  g_pre  [M_ROWS * G4];
__device__ __half g_Xh   [M_ROWS * EMB];     // hi split of 256*x (gathered emb rows)
__device__ __half g_Xl   [M_ROWS * EMB];
__device__ __half g_Wih_h[G4 * EMB];         // hi split of 1024*W_ih
__device__ __half g_Wih_l[G4 * EMB];
__device__ __half g_Ah   [M_ROWS * HID];     // hi split of 256*h per step
__device__ __half g_Al   [M_ROWS * HID];
__device__ __half g_h0h  [BATCH * HID];
__device__ __half g_h0l  [BATCH * HID];
__device__ __half g_Whh_h[G4 * HID];         // hi split of 1024*W_hh
__device__ __half g_Whh_l[G4 * HID];
__device__ __half g_Bh   [VOCAB * HID];      // hi split of 1024*W_out
__device__ __half g_Bl   [VOCAB * HID];
__device__ float  g_pmax [M_ROWS * NCHUNK];
__device__ int    g_parg [M_ROWS * NCHUNK];
__device__ float  g_psum [M_ROWS * NCHUNK];
__device__ float  g_plab [M_ROWS * NCHUNK];
__device__ float  g_nll  [M_ROWS];
__device__ unsigned g_bar;

// ---------------- PTX helpers ----------------
__device__ __forceinline__ void cp16(void* dst, const void* src) {
    uint32_t d = (uint32_t)__cvta_generic_to_shared(dst);
    asm volatile("cp.async.cg.shared.global [%0], [%1], 16;\n" :: "r"(d), "l"(src));
}
__device__ __forceinline__ void cp_commit() {
    asm volatile("cp.async.commit_group;\n");
}
template <int N>
__device__ __forceinline__ void cp_wait() {
    asm volatile("cp.async.wait_group %0;\n" :: "n"(N));
}
__device__ __forceinline__ void ldm4(uint32_t& r0, uint32_t& r1, uint32_t& r2, uint32_t& r3,
                                     const void* p) {
    uint32_t a = (uint32_t)__cvta_generic_to_shared(p);
    asm volatile("ldmatrix.sync.aligned.m8n8.x4.shared.b16 {%0,%1,%2,%3}, [%4];\n"
                 : "=r"(r0), "=r"(r1), "=r"(r2), "=r"(r3) : "r"(a));
}
__device__ __forceinline__ void mma16816(float* c, const uint32_t* a, const uint32_t* b) {
    asm volatile("mma.sync.aligned.m16n8k16.row.col.f32.f16.f16.f32 "
                 "{%0,%1,%2,%3}, {%4,%5,%6,%7}, {%8,%9}, {%0,%1,%2,%3};\n"
                 : "+f"(c[0]), "+f"(c[1]), "+f"(c[2]), "+f"(c[3])
                 : "r"(a[0]), "r"(a[1]), "r"(a[2]), "r"(a[3]), "r"(b[0]), "r"(b[1]));
}

// ---------------- init: reset barrier + split h0 ----------------
__global__ void init_kernel(const float* __restrict__ h0) {
    int i = blockIdx.x * blockDim.x + threadIdx.x;
    if (i == 0) g_bar = 0u;
    if (i < BATCH * HID) {
        float a = h0[i] * SCALE_A;
        __half h = __float2half_rn(a);
        g_h0h[i] = h;
        g_h0l[i] = __float2half_rn(a - __half2float(h));
    }
}

// ---------------- split kernels ----------------
__global__ void gather_split_x_kernel(const int* __restrict__ ot,
                                      const float* __restrict__ emb) {
    int i = blockIdx.x * blockDim.x + threadIdx.x;
    if (i >= M_ROWS * EMB) return;
    const int m = i >> 9, e = i & 511;
    float a = emb[(long)ot[m] * EMB + e] * SCALE_A;
    __half h = __float2half_rn(a);
    g_Xh[i] = h;
    g_Xl[i] = __float2half_rn(a - __half2float(h));
}
__global__ void split_wih_kernel(const float* __restrict__ Wih) {
    long i = (long)blockIdx.x * blockDim.x + threadIdx.x;
    if (i < (long)G4 * EMB) {
        float a = Wih[i] * SCALE_B;
        __half h = __float2half_rn(a);
        g_Wih_h[i] = h;
        g_Wih_l[i] = __float2half_rn(a - __half2float(h));
    }
}
__global__ void split_whh_kernel(const float* __restrict__ Whh) {
    long i = (long)blockIdx.x * blockDim.x + threadIdx.x;
    if (i < (long)G4 * HID) {
        float a = Whh[i] * SCALE_B;
        __half h = __float2half_rn(a);
        g_Whh_h[i] = h;
        g_Whh_l[i] = __float2half_rn(a - __half2float(h));
    }
}
__global__ void split_w_kernel(const float* __restrict__ Wout) {
    long i = (long)blockIdx.x * blockDim.x + threadIdx.x;
    if (i < (long)VOCAB * HID) {
        float a = Wout[i] * SCALE_B;
        __half h = __float2half_rn(a);
        g_Bh[i] = h;
        g_Bl[i] = __float2half_rn(a - __half2float(h));
    }
}

// =======================================================================
// K1: pre-gates GEMM via fp16-split mma (3 products). 64M x 128N tile,
// K=512 (32 chunks of 16), 3-stage cp.async pipeline, 1 sync/chunk.
// =======================================================================
#define PRE_SMEM (3 * (1536 + 1536 + 3072 + 3072) * 2)
__global__ __launch_bounds__(256, 2)
void pre_mma_kernel(const float* __restrict__ bih, const float* __restrict__ bhh) {
    extern __shared__ __align__(16) char dsm[];
    __half* As_h = (__half*)dsm;              // 3 * 1536
    __half* As_l = As_h + 3 * 1536;
    __half* Bs_h = As_l + 3 * 1536;           // 3 * 3072
    __half* Bs_l = Bs_h + 3 * 3072;

    const int tid  = threadIdx.x;
    const int lane = tid & 31;
    const int warp = tid >> 5;
    const int wm   = warp >> 2;
    const int wn   = warp & 3;
    const int mblk = blockIdx.x * 64;
    const int nblk = blockIdx.y * 128;

    const __half* src[3];
    __half* arrb[3];
    int off3[3], strd[3];
#pragma unroll
    for (int s = 0; s < 3; s++) {
        int c = tid + s * 256;
        if (c < 128) {
            int row = c >> 1, col = (c & 1) * 8;
            src[s] = g_Xh + (long)(mblk + row) * EMB + col;
            arrb[s] = As_h; off3[s] = row * 24 + col; strd[s] = 1536;
        } else if (c < 256) {
            int r = c - 128, row = r >> 1, col = (r & 1) * 8;
            src[s] = g_Xl + (long)(mblk + row) * EMB + col;
            arrb[s] = As_l; off3[s] = row * 24 + col; strd[s] = 1536;
        } else if (c < 512) {
            int r = c - 256, row = r >> 1, col = (r & 1) * 8;
            src[s] = g_Wih_h + (long)(nblk + row) * EMB + col;
            arrb[s] = Bs_h; off3[s] = row * 24 + col; strd[s] = 3072;
        } else {
            int r = c - 512, row = r >> 1, col = (r & 1) * 8;
            src[s] = g_Wih_l + (long)(nblk + row) * EMB + col;
            arrb[s] = Bs_l; off3[s] = row * 24 + col; strd[s] = 3072;
        }
    }

    const int q = lane >> 3, r8 = lane & 7;
    const int rowA = (q & 1) * 8 + r8;
    const int colA = (q >> 1) * 8;
    const int rowB = (q >> 1) * 8 + r8;
    const int colB = (q & 1) * 8;

    float acc[2][4][4];
#pragma unroll
    for (int i = 0; i < 2; i++)
#pragma unroll
        for (int j = 0; j < 4; j++)
#pragma unroll
            for (int k = 0; k < 4; k++) acc[i][j][k] = 0.f;

    // prologue stages 0,1
#pragma unroll
    for (int p = 0; p < 2; p++) {
#pragma unroll
        for (int s = 0; s < 3; s++)
            cp16(arrb[s] + p * strd[s] + off3[s], src[s] + p * 16);
        cp_commit();
    }

    for (int kk = 0; kk < 32; kk++) {
        if (kk < 31) cp_wait<1>(); else cp_wait<0>();
        __syncthreads();
        if (kk + 2 < 32) {
            const int stg = (kk + 2) % 3;
#pragma unroll
            for (int s = 0; s < 3; s++)
                cp16(arrb[s] + stg * strd[s] + off3[s], src[s] + (kk + 2) * 16);
            cp_commit();
        }
        const int st = kk % 3;

        uint32_t aH[2][4], aL[2][4], bH[4][2], bL[4][2];
#pragma unroll
        for (int i = 0; i < 2; i++) {
            ldm4(aH[i][0], aH[i][1], aH[i][2], aH[i][3],
                 As_h + st * 1536 + (wm * 32 + i * 16 + rowA) * 24 + colA);
            ldm4(aL[i][0], aL[i][1], aL[i][2], aL[i][3],
                 As_l + st * 1536 + (wm * 32 + i * 16 + rowA) * 24 + colA);
        }
#pragma unroll
        for (int j2 = 0; j2 < 2; j2++) {
            ldm4(bH[j2 * 2][0], bH[j2 * 2][1], bH[j2 * 2 + 1][0], bH[j2 * 2 + 1][1],
                 Bs_h + st * 3072 + (wn * 32 + j2 * 16 + rowB) * 24 + colB);
            ldm4(bL[j2 * 2][0], bL[j2 * 2][1], bL[j2 * 2 + 1][0], bL[j2 * 2 + 1][1],
                 Bs_l + st * 3072 + (wn * 32 + j2 * 16 + rowB) * 24 + colB);
        }
#pragma unroll
        for (int i = 0; i < 2; i++)
#pragma unroll
            for (int j = 0; j < 4; j++) {
                mma16816(acc[i][j], aH[i], bH[j]);
                mma16816(acc[i][j], aH[i], bL[j]);
                mma16816(acc[i][j], aL[i], bH[j]);
            }
    }

    // epilogue: scale + biases, direct store
    const int groupRow = lane >> 2;
    const int colPos   = lane & 3;
#pragma unroll
    for (int j = 0; j < 4; j++) {
        const int col = nblk + wn * 32 + j * 8 + colPos * 2;
        const float bb0 = bih[col] + bhh[col];
        const float bb1 = bih[col + 1] + bhh[col + 1];
#pragma unroll
        for (int i = 0; i < 2; i++) {
#pragma unroll
            for (int half = 0; half < 2; half++) {
                const long row = mblk + wm * 32 + i * 16 + groupRow + half * 8;
                float2 v;
                v.x = acc[i][j][half * 2]     * INV_SCALE + bb0;
                v.y = acc[i][j][half * 2 + 1] * INV_SCALE + bb1;
                *(float2*)(g_pre + row * G4 + col) = v;
            }
        }
    }
}

// =======================================================================
// K2: persistent LSTM. 128 blocks, block j owns hidden units [j*8, j*8+8).
// 4-stage cp.async pipeline over 16 K-chunks of 64, one sync per chunk.
// g_pre slice prefetched into smem with chunk 0's group.
// =======================================================================
#define LSTM_SMEM (132096 + 73728 + 8448 + 2048 + 9216)
__global__ __launch_bounds__(256, 1)
void lstm_persistent_kernel(const float* __restrict__ c0) {
    extern __shared__ __align__(16) char smem[];
    __half* Ws_h = (__half*)smem;                 // 32 x 1032
    __half* Ws_l = Ws_h + 32 * 1032;
    __half* Hs   = Ws_l + 32 * 1032;              // 4 stages x 2 splits x 64 x 72
    float*  Gs   = (float*)(Hs + 4 * 2 * 64 * 72);// 64 x 33
    float*  Cs   = Gs + 64 * 33;                  // 512
    float*  Ps   = Cs + 512;                      // 64 x 36 (pre-gates slice)

    const int tid  = threadIdx.x;
    const int lane = tid & 31;
    const int warp = tid >> 5;
    const int mw   = warp & 3;
    const int nh   = warp >> 2;
    const int blk  = blockIdx.x;

    // load W_hh slice into smem (once)
    for (int c = tid; c < 8192; c += 256) {
        const int split = c >> 12;
        const int rr    = (c >> 7) & 31;
        const int seg   = c & 127;
        const long nglob = (long)((rr >> 3) * 1024 + blk * 8 + (rr & 7));
        const __half* srcp = (split ? g_Whh_l : g_Whh_h) + nglob * HID + seg * 8;
        float4 v = *(const float4*)srcp;
        *(float4*)((split ? Ws_l : Ws_h) + rr * 1032 + seg * 8) = v;
    }
    for (int cell = tid; cell < 512; cell += 256) {
        const int b = cell >> 3, u = cell & 7;
        Cs[cell] = c0[b * HID + blk * 8 + u];
    }
    __syncthreads();

    const int q = lane >> 3, r8 = lane & 7;
    const int rowA = (q & 1) * 8 + r8;
    const int colA = (q >> 1) * 8;
    const int rowB = (q >> 1) * 8 + r8;
    const int colB = (q & 1) * 8;
    const int groupRow = lane >> 2;
    const int colPos   = lane & 3;

    for (int t = 0; t < 63; t++) {
        const __half* pAh = t ? (g_Ah + (size_t)(t - 1) * BATCH * HID) : g_h0h;
        const __half* pAl = t ? (g_Al + (size_t)(t - 1) * BATCH * HID) : g_h0l;

        float acc[2][4];
#pragma unroll
        for (int i = 0; i < 2; i++)
#pragma unroll
            for (int k = 0; k < 4; k++) acc[i][k] = 0.f;

        // ---- prologue: chunks 0,1,2 into stages 0,1,2; Ps bundled with chunk 0 ----
#pragma unroll
        for (int pc = 0; pc < 3; pc++) {
#pragma unroll
            for (int s = 0; s < 4; s++) {
                const int id = tid + 256 * s;
                const int split = id >> 9, r = id & 511, row = r >> 3, seg = r & 7;
                const __half* srcp = (split ? pAl : pAh) + (size_t)row * HID
                                     + pc * 64 + seg * 8;
                cp16(Hs + ((pc * 2 + split) * 64 + row) * 72 + seg * 8, srcp);
            }
            if (pc == 0) {
                // pre-gates prefetch: 512 chunks of 16B
#pragma unroll
                for (int s2 = 0; s2 < 2; s2++) {
                    const int cid = tid + 256 * s2;
                    const int b = cid >> 3, r = cid & 7, g = r >> 1, seg = r & 1;
                    cp16(Ps + b * 36 + g * 8 + seg * 4,
                         g_pre + ((size_t)(t * 64 + b)) * G4 + g * 1024 + blk * 8 + seg * 4);
                }
            }
            cp_commit();
        }

        // ---- main loop: 16 chunks, 1 sync each ----
        for (int c = 0; c < 16; c++) {
            if (c < 14)       cp_wait<2>();
            else if (c == 14) cp_wait<1>();
            else              cp_wait<0>();
            __syncthreads();
            if (c + 3 < 16) {
                const int stg = (c + 3) & 3;
#pragma unroll
                for (int s = 0; s < 4; s++) {
                    const int id = tid + 256 * s;
                    const int split = id >> 9, r = id & 511, row = r >> 3, seg = r & 7;
                    const __half* srcp = (split ? pAl : pAh) + (size_t)row * HID
                                         + (c + 3) * 64 + seg * 8;
                    cp16(Hs + ((stg * 2 + split) * 64 + row) * 72 + seg * 8, srcp);
                }
                cp_commit();
            }
            const int st = c & 3;
#pragma unroll
            for (int k16 = 0; k16 < 4; k16++) {
                uint32_t aH[4], aL[4], bH[2][2], bL[2][2];
                ldm4(aH[0], aH[1], aH[2], aH[3],
                     Hs + ((st * 2 + 0) * 64 + mw * 16 + rowA) * 72 + k16 * 16 + colA);
                ldm4(aL[0], aL[1], aL[2], aL[3],
                     Hs + ((st * 2 + 1) * 64 + mw * 16 + rowA) * 72 + k16 * 16 + colA);
                ldm4(bH[0][0], bH[0][1], bH[1][0], bH[1][1],
                     Ws_h + (nh * 16 + rowB) * 1032 + c * 64 + k16 * 16 + colB);
                ldm4(bL[0][0], bL[0][1], bL[1][0], bL[1][1],
                     Ws_l + (nh * 16 + rowB) * 1032 + c * 64 + k16 * 16 + colB);
#pragma unroll
                for (int j = 0; j < 2; j++) {
                    mma16816(acc[j], aH, bH[j]);
                    mma16816(acc[j], aH, bL[j]);
                    mma16816(acc[j], aL, bH[j]);
                }
            }
        }

        // write gates to smem
#pragma unroll
        for (int j = 0; j < 2; j++) {
            const int col = nh * 16 + j * 8 + colPos * 2;
            Gs[(mw * 16 + groupRow) * 33 + col]         = acc[j][0];
            Gs[(mw * 16 + groupRow) * 33 + col + 1]     = acc[j][1];
            Gs[(mw * 16 + groupRow + 8) * 33 + col]     = acc[j][2];
            Gs[(mw * 16 + groupRow + 8) * 33 + col + 1] = acc[j][3];
        }
        __syncthreads();

        // LSTM update for this block's 512 cells
        for (int cell = tid; cell < 512; cell += 256) {
            const int b = cell >> 3, u = cell & 7;
            const float gi = Gs[b * 33 + u]      * INV_SCALE + Ps[b * 36 + u];
            const float gf = Gs[b * 33 + 8 + u]  * INV_SCALE + Ps[b * 36 + 8 + u];
            const float gg = Gs[b * 33 + 16 + u] * INV_SCALE + Ps[b * 36 + 16 + u];
            const float go = Gs[b * 33 + 24 + u] * INV_SCALE + Ps[b * 36 + 24 + u];

            const float i_ = 1.f / (1.f + expf(-gi));
            const float f_ = 1.f / (1.f + expf(-gf));
            const float g_ = tanhf(gg);
            const float o_ = 1.f / (1.f + expf(-go));

            const float cN = f_ * Cs[cell] + i_ * g_;
            Cs[cell] = cN;
            const float h = o_ * tanhf(cN);

            const float a = h * SCALE_A;
            const __half hh = __float2half_rn(a);
            const __half hl = __float2half_rn(a - __half2float(hh));
            const size_t m = ((size_t)(t * 64 + b)) * HID + blk * 8 + u;
            g_Ah[m] = hh;
            g_Al[m] = hl;
        }

        // grid barrier
        __syncthreads();
        if (tid == 0) {
            __threadfence();
            atomicAdd(&g_bar, 1u);
            volatile unsigned* p = &g_bar;
            const unsigned target = (unsigned)(t + 1) * NBLK;
            while (*p < target) { }
            __threadfence();
        }
        __syncthreads();
    }
}

// =======================================================================
// K3: logits GEMM (fp16 split, 3 products) + fused softmax stats.
// 3-stage pipeline, 1 sync per K-chunk.
// =======================================================================
#define LOG_SMEM (3 * (1536 + 1536 + 3072 + 3072) * 2 + 4 * 1024 + 256 + 256)
__global__ __launch_bounds__(256, 2)
void logits_mma_kernel(const float* __restrict__ bout, const int* __restrict__ ot) {
    extern __shared__ __align__(16) char dsm[];
    __half* As_h = (__half*)dsm;
    __half* As_l = As_h + 3 * 1536;
    __half* Bs_h = As_l + 3 * 1536;
    __half* Bs_l = Bs_h + 3 * 3072;
    float*  wmax = (float*)(Bs_l + 3 * 3072);   // 64 x 4
    int*    warg = (int*)(wmax + 256);
    float*  wsum = (float*)(warg + 256);
    float*  wlab = wsum + 256;
    float*  rowmax_s = wlab + 256;              // 64
    int*    labels_s = (int*)(rowmax_s + 64);   // 64

    const int tid   = threadIdx.x;
    const int lane  = tid & 31;
    const int warp  = tid >> 5;
    const int wm    = warp >> 2;
    const int wn    = warp & 3;
    const int mblk  = blockIdx.x * 64;
    const int nblk  = blockIdx.y * 128;

    if (tid < 64) labels_s[tid] = ot[64 + mblk + tid];

    const __half* src[3];
    __half* arrb[3];
    int off3[3], strd[3];
#pragma unroll
    for (int s = 0; s < 3; s++) {
        int c = tid + s * 256;
        if (c < 128) {
            int row = c >> 1, col = (c & 1) * 8;
            src[s] = g_Ah + (long)(mblk + row) * HID + col;
            arrb[s] = As_h; off3[s] = row * 24 + col; strd[s] = 1536;
        } else if (c < 256) {
            int r = c - 128, row = r >> 1, col = (r & 1) * 8;
            src[s] = g_Al + (long)(mblk + row) * HID + col;
            arrb[s] = As_l; off3[s] = row * 24 + col; strd[s] = 1536;
        } else if (c < 512) {
            int r = c - 256, row = r >> 1, col = (r & 1) * 8;
            src[s] = g_Bh + (long)(nblk + row) * HID + col;
            arrb[s] = Bs_h; off3[s] = row * 24 + col; strd[s] = 3072;
        } else {
            int r = c - 512, row = r >> 1, col = (r & 1) * 8;
            src[s] = g_Bl + (long)(nblk + row) * HID + col;
            arrb[s] = Bs_l; off3[s] = row * 24 + col; strd[s] = 3072;
        }
    }

    const int q = lane >> 3, r8 = lane & 7;
    const int rowA = (q & 1) * 8 + r8;
    const int colA = (q >> 1) * 8;
    const int rowB = (q >> 1) * 8 + r8;
    const int colB = (q & 1) * 8;

    float acc[2][4][4];
#pragma unroll
    for (int i = 0; i < 2; i++)
#pragma unroll
        for (int j = 0; j < 4; j++)
#pragma unroll
            for (int k = 0; k < 4; k++) acc[i][j][k] = 0.f;

#pragma unroll
    for (int p = 0; p < 2; p++) {
#pragma unroll
        for (int s = 0; s < 3; s++)
            cp16(arrb[s] + p * strd[s] + off3[s], src[s] + p * 16);
        cp_commit();
    }

    for (int kk = 0; kk < 64; kk++) {
        if (kk < 63) cp_wait<1>(); else cp_wait<0>();
        __syncthreads();
        if (kk + 2 < 64) {
            const int stg = (kk + 2) % 3;
#pragma unroll
            for (int s = 0; s < 3; s++)
                cp16(arrb[s] + stg * strd[s] + off3[s], src[s] + (kk + 2) * 16);
            cp_commit();
        }
        const int st = kk % 3;

        uint32_t aH[2][4], aL[2][4], bH[4][2], bL[4][2];
#pragma unroll
        for (int i = 0; i < 2; i++) {
            ldm4(aH[i][0], aH[i][1], aH[i][2], aH[i][3],
                 As_h + st * 1536 + (wm * 32 + i * 16 + rowA) * 24 + colA);
            ldm4(aL[i][0], aL[i][1], aL[i][2], aL[i][3],
                 As_l + st * 1536 + (wm * 32 + i * 16 + rowA) * 24 + colA);
        }
#pragma unroll
        for (int j2 = 0; j2 < 2; j2++) {
            ldm4(bH[j2 * 2][0], bH[j2 * 2][1], bH[j2 * 2 + 1][0], bH[j2 * 2 + 1][1],
                 Bs_h + st * 3072 + (wn * 32 + j2 * 16 + rowB) * 24 + colB);
            ldm4(bL[j2 * 2][0], bL[j2 * 2][1], bL[j2 * 2 + 1][0], bL[j2 * 2 + 1][1],
                 Bs_l + st * 3072 + (wn * 32 + j2 * 16 + rowB) * 24 + colB);
        }
#pragma unroll
        for (int i = 0; i < 2; i++)
#pragma unroll
            for (int j = 0; j < 4; j++) {
                mma16816(acc[i][j], aH[i], bH[j]);
                mma16816(acc[i][j], aH[i], bL[j]);
                mma16816(acc[i][j], aL[i], bH[j]);
            }
    }

    const int groupRow = lane >> 2;
    const int colPos   = lane & 3;

    float bcol[4][2];
#pragma unroll
    for (int j = 0; j < 4; j++)
#pragma unroll
        for (int kb = 0; kb < 2; kb++)
            bcol[j][kb] = bout[nblk + wn * 32 + j * 8 + colPos * 2 + kb];

    float vals[2][2][4][2];

#pragma unroll
    for (int i = 0; i < 2; i++) {
#pragma unroll
        for (int half = 0; half < 2; half++) {
            const int row_local = wm * 32 + i * 16 + groupRow + half * 8;
            const int lbl = labels_s[row_local];
            float mv = -1e30f; int ma = 0x7fffffff; float lv = -1e30f;
#pragma unroll
            for (int j = 0; j < 4; j++) {
#pragma unroll
                for (int kb = 0; kb < 2; kb++) {
                    const int colg = nblk + wn * 32 + j * 8 + colPos * 2 + kb;
                    const float v = acc[i][j][half * 2 + kb] * INV_SCALE + bcol[j][kb];
                    vals[i][half][j][kb] = v;
                    if (v > mv) { mv = v; ma = colg; }
                    if (colg == lbl) lv = v;
                }
            }
#pragma unroll
            for (int m = 1; m < 4; m <<= 1) {
                const float ov = __shfl_xor_sync(0xffffffffu, mv, m);
                const int   oa = __shfl_xor_sync(0xffffffffu, ma, m);
                const float ol = __shfl_xor_sync(0xffffffffu, lv, m);
                if (ov > mv || (ov == mv && oa < ma)) { mv = ov; ma = oa; }
                lv = fmaxf(lv, ol);
            }
            if (colPos == 0) {
                wmax[row_local * 4 + wn] = mv;
                warg[row_local * 4 + wn] = ma;
                wlab[row_local * 4 + wn] = lv;
            }
        }
    }
    __syncthreads();

    if (tid < 64) {
        float mv = wmax[tid * 4]; int ma = warg[tid * 4]; float lv = wlab[tid * 4];
#pragma unroll
        for (int x = 1; x < 4; x++) {
            const float v = wmax[tid * 4 + x]; const int a = warg[tid * 4 + x];
            if (v > mv || (v == mv && a < ma)) { mv = v; ma = a; }
            lv = fmaxf(lv, wlab[tid * 4 + x]);
        }
        rowmax_s[tid] = mv;
        const long p = (long)(mblk + tid) * NCHUNK + blockIdx.y;
        g_pmax[p] = mv;
        g_parg[p] = ma;
        g_plab[p] = lv;
    }
    __syncthreads();

#pragma unroll
    for (int i = 0; i < 2; i++) {
#pragma unroll
        for (int half = 0; half < 2; half++) {
            const int row_local = wm * 32 + i * 16 + groupRow + half * 8;
            const float rm = rowmax_s[row_local];
            float s = 0.f;
#pragma unroll
            for (int j = 0; j < 4; j++)
#pragma unroll
                for (int kb = 0; kb < 2; kb++)
                    s += expf(vals[i][half][j][kb] - rm);
#pragma unroll
            for (int m = 1; m < 4; m <<= 1)
                s += __shfl_xor_sync(0xffffffffu, s, m);
            if (colPos == 0) wsum[row_local * 4 + wn] = s;
        }
    }
    __syncthreads();

    if (tid < 64) {
        float s = wsum[tid * 4] + wsum[tid * 4 + 1] + wsum[tid * 4 + 2] + wsum[tid * 4 + 3];
        g_psum[(long)(mblk + tid) * NCHUNK + blockIdx.y] = s;
    }
}

// ---------------- K4: per-row cross-chunk reduction ----------------
__global__ void reduce_rows_kernel(float* __restrict__ out) {
    const int m = blockIdx.x;
    const int tid = threadIdx.x;
    const long base = (long)m * NCHUNK;

    float mv = -1e30f; int ma = 0x7fffffff;
    for (int c = tid; c < NCHUNK; c += 128) {
        const float v = g_pmax[base + c];
        const int   a = g_parg[base + c];
        if (v > mv || (v == mv && a < ma)) { mv = v; ma = a; }
    }
    __shared__ float sv[128]; __shared__ int sa[128];
    sv[tid] = mv; sa[tid] = ma;
    __syncthreads();
    for (int off = 64; off > 0; off >>= 1) {
        if (tid < off) {
            const float v = sv[tid + off]; const int a = sa[tid + off];
            if (v > sv[tid] || (v == sv[tid] && a < sa[tid])) { sv[tid] = v; sa[tid] = a; }
        }
        __syncthreads();
    }
    const float gmax = sv[0];
    const int   garg = sa[0];
    __syncthreads();

    float ssum = 0.f, lab = -1e30f;
    for (int c = tid; c < NCHUNK; c += 128) {
        ssum += g_psum[base + c] * expf(g_pmax[base + c] - gmax);
        lab = fmaxf(lab, g_plab[base + c]);
    }
    __shared__ float s2[128]; __shared__ float s3[128];
    s2[tid] = ssum; s3[tid] = lab;
    __syncthreads();
    for (int off = 64; off > 0; off >>= 1) {
        if (tid < off) {
            s2[tid] += s2[tid + off];
            s3[tid] = fmaxf(s3[tid], s3[tid + off]);
        }
        __syncthreads();
    }

    if (tid == 0) {
        const float lse = gmax + logf(s2[0]);
        g_nll[m] = lse - s3[0];
        out[65 + m] = (float)garg;
    }
}

// ---------------- K5: loss assembly + first result row ----------------
__global__ void finalize_kernel(const int* __restrict__ ot, float* __restrict__ out) {
    const int tid = threadIdx.x;
    __shared__ float ps[64];
    if (tid < 64) out[1 + tid] = 1.0f;
    if (tid < 63) {
        float s = 0.f, cnt = 0.f;
        for (int b = 0; b < 64; b++) {
            const int lbl = ot[(tid + 1) * 64 + b];
            if (lbl != 0) { s += g_nll[tid * 64 + b]; cnt += 1.f; }
        }
        ps[tid] = s / fmaxf(cnt, 1.f);
    }
    __syncthreads();
    if (tid == 0) {
        float loss = 0.f;
        for (int t = 0; t < 63; t++) loss += ps[t];
        out[0] = loss;
    }
}

// ---------------- entry point ----------------
extern "C" void kernel_launch(void* const* d_in, const int* in_sizes, int n_in,
                              void* d_out, int out_size) {
    const int*   ot   = (const int*)  d_in[0];
    const float* h0   = (const float*)d_in[3];
    const float* c0   = (const float*)d_in[4];
    const float* emb  = (const float*)d_in[5];
    const float* Wih  = (const float*)d_in[6];
    const float* Whh  = (const float*)d_in[7];
    const float* bih  = (const float*)d_in[8];
    const float* bhh  = (const float*)d_in[9];
    const float* Wout = (const float*)d_in[10];
    const float* bout = (const float*)d_in[11];
    float* out = (float*)d_out;

    cudaFuncSetAttribute(lstm_persistent_kernel,
                         cudaFuncAttributeMaxDynamicSharedMemorySize, LSTM_SMEM);
    cudaFuncSetAttribute(pre_mma_kernel,
                         cudaFuncAttributeMaxDynamicSharedMemorySize, PRE_SMEM);
    cudaFuncSetAttribute(logits_mma_kernel,
                         cudaFuncAttributeMaxDynamicSharedMemorySize, LOG_SMEM);

    init_kernel<<<64, 1024>>>(h0);
    gather_split_x_kernel<<<(M_ROWS * EMB + 255) / 256, 256>>>(ot, emb);
    split_wih_kernel<<<(G4 * EMB) / 256, 256>>>(Wih);
    split_whh_kernel<<<(G4 * HID) / 256, 256>>>(Whh);
    split_w_kernel<<<(VOCAB * HID) / 256, 256>>>(Wout);

    pre_mma_kernel<<<dim3(63, 32), 256, PRE_SMEM>>>(bih, bhh);
    lstm_persistent_kernel<<<NBLK, 256, LSTM_SMEM>>>(c0);

    logits_mma_kernel<<<dim3(63, 250), 256, LOG_SMEM>>>(bout, ot);
    reduce_rows_kernel<<<4032, 128>>>(out);
    finalize_kernel<<<1, 64>>>(ot, out);
}

// round 6
// speedup vs baseline: 4.3118x; 1.0726x over previous
#include <cuda_runtime.h>
#include <cuda_fp16.h>
#include <math.h>
#include <stdint.h>

// Problem constants
#define T_STEPS 64
#define BATCH   64
#define HID     1024
#define EMB     512
#define VOCAB   32000
#define G4      4096
#define M_ROWS  4032
#define NCHUNK  250         // VOCAB / 128
#define NBLK    128         // persistent LSTM blocks (1 CTA/SM)

#define SCALE_A 256.0f
#define SCALE_B 1024.0f
#define INV_SCALE (1.0f / (256.0f * 1024.0f))

// SW128 swizzle (Swizzle<3,4,3>) on byte offsets, within 1024B atoms
#define SWZ(x) ((x) ^ (((x) >> 3) & 0x70))

// h blocked layout: [step][chunk(16)][split(2)][8192B (64 rows x 128B, swizzled)]
#define HB_STEP_BYTES  262144            // 16 * 2 * 8192
#define HB_CHUNK_BYTES 16384             // 2 * 8192

// ---------------- device scratch ----------------
__device__ __align__(16) float  g_pre  [M_ROWS * G4];   // blocked: [(t*128+blk)*64+b]*32 + gate*8 + u
__device__ __half g_Xh   [M_ROWS * EMB];
__device__ __half g_Xl   [M_ROWS * EMB];
__device__ __half g_Wih_h[G4 * EMB];
__device__ __half g_Wih_l[G4 * EMB];
__device__ __align__(16) __half g_Hb  [63 * 131072];    // blocked+swizzled split h
__device__ __align__(16) __half g_H0b [131072];         // blocked+swizzled split h0
__device__ __half g_Whh_h[G4 * HID];
__device__ __half g_Whh_l[G4 * HID];
__device__ __half g_Bh   [VOCAB * HID];
__device__ __half g_Bl   [VOCAB * HID];
__device__ float  g_pmax [M_ROWS * NCHUNK];
__device__ int    g_parg [M_ROWS * NCHUNK];
__device__ float  g_psum [M_ROWS * NCHUNK];
__device__ float  g_plab [M_ROWS * NCHUNK];
__device__ float  g_nll  [M_ROWS];
__device__ unsigned g_bar;

// ---------------- PTX helpers ----------------
__device__ __forceinline__ void cp16(void* dst, const void* src) {
    uint32_t d = (uint32_t)__cvta_generic_to_shared(dst);
    asm volatile("cp.async.cg.shared.global [%0], [%1], 16;\n" :: "r"(d), "l"(src));
}
__device__ __forceinline__ void cp_commit() {
    asm volatile("cp.async.commit_group;\n");
}
template <int N>
__device__ __forceinline__ void cp_wait() {
    asm volatile("cp.async.wait_group %0;\n" :: "n"(N));
}
__device__ __forceinline__ void bulkcp(uint32_t dst_smem, const void* src,
                                       uint32_t bytes, uint32_t mbar) {
    asm volatile(
        "cp.async.bulk.shared::cluster.global.mbarrier::complete_tx::bytes [%0], [%1], %2, [%3];"
        :: "r"(dst_smem), "l"(src), "r"(bytes), "r"(mbar) : "memory");
}
#define MBAR_INIT(mb, cnt) \
    asm volatile("mbarrier.init.shared.b64 [%0], %1;" :: "r"(mb), "r"((uint32_t)(cnt)) : "memory")
#define MBAR_EXPECT(mb, n) \
    asm volatile("mbarrier.arrive.expect_tx.shared.b64 _, [%0], %1;" :: "r"(mb), "r"((uint32_t)(n)) : "memory")
#define MBAR_WAIT(mb, par) do { \
    asm volatile( \
        "{\n\t.reg .pred P1;\n\t" \
        "WAIT_LOOP_%=:\n\t" \
        "mbarrier.try_wait.parity.acquire.cta.shared::cta.b64 P1, [%0], %1, 0x989680;\n\t" \
        "@P1 bra.uni WAIT_DONE_%=;\n\t" \
        "bra.uni WAIT_LOOP_%=;\n\t" \
        "WAIT_DONE_%=:\n\t}" \
        :: "r"(mb), "r"((uint32_t)(par)) : "memory"); \
} while (0)

__device__ __forceinline__ void ldm4(uint32_t& r0, uint32_t& r1, uint32_t& r2, uint32_t& r3,
                                     const void* p) {
    uint32_t a = (uint32_t)__cvta_generic_to_shared(p);
    asm volatile("ldmatrix.sync.aligned.m8n8.x4.shared.b16 {%0,%1,%2,%3}, [%4];\n"
                 : "=r"(r0), "=r"(r1), "=r"(r2), "=r"(r3) : "r"(a));
}
__device__ __forceinline__ void ldm4s(uint32_t& r0, uint32_t& r1, uint32_t& r2, uint32_t& r3,
                                      uint32_t a) {
    asm volatile("ldmatrix.sync.aligned.m8n8.x4.shared.b16 {%0,%1,%2,%3}, [%4];\n"
                 : "=r"(r0), "=r"(r1), "=r"(r2), "=r"(r3) : "r"(a));
}
__device__ __forceinline__ void mma16816(float* c, const uint32_t* a, const uint32_t* b) {
    asm volatile("mma.sync.aligned.m16n8k16.row.col.f32.f16.f16.f32 "
                 "{%0,%1,%2,%3}, {%4,%5,%6,%7}, {%8,%9}, {%0,%1,%2,%3};\n"
                 : "+f"(c[0]), "+f"(c[1]), "+f"(c[2]), "+f"(c[3])
                 : "r"(a[0]), "r"(a[1]), "r"(a[2]), "r"(a[3]), "r"(b[0]), "r"(b[1]));
}

// ---------------- init: reset barrier + split h0 into blocked layout ----------------
__global__ void init_kernel(const float* __restrict__ h0) {
    int i = blockIdx.x * blockDim.x + threadIdx.x;
    if (i == 0) g_bar = 0u;
    if (i < BATCH * HID) {
        const int b = i >> 10, col = i & 1023;
        const int c = col >> 6, inner = col & 63;
        float a = h0[i] * SCALE_A;
        __half hh = __float2half_rn(a);
        __half hl = __float2half_rn(a - __half2float(hh));
        char* base = (char*)g_H0b + (size_t)c * HB_CHUNK_BYTES;
        const uint32_t off = SWZ((uint32_t)(b * 128 + inner * 2));
        *(__half*)(base + off)        = hh;
        *(__half*)(base + 8192 + off) = hl;
    }
}

// ---------------- split kernels ----------------
__global__ void gather_split_x_kernel(const int* __restrict__ ot,
                                      const float* __restrict__ emb) {
    int i = blockIdx.x * blockDim.x + threadIdx.x;
    if (i >= M_ROWS * EMB) return;
    const int m = i >> 9, e = i & 511;
    float a = emb[(long)ot[m] * EMB + e] * SCALE_A;
    __half h = __float2half_rn(a);
    g_Xh[i] = h;
    g_Xl[i] = __float2half_rn(a - __half2float(h));
}
__global__ void split_wih_kernel(const float* __restrict__ Wih) {
    long i = (long)blockIdx.x * blockDim.x + threadIdx.x;
    if (i < (long)G4 * EMB) {
        float a = Wih[i] * SCALE_B;
        __half h = __float2half_rn(a);
        g_Wih_h[i] = h;
        g_Wih_l[i] = __float2half_rn(a - __half2float(h));
    }
}
__global__ void split_whh_kernel(const float* __restrict__ Whh) {
    long i = (long)blockIdx.x * blockDim.x + threadIdx.x;
    if (i < (long)G4 * HID) {
        float a = Whh[i] * SCALE_B;
        __half h = __float2half_rn(a);
        g_Whh_h[i] = h;
        g_Whh_l[i] = __float2half_rn(a - __half2float(h));
    }
}
// vectorized: 4 elements per thread
__global__ void split_w_kernel(const float* __restrict__ Wout) {
    size_t i4 = ((size_t)blockIdx.x * blockDim.x + threadIdx.x) * 4;
    if (i4 < (size_t)VOCAB * HID) {
        float4 v = *(const float4*)(Wout + i4);
        float a0 = v.x * SCALE_B, a1 = v.y * SCALE_B, a2 = v.z * SCALE_B, a3 = v.w * SCALE_B;
        __half h0 = __float2half_rn(a0), h1 = __float2half_rn(a1);
        __half h2 = __float2half_rn(a2), h3 = __float2half_rn(a3);
        __half hs[4] = {h0, h1, h2, h3};
        __half ls[4] = {__float2half_rn(a0 - __half2float(h0)),
                        __float2half_rn(a1 - __half2float(h1)),
                        __float2half_rn(a2 - __half2float(h2)),
                        __float2half_rn(a3 - __half2float(h3))};
        *(uint2*)(g_Bh + i4) = *(uint2*)hs;
        *(uint2*)(g_Bl + i4) = *(uint2*)ls;
    }
}

// =======================================================================
// K1: pre-gates GEMM via fp16-split mma (3 products). Writes g_pre in the
// per-(step, lstm-block) blocked layout.
// =======================================================================
#define PRE_SMEM (3 * (1536 + 1536 + 3072 + 3072) * 2)
__global__ __launch_bounds__(256, 2)
void pre_mma_kernel(const float* __restrict__ bih, const float* __restrict__ bhh) {
    extern __shared__ __align__(16) char dsm[];
    __half* As_h = (__half*)dsm;
    __half* As_l = As_h + 3 * 1536;
    __half* Bs_h = As_l + 3 * 1536;
    __half* Bs_l = Bs_h + 3 * 3072;

    const int tid  = threadIdx.x;
    const int lane = tid & 31;
    const int warp = tid >> 5;
    const int wm   = warp >> 2;
    const int wn   = warp & 3;
    const int mblk = blockIdx.x * 64;
    const int nblk = blockIdx.y * 128;

    const __half* src[3];
    __half* arrb[3];
    int off3[3], strd[3];
#pragma unroll
    for (int s = 0; s < 3; s++) {
        int c = tid + s * 256;
        if (c < 128) {
            int row = c >> 1, col = (c & 1) * 8;
            src[s] = g_Xh + (long)(mblk + row) * EMB + col;
            arrb[s] = As_h; off3[s] = row * 24 + col; strd[s] = 1536;
        } else if (c < 256) {
            int r = c - 128, row = r >> 1, col = (r & 1) * 8;
            src[s] = g_Xl + (long)(mblk + row) * EMB + col;
            arrb[s] = As_l; off3[s] = row * 24 + col; strd[s] = 1536;
        } else if (c < 512) {
            int r = c - 256, row = r >> 1, col = (r & 1) * 8;
            src[s] = g_Wih_h + (long)(nblk + row) * EMB + col;
            arrb[s] = Bs_h; off3[s] = row * 24 + col; strd[s] = 3072;
        } else {
            int r = c - 512, row = r >> 1, col = (r & 1) * 8;
            src[s] = g_Wih_l + (long)(nblk + row) * EMB + col;
            arrb[s] = Bs_l; off3[s] = row * 24 + col; strd[s] = 3072;
        }
    }

    const int q = lane >> 3, r8 = lane & 7;
    const int rowA = (q & 1) * 8 + r8;
    const int colA = (q >> 1) * 8;
    const int rowB = (q >> 1) * 8 + r8;
    const int colB = (q & 1) * 8;

    float acc[2][4][4];
#pragma unroll
    for (int i = 0; i < 2; i++)
#pragma unroll
        for (int j = 0; j < 4; j++)
#pragma unroll
            for (int k = 0; k < 4; k++) acc[i][j][k] = 0.f;

#pragma unroll
    for (int p = 0; p < 2; p++) {
#pragma unroll
        for (int s = 0; s < 3; s++)
            cp16(arrb[s] + p * strd[s] + off3[s], src[s] + p * 16);
        cp_commit();
    }

    for (int kk = 0; kk < 32; kk++) {
        if (kk < 31) cp_wait<1>(); else cp_wait<0>();
        __syncthreads();
        if (kk + 2 < 32) {
            const int stg = (kk + 2) % 3;
#pragma unroll
            for (int s = 0; s < 3; s++)
                cp16(arrb[s] + stg * strd[s] + off3[s], src[s] + (kk + 2) * 16);
            cp_commit();
        }
        const int st = kk % 3;

        uint32_t aH[2][4], aL[2][4], bH[4][2], bL[4][2];
#pragma unroll
        for (int i = 0; i < 2; i++) {
            ldm4(aH[i][0], aH[i][1], aH[i][2], aH[i][3],
                 As_h + st * 1536 + (wm * 32 + i * 16 + rowA) * 24 + colA);
            ldm4(aL[i][0], aL[i][1], aL[i][2], aL[i][3],
                 As_l + st * 1536 + (wm * 32 + i * 16 + rowA) * 24 + colA);
        }
#pragma unroll
        for (int j2 = 0; j2 < 2; j2++) {
            ldm4(bH[j2 * 2][0], bH[j2 * 2][1], bH[j2 * 2 + 1][0], bH[j2 * 2 + 1][1],
                 Bs_h + st * 3072 + (wn * 32 + j2 * 16 + rowB) * 24 + colB);
            ldm4(bL[j2 * 2][0], bL[j2 * 2][1], bL[j2 * 2 + 1][0], bL[j2 * 2 + 1][1],
                 Bs_l + st * 3072 + (wn * 32 + j2 * 16 + rowB) * 24 + colB);
        }
#pragma unroll
        for (int i = 0; i < 2; i++)
#pragma unroll
            for (int j = 0; j < 4; j++) {
                mma16816(acc[i][j], aH[i], bH[j]);
                mma16816(acc[i][j], aH[i], bL[j]);
                mma16816(acc[i][j], aL[i], bH[j]);
            }
    }

    // epilogue: scale + biases; store into blocked g_pre layout
    const int groupRow = lane >> 2;
    const int colPos   = lane & 3;
#pragma unroll
    for (int j = 0; j < 4; j++) {
        const int col  = nblk + wn * 32 + j * 8 + colPos * 2;  // global gate col
        const int gate = col >> 10;
        const int r10  = col & 1023;
        const int blk2 = r10 >> 3;
        const int u    = r10 & 7;
        const float bb0 = bih[col] + bhh[col];
        const float bb1 = bih[col + 1] + bhh[col + 1];
#pragma unroll
        for (int i = 0; i < 2; i++) {
#pragma unroll
            for (int half = 0; half < 2; half++) {
                const int m = mblk + wm * 32 + i * 16 + groupRow + half * 8;
                const int t = m >> 6, b = m & 63;
                float2 v;
                v.x = acc[i][j][half * 2]     * INV_SCALE + bb0;
                v.y = acc[i][j][half * 2 + 1] * INV_SCALE + bb1;
                *(float2*)(g_pre + (((size_t)(t * 128 + blk2) * 64 + b) * 32 + gate * 8 + u)) = v;
            }
        }
    }
}

// =======================================================================
// K2: persistent LSTM with cp.async.bulk stage loads.
// smem: Ws_h(66048) Ws_l(66048) Hs(4x16384) Gs(8448) Cs(2048) Ps(8192) mbar(40)
// =======================================================================
#define LSTM_SMEM 216384
__global__ __launch_bounds__(256, 1)
void lstm_persistent_kernel(const float* __restrict__ c0) {
    extern __shared__ __align__(16) char smem[];
    __half* Ws_h = (__half*)smem;
    __half* Ws_l = Ws_h + 32 * 1032;
    float*  Gs   = (float*)(smem + 197632);
    float*  Cs   = (float*)(smem + 206080);
    float*  Ps   = (float*)(smem + 208128);
    const uint32_t sb  = (uint32_t)__cvta_generic_to_shared(smem);
    const uint32_t HS  = sb + 132096;          // 4 stages x 16384
    const uint32_t PSA = sb + 208128;
    const uint32_t MB  = sb + 216320;          // 4 stage mbarriers + 1 pre mbarrier

    const int tid  = threadIdx.x;
    const int lane = tid & 31;
    const int warp = tid >> 5;
    const int mw   = warp & 3;
    const int nh   = warp >> 2;
    const int blk  = blockIdx.x;

    // load W_hh slice into smem (once)
    for (int c = tid; c < 8192; c += 256) {
        const int split = c >> 12;
        const int rr    = (c >> 7) & 31;
        const int seg   = c & 127;
        const long nglob = (long)((rr >> 3) * 1024 + blk * 8 + (rr & 7));
        const __half* srcp = (split ? g_Whh_l : g_Whh_h) + nglob * HID + seg * 8;
        float4 v = *(const float4*)srcp;
        *(float4*)((split ? Ws_l : Ws_h) + rr * 1032 + seg * 8) = v;
    }
    for (int cell = tid; cell < 512; cell += 256) {
        const int b = cell >> 3, u = cell & 7;
        Cs[cell] = c0[b * HID + blk * 8 + u];
    }
    if (tid == 0) {
#pragma unroll
        for (int s = 0; s < 5; s++) MBAR_INIT(MB + s * 8, 1);
    }
    __syncthreads();

    const int q = lane >> 3, r8 = lane & 7;
    const int rowA = (q & 1) * 8 + r8;
    const int colA = (q >> 1) * 8;
    const int rowB = (q >> 1) * 8 + r8;
    const int colB = (q & 1) * 8;
    const int groupRow = lane >> 2;
    const int colPos   = lane & 3;

    // per-lane A swizzle base (byte offset within 8KB split block, before k16 shift)
    const uint32_t aRowByte = (uint32_t)((mw * 16 + rowA) * 128 + colA * 2);

    // h write addressing (constant per block)
    const int c2 = blk >> 3;                    // chunk owning this block's columns

    for (int t = 0; t < 63; t++) {
        const char* hsrc = t ? ((const char*)g_Hb + (size_t)(t - 1) * HB_STEP_BYTES)
                             : (const char*)g_H0b;

        if (tid == 0) {
#pragma unroll
            for (int pc = 0; pc < 3; pc++) {
                MBAR_EXPECT(MB + pc * 8, HB_CHUNK_BYTES);
                bulkcp(HS + pc * 16384, hsrc + (size_t)pc * HB_CHUNK_BYTES,
                       HB_CHUNK_BYTES, MB + pc * 8);
            }
            MBAR_EXPECT(MB + 32, 8192);
            bulkcp(PSA, (const char*)g_pre + ((size_t)t * 128 + blk) * 8192, 8192, MB + 32);
        }

        float acc[2][4];
#pragma unroll
        for (int i = 0; i < 2; i++)
#pragma unroll
            for (int k = 0; k < 4; k++) acc[i][k] = 0.f;

        for (int c = 0; c < 16; c++) {
            if (c) __syncthreads();   // readers of chunk c-1 done -> stage reuse safe
            if (c + 3 < 16 && tid == 0) {
                const int s3 = (c + 3) & 3;
                MBAR_EXPECT(MB + s3 * 8, HB_CHUNK_BYTES);
                bulkcp(HS + s3 * 16384, hsrc + (size_t)(c + 3) * HB_CHUNK_BYTES,
                       HB_CHUNK_BYTES, MB + s3 * 8);
            }
            MBAR_WAIT(MB + (c & 3) * 8, (c >> 2) & 1);
            const uint32_t hb = HS + (c & 3) * 16384;

#pragma unroll
            for (int k16 = 0; k16 < 4; k16++) {
                uint32_t aH[4], aL[4], bH[2][2], bL[2][2];
                const uint32_t aoff = SWZ(aRowByte + (uint32_t)(k16 * 32));
                ldm4s(aH[0], aH[1], aH[2], aH[3], hb + aoff);
                ldm4s(aL[0], aL[1], aL[2], aL[3], hb + 8192 + aoff);
                ldm4(bH[0][0], bH[0][1], bH[1][0], bH[1][1],
                     Ws_h + (nh * 16 + rowB) * 1032 + c * 64 + k16 * 16 + colB);
                ldm4(bL[0][0], bL[0][1], bL[1][0], bL[1][1],
                     Ws_l + (nh * 16 + rowB) * 1032 + c * 64 + k16 * 16 + colB);
#pragma unroll
                for (int j = 0; j < 2; j++) {
                    mma16816(acc[j], aH, bH[j]);
                    mma16816(acc[j], aH, bL[j]);
                    mma16816(acc[j], aL, bH[j]);
                }
            }
        }

        // write gates to smem
#pragma unroll
        for (int j = 0; j < 2; j++) {
            const int col = nh * 16 + j * 8 + colPos * 2;
            Gs[(mw * 16 + groupRow) * 33 + col]         = acc[j][0];
            Gs[(mw * 16 + groupRow) * 33 + col + 1]     = acc[j][1];
            Gs[(mw * 16 + groupRow + 8) * 33 + col]     = acc[j][2];
            Gs[(mw * 16 + groupRow + 8) * 33 + col + 1] = acc[j][3];
        }
        __syncthreads();
        MBAR_WAIT(MB + 32, t & 1);   // pre-gates slice ready (long ago)

        // LSTM update for this block's 512 cells; write h to blocked layout
        char* hdst = (char*)g_Hb + (size_t)t * HB_STEP_BYTES + (size_t)c2 * HB_CHUNK_BYTES;
        for (int cell = tid; cell < 512; cell += 256) {
            const int b = cell >> 3, u = cell & 7;
            const float gi = Gs[b * 33 + u]      * INV_SCALE + Ps[b * 32 + u];
            const float gf = Gs[b * 33 + 8 + u]  * INV_SCALE + Ps[b * 32 + 8 + u];
            const float gg = Gs[b * 33 + 16 + u] * INV_SCALE + Ps[b * 32 + 16 + u];
            const float go = Gs[b * 33 + 24 + u] * INV_SCALE + Ps[b * 32 + 24 + u];

            const float i_ = 1.f / (1.f + expf(-gi));
            const float f_ = 1.f / (1.f + expf(-gf));
            const float g_ = tanhf(gg);
            const float o_ = 1.f / (1.f + expf(-go));

            const float cN = f_ * Cs[cell] + i_ * g_;
            Cs[cell] = cN;
            const float h = o_ * tanhf(cN);

            const float a = h * SCALE_A;
            const __half hh = __float2half_rn(a);
            const __half hl = __float2half_rn(a - __half2float(hh));
            const int inner = (blk & 7) * 8 + u;
            const uint32_t off = SWZ((uint32_t)(b * 128 + inner * 2));
            *(__half*)(hdst + off)        = hh;
            *(__half*)(hdst + 8192 + off) = hl;
        }

        // grid barrier
        __syncthreads();
        if (tid == 0) {
            asm volatile("fence.proxy.async;" ::: "memory");
            __threadfence();
            atomicAdd(&g_bar, 1u);
            volatile unsigned* p = &g_bar;
            const unsigned target = (unsigned)(t + 1) * NBLK;
            while (*p < target) { }
            __threadfence();
            asm volatile("fence.proxy.async;" ::: "memory");
        }
        __syncthreads();
    }
}

// =======================================================================
// K3: logits GEMM (fp16 split, 3 products) + fused softmax stats.
// Same as R4 except A sources come from the blocked+swizzled g_Hb.
// =======================================================================
#define LOG_SMEM (3 * (1536 + 1536 + 3072 + 3072) * 2 + 4 * 1024 + 256 + 256)
__global__ __launch_bounds__(256, 2)
void logits_mma_kernel(const float* __restrict__ bout, const int* __restrict__ ot) {
    extern __shared__ __align__(16) char dsm[];
    __half* As_h = (__half*)dsm;
    __half* As_l = As_h + 3 * 1536;
    __half* Bs_h = As_l + 3 * 1536;
    __half* Bs_l = Bs_h + 3 * 3072;
    float*  wmax = (float*)(Bs_l + 3 * 3072);
    int*    warg = (int*)(wmax + 256);
    float*  wsum = (float*)(warg + 256);
    float*  wlab = wsum + 256;
    float*  rowmax_s = wlab + 256;
    int*    labels_s = (int*)(rowmax_s + 64);

    const int tid   = threadIdx.x;
    const int lane  = tid & 31;
    const int warp  = tid >> 5;
    const int wm    = warp >> 2;
    const int wn    = warp & 3;
    const int mblk  = blockIdx.x * 64;      // == step t * 64
    const int nblk  = blockIdx.y * 128;

    if (tid < 64) labels_s[tid] = ot[64 + mblk + tid];

    // slot 0: A (hi for tid<128, lo for tid>=128) from blocked g_Hb
    const int splitA = tid >> 7;
    const int rA     = tid & 127;
    const int rowA0  = rA >> 1;              // 0..63 (= batch b; step = blockIdx.x)
    const uint32_t aoff0 = (uint32_t)(rowA0 * 128 + (rA & 1) * 16);
    const char* aBase = (const char*)g_Hb + (size_t)blockIdx.x * HB_STEP_BYTES
                        + (size_t)splitA * 8192;
    __half* dstA = (splitA ? As_l : As_h) + rowA0 * 24 + (rA & 1) * 8;

    // slots 1,2: B (row-major, unchanged)
    const __half* src[3];
    __half* arrb[3];
    int off3[3], strd[3];
#pragma unroll
    for (int s = 1; s < 3; s++) {
        int c = tid + s * 256;
        if (c < 512) {
            int r = c - 256, row = r >> 1, col = (r & 1) * 8;
            src[s] = g_Bh + (long)(nblk + row) * HID + col;
            arrb[s] = Bs_h; off3[s] = row * 24 + col; strd[s] = 3072;
        } else {
            int r = c - 512, row = r >> 1, col = (r & 1) * 8;
            src[s] = g_Bl + (long)(nblk + row) * HID + col;
            arrb[s] = Bs_l; off3[s] = row * 24 + col; strd[s] = 3072;
        }
    }

    const int q = lane >> 3, r8 = lane & 7;
    const int rowA = (q & 1) * 8 + r8;
    const int colA = (q >> 1) * 8;
    const int rowB = (q >> 1) * 8 + r8;
    const int colB = (q & 1) * 8;

    float acc[2][4][4];
#pragma unroll
    for (int i = 0; i < 2; i++)
#pragma unroll
        for (int j = 0; j < 4; j++)
#pragma unroll
            for (int k = 0; k < 4; k++) acc[i][j][k] = 0.f;

#pragma unroll
    for (int p = 0; p < 2; p++) {
        cp16(dstA + p * 1536,
             aBase + (size_t)(p >> 2) * HB_CHUNK_BYTES + SWZ(aoff0 + (uint32_t)((p & 3) * 32)));
#pragma unroll
        for (int s = 1; s < 3; s++)
            cp16(arrb[s] + p * strd[s] + off3[s], src[s] + p * 16);
        cp_commit();
    }

    for (int kk = 0; kk < 64; kk++) {
        if (kk < 63) cp_wait<1>(); else cp_wait<0>();
        __syncthreads();
        if (kk + 2 < 64) {
            const int stg = (kk + 2) % 3;
            const int k2 = kk + 2;
            cp16(dstA + stg * 1536,
                 aBase + (size_t)(k2 >> 2) * HB_CHUNK_BYTES + SWZ(aoff0 + (uint32_t)((k2 & 3) * 32)));
#pragma unroll
            for (int s = 1; s < 3; s++)
                cp16(arrb[s] + stg * strd[s] + off3[s], src[s] + k2 * 16);
            cp_commit();
        }
        const int st = kk % 3;

        uint32_t aH[2][4], aL[2][4], bH[4][2], bL[4][2];
#pragma unroll
        for (int i = 0; i < 2; i++) {
            ldm4(aH[i][0], aH[i][1], aH[i][2], aH[i][3],
                 As_h + st * 1536 + (wm * 32 + i * 16 + rowA) * 24 + colA);
            ldm4(aL[i][0], aL[i][1], aL[i][2], aL[i][3],
                 As_l + st * 1536 + (wm * 32 + i * 16 + rowA) * 24 + colA);
        }
#pragma unroll
        for (int j2 = 0; j2 < 2; j2++) {
            ldm4(bH[j2 * 2][0], bH[j2 * 2][1], bH[j2 * 2 + 1][0], bH[j2 * 2 + 1][1],
                 Bs_h + st * 3072 + (wn * 32 + j2 * 16 + rowB) * 24 + colB);
            ldm4(bL[j2 * 2][0], bL[j2 * 2][1], bL[j2 * 2 + 1][0], bL[j2 * 2 + 1][1],
                 Bs_l + st * 3072 + (wn * 32 + j2 * 16 + rowB) * 24 + colB);
        }
#pragma unroll
        for (int i = 0; i < 2; i++)
#pragma unroll
            for (int j = 0; j < 4; j++) {
                mma16816(acc[i][j], aH[i], bH[j]);
                mma16816(acc[i][j], aH[i], bL[j]);
                mma16816(acc[i][j], aL[i], bH[j]);
            }
    }

    const int groupRow = lane >> 2;
    const int colPos   = lane & 3;

    float bcol[4][2];
#pragma unroll
    for (int j = 0; j < 4; j++)
#pragma unroll
        for (int kb = 0; kb < 2; kb++)
            bcol[j][kb] = bout[nblk + wn * 32 + j * 8 + colPos * 2 + kb];

    float vals[2][2][4][2];

#pragma unroll
    for (int i = 0; i < 2; i++) {
#pragma unroll
        for (int half = 0; half < 2; half++) {
            const int row_local = wm * 32 + i * 16 + groupRow + half * 8;
            const int lbl = labels_s[row_local];
            float mv = -1e30f; int ma = 0x7fffffff; float lv = -1e30f;
#pragma unroll
            for (int j = 0; j < 4; j++) {
#pragma unroll
                for (int kb = 0; kb < 2; kb++) {
                    const int colg = nblk + wn * 32 + j * 8 + colPos * 2 + kb;
                    const float v = acc[i][j][half * 2 + kb] * INV_SCALE + bcol[j][kb];
                    vals[i][half][j][kb] = v;
                    if (v > mv) { mv = v; ma = colg; }
                    if (colg == lbl) lv = v;
                }
            }
#pragma unroll
            for (int m = 1; m < 4; m <<= 1) {
                const float ov = __shfl_xor_sync(0xffffffffu, mv, m);
                const int   oa = __shfl_xor_sync(0xffffffffu, ma, m);
                const float ol = __shfl_xor_sync(0xffffffffu, lv, m);
                if (ov > mv || (ov == mv && oa < ma)) { mv = ov; ma = oa; }
                lv = fmaxf(lv, ol);
            }
            if (colPos == 0) {
                wmax[row_local * 4 + wn] = mv;
                warg[row_local * 4 + wn] = ma;
                wlab[row_local * 4 + wn] = lv;
            }
        }
    }
    __syncthreads();

    if (tid < 64) {
        float mv = wmax[tid * 4]; int ma = warg[tid * 4]; float lv = wlab[tid * 4];
#pragma unroll
        for (int x = 1; x < 4; x++) {
            const float v = wmax[tid * 4 + x]; const int a = warg[tid * 4 + x];
            if (v > mv || (v == mv && a < ma)) { mv = v; ma = a; }
            lv = fmaxf(lv, wlab[tid * 4 + x]);
        }
        rowmax_s[tid] = mv;
        const long p = (long)(mblk + tid) * NCHUNK + blockIdx.y;
        g_pmax[p] = mv;
        g_parg[p] = ma;
        g_plab[p] = lv;
    }
    __syncthreads();

#pragma unroll
    for (int i = 0; i < 2; i++) {
#pragma unroll
        for (int half = 0; half < 2; half++) {
            const int row_local = wm * 32 + i * 16 + groupRow + half * 8;
            const float rm = rowmax_s[row_local];
            float s = 0.f;
#pragma unroll
            for (int j = 0; j < 4; j++)
#pragma unroll
                for (int kb = 0; kb < 2; kb++)
                    s += expf(vals[i][half][j][kb] - rm);
#pragma unroll
            for (int m = 1; m < 4; m <<= 1)
                s += __shfl_xor_sync(0xffffffffu, s, m);
            if (colPos == 0) wsum[row_local * 4 + wn] = s;
        }
    }
    __syncthreads();

    if (tid < 64) {
        float s = wsum[tid * 4] + wsum[tid * 4 + 1] + wsum[tid * 4 + 2] + wsum[tid * 4 + 3];
        g_psum[(long)(mblk + tid) * NCHUNK + blockIdx.y] = s;
    }
}

// ---------------- K4: per-row cross-chunk reduction ----------------
__global__ void reduce_rows_kernel(float* __restrict__ out) {
    const int m = blockIdx.x;
    const int tid = threadIdx.x;
    const long base = (long)m * NCHUNK;

    float mv = -1e30f; int ma = 0x7fffffff;
    for (int c = tid; c < NCHUNK; c += 128) {
        const float v = g_pmax[base + c];
        const int   a = g_parg[base + c];
        if (v > mv || (v == mv && a < ma)) { mv = v; ma = a; }
    }
    __shared__ float sv[128]; __shared__ int sa[128];
    sv[tid] = mv; sa[tid] = ma;
    __syncthreads();
    for (int off = 64; off > 0; off >>= 1) {
        if (tid < off) {
            const float v = sv[tid + off]; const int a = sa[tid + off];
            if (v > sv[tid] || (v == sv[tid] && a < sa[tid])) { sv[tid] = v; sa[tid] = a; }
        }
        __syncthreads();
    }
    const float gmax = sv[0];
    const int   garg = sa[0];
    __syncthreads();

    float ssum = 0.f, lab = -1e30f;
    for (int c = tid; c < NCHUNK; c += 128) {
        ssum += g_psum[base + c] * expf(g_pmax[base + c] - gmax);
        lab = fmaxf(lab, g_plab[base + c]);
    }
    __shared__ float s2[128]; __shared__ float s3[128];
    s2[tid] = ssum; s3[tid] = lab;
    __syncthreads();
    for (int off = 64; off > 0; off >>= 1) {
        if (tid < off) {
            s2[tid] += s2[tid + off];
            s3[tid] = fmaxf(s3[tid], s3[tid + off]);
        }
        __syncthreads();
    }

    if (tid == 0) {
        const float lse = gmax + logf(s2[0]);
        g_nll[m] = lse - s3[0];
        out[65 + m] = (float)garg;
    }
}

// ---------------- K5: loss assembly + first result row ----------------
__global__ void finalize_kernel(const int* __restrict__ ot, float* __restrict__ out) {
    const int tid = threadIdx.x;
    __shared__ float ps[64];
    if (tid < 64) out[1 + tid] = 1.0f;
    if (tid < 63) {
        float s = 0.f, cnt = 0.f;
        for (int b = 0; b < 64; b++) {
            const int lbl = ot[(tid + 1) * 64 + b];
            if (lbl != 0) { s += g_nll[tid * 64 + b]; cnt += 1.f; }
        }
        ps[tid] = s / fmaxf(cnt, 1.f);
    }
    __syncthreads();
    if (tid == 0) {
        float loss = 0.f;
        for (int t = 0; t < 63; t++) loss += ps[t];
        out[0] = loss;
    }
}

// ---------------- entry point ----------------
extern "C" void kernel_launch(void* const* d_in, const int* in_sizes, int n_in,
                              void* d_out, int out_size) {
    const int*   ot   = (const int*)  d_in[0];
    const float* h0   = (const float*)d_in[3];
    const float* c0   = (const float*)d_in[4];
    const float* emb  = (const float*)d_in[5];
    const float* Wih  = (const float*)d_in[6];
    const float* Whh  = (const float*)d_in[7];
    const float* bih  = (const float*)d_in[8];
    const float* bhh  = (const float*)d_in[9];
    const float* Wout = (const float*)d_in[10];
    const float* bout = (const float*)d_in[11];
    float* out = (float*)d_out;

    cudaFuncSetAttribute(lstm_persistent_kernel,
                         cudaFuncAttributeMaxDynamicSharedMemorySize, LSTM_SMEM);
    cudaFuncSetAttribute(pre_mma_kernel,
                         cudaFuncAttributeMaxDynamicSharedMemorySize, PRE_SMEM);
    cudaFuncSetAttribute(logits_mma_kernel,
                         cudaFuncAttributeMaxDynamicSharedMemorySize, LOG_SMEM);

    init_kernel<<<64, 1024>>>(h0);
    gather_split_x_kernel<<<(M_ROWS * EMB + 255) / 256, 256>>>(ot, emb);
    split_wih_kernel<<<(G4 * EMB) / 256, 256>>>(Wih);
    split_whh_kernel<<<(G4 * HID) / 256, 256>>>(Whh);
    split_w_kernel<<<(VOCAB * HID / 4 + 255) / 256, 256>>>(Wout);

    pre_mma_kernel<<<dim3(63, 32), 256, PRE_SMEM>>>(bih, bhh);
    lstm_persistent_kernel<<<NBLK, 256, LSTM_SMEM>>>(c0);

    logits_mma_kernel<<<dim3(63, 250), 256, LOG_SMEM>>>(bout, ot);
    reduce_rows_kernel<<<4032, 128>>>(out);
    finalize_kernel<<<1, 64>>>(ot, out);
}

// round 9
// speedup vs baseline: 4.3374x; 1.0059x over previous
#include <cuda_runtime.h>
#include <cuda_fp16.h>
#include <math.h>
#include <stdint.h>

#define T_STEPS 64
#define BATCH   64
#define HID     1024
#define EMB     512
#define VOCAB   32000
#define G4      4096
#define M_ROWS  4032
#define NCHUNK  250
#define NBLK    128

#define SCALE_A 256.0f
#define SCALE_B 1024.0f
#define INV_SCALE (1.0f / (256.0f * 1024.0f))
#define SWZ(x) ((x) ^ (((x) >> 3) & 0x70))
#define HB_STEP_BYTES  262144
#define HB_CHUNK_BYTES 16384

__device__ __align__(16) float  g_pre  [M_ROWS * G4];
__device__ __half g_Xh   [M_ROWS * EMB];
__device__ __half g_Xl   [M_ROWS * EMB];
__device__ __half g_Wih_h[G4 * EMB];
__device__ __half g_Wih_l[G4 * EMB];
__device__ __align__(16) __half g_Hb  [63 * 131072];
__device__ __align__(16) __half g_H0b [131072];
__device__ __half g_Whh_h[G4 * HID];
__device__ __half g_Whh_l[G4 * HID];
__device__ __half g_Bh   [VOCAB * HID];
__device__ __half g_Bl   [VOCAB * HID];
__device__ float  g_pmax [M_ROWS * NCHUNK];
__device__ int    g_parg [M_ROWS * NCHUNK];
__device__ float  g_psum [M_ROWS * NCHUNK];
__device__ float  g_plab [M_ROWS * NCHUNK];
__device__ float  g_nll  [M_ROWS];
__device__ unsigned g_bar;

__device__ __forceinline__ void cp16(void* dst, const void* src) {
    uint32_t d = (uint32_t)__cvta_generic_to_shared(dst);
    asm volatile("cp.async.cg.shared.global [%0], [%1], 16;\n" :: "r"(d), "l"(src));
}
__device__ __forceinline__ void cp_commit() { asm volatile("cp.async.commit_group;\n"); }
template <int N>
__device__ __forceinline__ void cp_wait() {
    asm volatile("cp.async.wait_group %0;\n" :: "n"(N));
}
__device__ __forceinline__ void bulkcp(uint32_t dst_smem, const void* src,
                                       uint32_t bytes, uint32_t mbar) {
    asm volatile(
        "cp.async.bulk.shared::cluster.global.mbarrier::complete_tx::bytes [%0], [%1], %2, [%3];"
        :: "r"(dst_smem), "l"(src), "r"(bytes), "r"(mbar) : "memory");
}
#define MBAR_INIT(mb, cnt) \
    asm volatile("mbarrier.init.shared.b64 [%0], %1;" :: "r"(mb), "r"((uint32_t)(cnt)) : "memory")
#define MBAR_EXPECT(mb, n) \
    asm volatile("mbarrier.arrive.expect_tx.shared.b64 _, [%0], %1;" :: "r"(mb), "r"((uint32_t)(n)) : "memory")
#define MBAR_ARRIVE(mb) \
    asm volatile("mbarrier.arrive.shared.b64 _, [%0];" :: "r"(mb) : "memory")
#define MBAR_WAIT(mb, par) do { \
    asm volatile( \
        "{\n\t.reg .pred P1;\n\t" \
        "WAIT_LOOP_%=:\n\t" \
        "mbarrier.try_wait.parity.acquire.cta.shared::cta.b64 P1, [%0], %1, 0x989680;\n\t" \
        "@P1 bra.uni WAIT_DONE_%=;\n\t" \
        "bra.uni WAIT_LOOP_%=;\n\t" \
        "WAIT_DONE_%=:\n\t}" \
        :: "r"(mb), "r"((uint32_t)(par)) : "memory"); \
} while (0)

__device__ __forceinline__ void ldm4(uint32_t& r0, uint32_t& r1, uint32_t& r2, uint32_t& r3,
                                     const void* p) {
    uint32_t a = (uint32_t)__cvta_generic_to_shared(p);
    asm volatile("ldmatrix.sync.aligned.m8n8.x4.shared.b16 {%0,%1,%2,%3}, [%4];\n"
                 : "=r"(r0), "=r"(r1), "=r"(r2), "=r"(r3) : "r"(a));
}
__device__ __forceinline__ void ldm4s(uint32_t& r0, uint32_t& r1, uint32_t& r2, uint32_t& r3,
                                      uint32_t a) {
    asm volatile("ldmatrix.sync.aligned.m8n8.x4.shared.b16 {%0,%1,%2,%3}, [%4];\n"
                 : "=r"(r0), "=r"(r1), "=r"(r2), "=r"(r3) : "r"(a));
}
__device__ __forceinline__ void mma16816(float* c, const uint32_t* a, const uint32_t* b) {
    asm volatile("mma.sync.aligned.m16n8k16.row.col.f32.f16.f16.f32 "
                 "{%0,%1,%2,%3}, {%4,%5,%6,%7}, {%8,%9}, {%0,%1,%2,%3};\n"
                 : "+f"(c[0]), "+f"(c[1]), "+f"(c[2]), "+f"(c[3])
                 : "r"(a[0]), "r"(a[1]), "r"(a[2]), "r"(a[3]), "r"(b[0]), "r"(b[1]));
}

// ---- P0: fused prep (barrier reset, h0 split, x gather+split, Wih/Whh splits) ----
__global__ void prep_kernel(const int* __restrict__ ot, const float* __restrict__ emb,
                            const float* __restrict__ Wih, const float* __restrict__ Whh,
                            const float* __restrict__ h0) {
    const int T = blockIdx.x * blockDim.x + threadIdx.x;
    if (T == 0) g_bar = 0u;
    if (T < BATCH * HID) {
        const int b = T >> 10, col = T & 1023;
        const int c = col >> 6, inner = col & 63;
        float a = h0[T] * SCALE_A;
        __half hh = __float2half_rn(a);
        __half hl = __float2half_rn(a - __half2float(hh));
        char* base = (char*)g_H0b + (size_t)c * HB_CHUNK_BYTES;
        const uint32_t off = SWZ((uint32_t)(b * 128 + inner * 2));
        *(__half*)(base + off)        = hh;
        *(__half*)(base + 8192 + off) = hl;
    }
    if (T < M_ROWS * EMB) {
        const int m = T >> 9, e = T & 511;
        float a = emb[(long)ot[m] * EMB + e] * SCALE_A;
        __half h = __float2half_rn(a);
        g_Xh[T] = h;
        g_Xl[T] = __float2half_rn(a - __half2float(h));
    }
    if (T < G4 * EMB) {
        float a = Wih[T] * SCALE_B;
        __half h = __float2half_rn(a);
        g_Wih_h[T] = h;
        g_Wih_l[T] = __float2half_rn(a - __half2float(h));
    }
    if (T < G4 * HID) {
        float a = Whh[T] * SCALE_B;
        __half h = __float2half_rn(a);
        g_Whh_h[T] = h;
        g_Whh_l[T] = __float2half_rn(a - __half2float(h));
    }
}

__global__ void split_w_kernel(const float* __restrict__ Wout) {
    size_t i4 = ((size_t)blockIdx.x * blockDim.x + threadIdx.x) * 4;
    if (i4 < (size_t)VOCAB * HID) {
        float4 v = *(const float4*)(Wout + i4);
        float a0 = v.x * SCALE_B, a1 = v.y * SCALE_B, a2 = v.z * SCALE_B, a3 = v.w * SCALE_B;
        __half h0 = __float2half_rn(a0), h1 = __float2half_rn(a1);
        __half h2 = __float2half_rn(a2), h3 = __float2half_rn(a3);
        __half hs[4] = {h0, h1, h2, h3};
        __half ls[4] = {__float2half_rn(a0 - __half2float(h0)),
                        __float2half_rn(a1 - __half2float(h1)),
                        __float2half_rn(a2 - __half2float(h2)),
                        __float2half_rn(a3 - __half2float(h3))};
        *(uint2*)(g_Bh + i4) = *(uint2*)hs;
        *(uint2*)(g_Bl + i4) = *(uint2*)ls;
    }
}

// ---- K1: pre-gates GEMM (fp16 split, 3 products) -> blocked g_pre ----
#define PRE_SMEM (3 * (1536 + 1536 + 3072 + 3072) * 2)
__global__ __launch_bounds__(256, 2)
void pre_mma_kernel(const float* __restrict__ bih, const float* __restrict__ bhh) {
    extern __shared__ __align__(16) char dsm[];
    __half* As_h = (__half*)dsm;
    __half* As_l = As_h + 3 * 1536;
    __half* Bs_h = As_l + 3 * 1536;
    __half* Bs_l = Bs_h + 3 * 3072;

    const int tid  = threadIdx.x;
    const int lane = tid & 31;
    const int warp = tid >> 5;
    const int wm   = warp >> 2;
    const int wn   = warp & 3;
    const int mblk = blockIdx.x * 64;
    const int nblk = blockIdx.y * 128;

    const __half* src[3];
    __half* arrb[3];
    int off3[3], strd[3];
#pragma unroll
    for (int s = 0; s < 3; s++) {
        int c = tid + s * 256;
        if (c < 128) {
            int row = c >> 1, col = (c & 1) * 8;
            src[s] = g_Xh + (long)(mblk + row) * EMB + col;
            arrb[s] = As_h; off3[s] = row * 24 + col; strd[s] = 1536;
        } else if (c < 256) {
            int r = c - 128, row = r >> 1, col = (r & 1) * 8;
            src[s] = g_Xl + (long)(mblk + row) * EMB + col;
            arrb[s] = As_l; off3[s] = row * 24 + col; strd[s] = 1536;
        } else if (c < 512) {
            int r = c - 256, row = r >> 1, col = (r & 1) * 8;
            src[s] = g_Wih_h + (long)(nblk + row) * EMB + col;
            arrb[s] = Bs_h; off3[s] = row * 24 + col; strd[s] = 3072;
        } else {
            int r = c - 512, row = r >> 1, col = (r & 1) * 8;
            src[s] = g_Wih_l + (long)(nblk + row) * EMB + col;
            arrb[s] = Bs_l; off3[s] = row * 24 + col; strd[s] = 3072;
        }
    }

    const int q = lane >> 3, r8 = lane & 7;
    const int rowA = (q & 1) * 8 + r8;
    const int colA = (q >> 1) * 8;
    const int rowB = (q >> 1) * 8 + r8;
    const int colB = (q & 1) * 8;

    float acc[2][4][4];
#pragma unroll
    for (int i = 0; i < 2; i++)
#pragma unroll
        for (int j = 0; j < 4; j++)
#pragma unroll
            for (int k = 0; k < 4; k++) acc[i][j][k] = 0.f;

#pragma unroll
    for (int p = 0; p < 2; p++) {
#pragma unroll
        for (int s = 0; s < 3; s++)
            cp16(arrb[s] + p * strd[s] + off3[s], src[s] + p * 16);
        cp_commit();
    }

    for (int kk = 0; kk < 32; kk++) {
        if (kk < 31) cp_wait<1>(); else cp_wait<0>();
        __syncthreads();
        if (kk + 2 < 32) {
            const int stg = (kk + 2) % 3;
#pragma unroll
            for (int s = 0; s < 3; s++)
                cp16(arrb[s] + stg * strd[s] + off3[s], src[s] + (kk + 2) * 16);
            cp_commit();
        }
        const int st = kk % 3;

        uint32_t aH[2][4], aL[2][4], bH[4][2], bL[4][2];
#pragma unroll
        for (int i = 0; i < 2; i++) {
            ldm4(aH[i][0], aH[i][1], aH[i][2], aH[i][3],
                 As_h + st * 1536 + (wm * 32 + i * 16 + rowA) * 24 + colA);
            ldm4(aL[i][0], aL[i][1], aL[i][2], aL[i][3],
                 As_l + st * 1536 + (wm * 32 + i * 16 + rowA) * 24 + colA);
        }
#pragma unroll
        for (int j2 = 0; j2 < 2; j2++) {
            ldm4(bH[j2 * 2][0], bH[j2 * 2][1], bH[j2 * 2 + 1][0], bH[j2 * 2 + 1][1],
                 Bs_h + st * 3072 + (wn * 32 + j2 * 16 + rowB) * 24 + colB);
            ldm4(bL[j2 * 2][0], bL[j2 * 2][1], bL[j2 * 2 + 1][0], bL[j2 * 2 + 1][1],
                 Bs_l + st * 3072 + (wn * 32 + j2 * 16 + rowB) * 24 + colB);
        }
#pragma unroll
        for (int i = 0; i < 2; i++)
#pragma unroll
            for (int j = 0; j < 4; j++) {
                mma16816(acc[i][j], aH[i], bH[j]);
                mma16816(acc[i][j], aH[i], bL[j]);
                mma16816(acc[i][j], aL[i], bH[j]);
            }
    }

    const int groupRow = lane >> 2;
    const int colPos   = lane & 3;
#pragma unroll
    for (int j = 0; j < 4; j++) {
        const int col  = nblk + wn * 32 + j * 8 + colPos * 2;
        const int gate = col >> 10;
        const int r10  = col & 1023;
        const int blk2 = r10 >> 3;
        const int u    = r10 & 7;
        const float bb0 = bih[col] + bhh[col];
        const float bb1 = bih[col + 1] + bhh[col + 1];
#pragma unroll
        for (int i = 0; i < 2; i++) {
#pragma unroll
            for (int half = 0; half < 2; half++) {
                const int m = mblk + wm * 32 + i * 16 + groupRow + half * 8;
                const int t = m >> 6, b = m & 63;
                float2 v;
                v.x = acc[i][j][half * 2]     * INV_SCALE + bb0;
                v.y = acc[i][j][half * 2 + 1] * INV_SCALE + bb1;
                *(float2*)(g_pre + (((size_t)(t * 128 + blk2) * 64 + b) * 32 + gate * 8 + u)) = v;
            }
        }
    }
}

// ---- K2: persistent LSTM, decoupled producer/consumer pipeline ----
// full[s]: tx-barrier (count 1). consumed[s]: count 8 (one arrive/warp after reads).
// Producer (tid0) waits consumed[s] fill F-1 before fill F. No block sync in K-loop.
#define LSTM_SMEM 216400
__global__ __launch_bounds__(256, 1)
void lstm_persistent_kernel(const float* __restrict__ c0) {
    extern __shared__ __align__(16) char smem[];
    __half* Ws_h = (__half*)smem;
    __half* Ws_l = Ws_h + 32 * 1032;
    float*  Gs   = (float*)(smem + 197632);
    float*  Cs   = (float*)(smem + 206080);
    float*  Ps   = (float*)(smem + 208128);
    const uint32_t sb  = (uint32_t)__cvta_generic_to_shared(smem);
    const uint32_t HS  = sb + 132096;
    const uint32_t PSA = sb + 208128;
    const uint32_t MBF = sb + 216320;   // full[4]
    const uint32_t MBP = sb + 216352;   // pre barrier
    const uint32_t MBC = sb + 216360;   // consumed[4]

    const int tid  = threadIdx.x;
    const int lane = tid & 31;
    const int warp = tid >> 5;
    const int mw   = warp & 3;
    const int nh   = warp >> 2;
    const int blk  = blockIdx.x;

    for (int c = tid; c < 8192; c += 256) {
        const int split = c >> 12;
        const int rr    = (c >> 7) & 31;
        const int seg   = c & 127;
        const long nglob = (long)((rr >> 3) * 1024 + blk * 8 + (rr & 7));
        const __half* srcp = (split ? g_Whh_l : g_Whh_h) + nglob * HID + seg * 8;
        float4 v = *(const float4*)srcp;
        *(float4*)((split ? Ws_l : Ws_h) + rr * 1032 + seg * 8) = v;
    }
    for (int cell = tid; cell < 512; cell += 256) {
        const int b = cell >> 3, u = cell & 7;
        Cs[cell] = c0[b * HID + blk * 8 + u];
    }
    if (tid == 0) {
#pragma unroll
        for (int s = 0; s < 4; s++) MBAR_INIT(MBF + s * 8, 1);
        MBAR_INIT(MBP, 1);
#pragma unroll
        for (int s = 0; s < 4; s++) MBAR_INIT(MBC + s * 8, 8);
    }
    __syncthreads();

    const int q = lane >> 3, r8 = lane & 7;
    const int rowA = (q & 1) * 8 + r8;
    const int colA = (q >> 1) * 8;
    const int rowB = (q >> 1) * 8 + r8;
    const int colB = (q & 1) * 8;
    const int groupRow = lane >> 2;
    const int colPos   = lane & 3;

    const uint32_t aRowByte = (uint32_t)((mw * 16 + rowA) * 128 + colA * 2);
    const int c2 = blk >> 3;

    for (int t = 0; t < 63; t++) {
        const char* hsrc = t ? ((const char*)g_Hb + (size_t)(t - 1) * HB_STEP_BYTES)
                             : (const char*)g_H0b;

        if (tid == 0) {
#pragma unroll
            for (int m = 0; m < 3; m++) {
                const int F = t * 4;               // first fill of stage m this step
                if (F) MBAR_WAIT(MBC + m * 8, (F - 1) & 1);
                MBAR_EXPECT(MBF + m * 8, HB_CHUNK_BYTES);
                bulkcp(HS + m * 16384, hsrc + (size_t)m * HB_CHUNK_BYTES,
                       HB_CHUNK_BYTES, MBF + m * 8);
            }
            MBAR_EXPECT(MBP, 8192);
            bulkcp(PSA, (const char*)g_pre + ((size_t)t * 128 + blk) * 8192, 8192, MBP);
        }

        float aHH[2][4], aHL[2][4], aLH[2][4];
#pragma unroll
        for (int j = 0; j < 2; j++)
#pragma unroll
            for (int k = 0; k < 4; k++) { aHH[j][k] = 0.f; aHL[j][k] = 0.f; aLH[j][k] = 0.f; }

        for (int c = 0; c < 16; c++) {
            if (tid == 0 && c + 3 < 16) {
                const int m = c + 3;
                const int s = m & 3;
                const int F = t * 4 + (m >> 2);
                if (F) MBAR_WAIT(MBC + s * 8, (F - 1) & 1);
                MBAR_EXPECT(MBF + s * 8, HB_CHUNK_BYTES);
                bulkcp(HS + s * 16384, hsrc + (size_t)m * HB_CHUNK_BYTES,
                       HB_CHUNK_BYTES, MBF + s * 8);
            }
            MBAR_WAIT(MBF + (c & 3) * 8, (c >> 2) & 1);
            __syncwarp();
            const uint32_t hb = HS + (c & 3) * 16384;

#pragma unroll
            for (int k16 = 0; k16 < 4; k16++) {
                uint32_t aH[4], aL[4], bH[2][2], bL[2][2];
                const uint32_t aoff = SWZ(aRowByte + (uint32_t)(k16 * 32));
                ldm4s(aH[0], aH[1], aH[2], aH[3], hb + aoff);
                ldm4s(aL[0], aL[1], aL[2], aL[3], hb + 8192 + aoff);
                ldm4(bH[0][0], bH[0][1], bH[1][0], bH[1][1],
                     Ws_h + (nh * 16 + rowB) * 1032 + c * 64 + k16 * 16 + colB);
                ldm4(bL[0][0], bL[0][1], bL[1][0], bL[1][1],
                     Ws_l + (nh * 16 + rowB) * 1032 + c * 64 + k16 * 16 + colB);
#pragma unroll
                for (int j = 0; j < 2; j++) {
                    mma16816(aHH[j], aH, bH[j]);
                    mma16816(aHL[j], aH, bL[j]);
                    mma16816(aLH[j], aL, bH[j]);
                }
            }
            __syncwarp();
            if (lane == 0) MBAR_ARRIVE(MBC + (c & 3) * 8);
        }

#pragma unroll
        for (int j = 0; j < 2; j++) {
            const int col = nh * 16 + j * 8 + colPos * 2;
            Gs[(mw * 16 + groupRow) * 33 + col]         = aHH[j][0] + aHL[j][0] + aLH[j][0];
            Gs[(mw * 16 + groupRow) * 33 + col + 1]     = aHH[j][1] + aHL[j][1] + aLH[j][1];
            Gs[(mw * 16 + groupRow + 8) * 33 + col]     = aHH[j][2] + aHL[j][2] + aLH[j][2];
            Gs[(mw * 16 + groupRow + 8) * 33 + col + 1] = aHH[j][3] + aHL[j][3] + aLH[j][3];
        }
        __syncthreads();
        MBAR_WAIT(MBP, t & 1);

        char* hdst = (char*)g_Hb + (size_t)t * HB_STEP_BYTES + (size_t)c2 * HB_CHUNK_BYTES;
        for (int cell = tid; cell < 512; cell += 256) {
            const int b = cell >> 3, u = cell & 7;
            const float gi = Gs[b * 33 + u]      * INV_SCALE + Ps[b * 32 + u];
            const float gf = Gs[b * 33 + 8 + u]  * INV_SCALE + Ps[b * 32 + 8 + u];
            const float gg = Gs[b * 33 + 16 + u] * INV_SCALE + Ps[b * 32 + 16 + u];
            const float go = Gs[b * 33 + 24 + u] * INV_SCALE + Ps[b * 32 + 24 + u];

            const float i_ = 1.f / (1.f + expf(-gi));
            const float f_ = 1.f / (1.f + expf(-gf));
            const float g_ = tanhf(gg);
            const float o_ = 1.f / (1.f + expf(-go));

            const float cN = f_ * Cs[cell] + i_ * g_;
            Cs[cell] = cN;
            const float h = o_ * tanhf(cN);

            const float a = h * SCALE_A;
            const __half hh = __float2half_rn(a);
            const __half hl = __float2half_rn(a - __half2float(hh));
            const int inner = (blk & 7) * 8 + u;
            const uint32_t off = SWZ((uint32_t)(b * 128 + inner * 2));
            *(__half*)(hdst + off)        = hh;
            *(__half*)(hdst + 8192 + off) = hl;
        }

        __syncthreads();
        if (tid == 0) {
            asm volatile("fence.proxy.async;" ::: "memory");
            __threadfence();
            atomicAdd(&g_bar, 1u);
            volatile unsigned* p = &g_bar;
            const unsigned target = (unsigned)(t + 1) * NBLK;
            while (*p < target) { __nanosleep(64); }
            __threadfence();
            asm volatile("fence.proxy.async;" ::: "memory");
        }
        __syncthreads();
    }
}

// ---- K3: logits GEMM (fp16 split, 3 products) + fused softmax stats (R6) ----
#define LOG_SMEM (3 * (1536 + 1536 + 3072 + 3072) * 2 + 4 * 1024 + 256 + 256)
__global__ __launch_bounds__(256, 2)
void logits_mma_kernel(const float* __restrict__ bout, const int* __restrict__ ot) {
    extern __shared__ __align__(16) char dsm[];
    __half* As_h = (__half*)dsm;
    __half* As_l = As_h + 3 * 1536;
    __half* Bs_h = As_l + 3 * 1536;
    __half* Bs_l = Bs_h + 3 * 3072;
    float*  wmax = (float*)(Bs_l + 3 * 3072);
    int*    warg = (int*)(wmax + 256);
    float*  wsum = (float*)(warg + 256);
    float*  wlab = wsum + 256;
    float*  rowmax_s = wlab + 256;
    int*    labels_s = (int*)(rowmax_s + 64);

    const int tid   = threadIdx.x;
    const int lane  = tid & 31;
    const int warp  = tid >> 5;
    const int wm    = warp >> 2;
    const int wn    = warp & 3;
    const int mblk  = blockIdx.x * 64;
    const int nblk  = blockIdx.y * 128;

    if (tid < 64) labels_s[tid] = ot[64 + mblk + tid];

    const int splitA = tid >> 7;
    const int rA     = tid & 127;
    const int rowA0  = rA >> 1;
    const uint32_t aoff0 = (uint32_t)(rowA0 * 128 + (rA & 1) * 16);
    const char* aBase = (const char*)g_Hb + (size_t)blockIdx.x * HB_STEP_BYTES
                        + (size_t)splitA * 8192;
    __half* dstA = (splitA ? As_l : As_h) + rowA0 * 24 + (rA & 1) * 8;

    const __half* src[3];
    __half* arrb[3];
    int off3[3], strd[3];
#pragma unroll
    for (int s = 1; s < 3; s++) {
        int c = tid + s * 256;
        if (c < 512) {
            int r = c - 256, row = r >> 1, col = (r & 1) * 8;
            src[s] = g_Bh + (long)(nblk + row) * HID + col;
            arrb[s] = Bs_h; off3[s] = row * 24 + col; strd[s] = 3072;
        } else {
            int r = c - 512, row = r >> 1, col = (r & 1) * 8;
            src[s] = g_Bl + (long)(nblk + row) * HID + col;
            arrb[s] = Bs_l; off3[s] = row * 24 + col; strd[s] = 3072;
        }
    }

    const int q = lane >> 3, r8 = lane & 7;
    const int rowA = (q & 1) * 8 + r8;
    const int colA = (q >> 1) * 8;
    const int rowB = (q >> 1) * 8 + r8;
    const int colB = (q & 1) * 8;

    float acc[2][4][4];
#pragma unroll
    for (int i = 0; i < 2; i++)
#pragma unroll
        for (int j = 0; j < 4; j++)
#pragma unroll
            for (int k = 0; k < 4; k++) acc[i][j][k] = 0.f;

#pragma unroll
    for (int p = 0; p < 2; p++) {
        cp16(dstA + p * 1536,
             aBase + (size_t)(p >> 2) * HB_CHUNK_BYTES + SWZ(aoff0 + (uint32_t)((p & 3) * 32)));
#pragma unroll
        for (int s = 1; s < 3; s++)
            cp16(arrb[s] + p * strd[s] + off3[s], src[s] + p * 16);
        cp_commit();
    }

    for (int kk = 0; kk < 64; kk++) {
        if (kk < 63) cp_wait<1>(); else cp_wait<0>();
        __syncthreads();
        if (kk + 2 < 64) {
            const int stg = (kk + 2) % 3;
            const int k2 = kk + 2;
            cp16(dstA + stg * 1536,
                 aBase + (size_t)(k2 >> 2) * HB_CHUNK_BYTES + SWZ(aoff0 + (uint32_t)((k2 & 3) * 32)));
#pragma unroll
            for (int s = 1; s < 3; s++)
                cp16(arrb[s] + stg * strd[s] + off3[s], src[s] + k2 * 16);
            cp_commit();
        }
        const int st = kk % 3;

        uint32_t aH[2][4], aL[2][4], bH[4][2], bL[4][2];
#pragma unroll
        for (int i = 0; i < 2; i++) {
            ldm4(aH[i][0], aH[i][1], aH[i][2], aH[i][3],
                 As_h + st * 1536 + (wm * 32 + i * 16 + rowA) * 24 + colA);
            ldm4(aL[i][0], aL[i][1], aL[i][2], aL[i][3],
                 As_l + st * 1536 + (wm * 32 + i * 16 + rowA) * 24 + colA);
        }
#pragma unroll
        for (int j2 = 0; j2 < 2; j2++) {
            ldm4(bH[j2 * 2][0], bH[j2 * 2][1], bH[j2 * 2 + 1][0], bH[j2 * 2 + 1][1],
                 Bs_h + st * 3072 + (wn * 32 + j2 * 16 + rowB) * 24 + colB);
            ldm4(bL[j2 * 2][0], bL[j2 * 2][1], bL[j2 * 2 + 1][0], bL[j2 * 2 + 1][1],
                 Bs_l + st * 3072 + (wn * 32 + j2 * 16 + rowB) * 24 + colB);
        }
#pragma unroll
        for (int i = 0; i < 2; i++)
#pragma unroll
            for (int j = 0; j < 4; j++) {
                mma16816(acc[i][j], aH[i], bH[j]);
                mma16816(acc[i][j], aH[i], bL[j]);
                mma16816(acc[i][j], aL[i], bH[j]);
            }
    }

    const int groupRow = lane >> 2;
    const int colPos   = lane & 3;

    float bcol[4][2];
#pragma unroll
    for (int j = 0; j < 4; j++)
#pragma unroll
        for (int kb = 0; kb < 2; kb++)
            bcol[j][kb] = bout[nblk + wn * 32 + j * 8 + colPos * 2 + kb];

    float vals[2][2][4][2];

#pragma unroll
    for (int i = 0; i < 2; i++) {
#pragma unroll
        for (int half = 0; half < 2; half++) {
            const int row_local = wm * 32 + i * 16 + groupRow + half * 8;
            const int lbl = labels_s[row_local];
            float mv = -1e30f; int ma = 0x7fffffff; float lv = -1e30f;
#pragma unroll
            for (int j = 0; j < 4; j++) {
#pragma unroll
                for (int kb = 0; kb < 2; kb++) {
                    const int colg = nblk + wn * 32 + j * 8 + colPos * 2 + kb;
                    const float v = acc[i][j][half * 2 + kb] * INV_SCALE + bcol[j][kb];
                    vals[i][half][j][kb] = v;
                    if (v > mv) { mv = v; ma = colg; }
                    if (colg == lbl) lv = v;
                }
            }
#pragma unroll
            for (int m = 1; m < 4; m <<= 1) {
                const float ov = __shfl_xor_sync(0xffffffffu, mv, m);
                const int   oa = __shfl_xor_sync(0xffffffffu, ma, m);
                const float ol = __shfl_xor_sync(0xffffffffu, lv, m);
                if (ov > mv || (ov == mv && oa < ma)) { mv = ov; ma = oa; }
                lv = fmaxf(lv, ol);
            }
            if (colPos == 0) {
                wmax[row_local * 4 + wn] = mv;
                warg[row_local * 4 + wn] = ma;
                wlab[row_local * 4 + wn] = lv;
            }
        }
    }
    __syncthreads();

    if (tid < 64) {
        float mv = wmax[tid * 4]; int ma = warg[tid * 4]; float lv = wlab[tid * 4];
#pragma unroll
        for (int x = 1; x < 4; x++) {
            const float v = wmax[tid * 4 + x]; const int a = warg[tid * 4 + x];
            if (v > mv || (v == mv && a < ma)) { mv = v; ma = a; }
            lv = fmaxf(lv, wlab[tid * 4 + x]);
        }
        rowmax_s[tid] = mv;
        const long p = (long)(mblk + tid) * NCHUNK + blockIdx.y;
        g_pmax[p] = mv;
        g_parg[p] = ma;
        g_plab[p] = lv;
    }
    __syncthreads();

#pragma unroll
    for (int i = 0; i < 2; i++) {
#pragma unroll
        for (int half = 0; half < 2; half++) {
            const int row_local = wm * 32 + i * 16 + groupRow + half * 8;
            const float rm = rowmax_s[row_local];
            float s = 0.f;
#pragma unroll
            for (int j = 0; j < 4; j++)
#pragma unroll
                for (int kb = 0; kb < 2; kb++)
                    s += expf(vals[i][half][j][kb] - rm);
#pragma unroll
            for (int m = 1; m < 4; m <<= 1)
                s += __shfl_xor_sync(0xffffffffu, s, m);
            if (colPos == 0) wsum[row_local * 4 + wn] = s;
        }
    }
    __syncthreads();

    if (tid < 64) {
        float s = wsum[tid * 4] + wsum[tid * 4 + 1] + wsum[tid * 4 + 2] + wsum[tid * 4 + 3];
        g_psum[(long)(mblk + tid) * NCHUNK + blockIdx.y] = s;
    }
}

// ---- K4: per-row cross-chunk reduction ----
__global__ void reduce_rows_kernel(float* __restrict__ out) {
    const int m = blockIdx.x;
    const int tid = threadIdx.x;
    const long base = (long)m * NCHUNK;

    float mv = -1e30f; int ma = 0x7fffffff;
    for (int c = tid; c < NCHUNK; c += 128) {
        const float v = g_pmax[base + c];
        const int   a = g_parg[base + c];
        if (v > mv || (v == mv && a < ma)) { mv = v; ma = a; }
    }
    __shared__ float sv[128]; __shared__ int sa[128];
    sv[tid] = mv; sa[tid] = ma;
    __syncthreads();
    for (int off = 64; off > 0; off >>= 1) {
        if (tid < off) {
            const float v = sv[tid + off]; const int a = sa[tid + off];
            if (v > sv[tid] || (v == sv[tid] && a < sa[tid])) { sv[tid] = v; sa[tid] = a; }
        }
        __syncthreads();
    }
    const float gmax = sv[0];
    const int   garg = sa[0];
    __syncthreads();

    float ssum = 0.f, lab = -1e30f;
    for (int c = tid; c < NCHUNK; c += 128) {
        ssum += g_psum[base + c] * expf(g_pmax[base + c] - gmax);
        lab = fmaxf(lab, g_plab[base + c]);
    }
    __shared__ float s2[128]; __shared__ float s3[128];
    s2[tid] = ssum; s3[tid] = lab;
    __syncthreads();
    for (int off = 64; off > 0; off >>= 1) {
        if (tid < off) {
            s2[tid] += s2[tid + off];
            s3[tid] = fmaxf(s3[tid], s3[tid + off]);
        }
        __syncthreads();
    }

    if (tid == 0) {
        const float lse = gmax + logf(s2[0]);
        g_nll[m] = lse - s3[0];
        out[65 + m] = (float)garg;
    }
}

// ---- K5: loss assembly + first result row ----
__global__ void finalize_kernel(const int* __restrict__ ot, float* __restrict__ out) {
    const int tid = threadIdx.x;
    __shared__ float ps[64];
    if (tid < 64) out[1 + tid] = 1.0f;
    if (tid < 63) {
        float s = 0.f, cnt = 0.f;
        for (int b = 0; b < 64; b++) {
            const int lbl = ot[(tid + 1) * 64 + b];
            if (lbl != 0) { s += g_nll[tid * 64 + b]; cnt += 1.f; }
        }
        ps[tid] = s / fmaxf(cnt, 1.f);
    }
    __syncthreads();
    if (tid == 0) {
        float loss = 0.f;
        for (int t = 0; t < 63; t++) loss += ps[t];
        out[0] = loss;
    }
}

// ---- entry point ----
extern "C" void kernel_launch(void* const* d_in, const int* in_sizes, int n_in,
                              void* d_out, int out_size) {
    const int*   ot   = (const int*)  d_in[0];
    const float* h0   = (const float*)d_in[3];
    const float* c0   = (const float*)d_in[4];
    const float* emb  = (const float*)d_in[5];
    const float* Wih  = (const float*)d_in[6];
    const float* Whh  = (const float*)d_in[7];
    const float* bih  = (const float*)d_in[8];
    const float* bhh  = (const float*)d_in[9];
    const float* Wout = (const float*)d_in[10];
    const float* bout = (const float*)d_in[11];
    float* out = (float*)d_out;

    cudaFuncSetAttribute(lstm_persistent_kernel,
                         cudaFuncAttributeMaxDynamicSharedMemorySize, LSTM_SMEM);
    cudaFuncSetAttribute(pre_mma_kernel,
                         cudaFuncAttributeMaxDynamicSharedMemorySize, PRE_SMEM);
    cudaFuncSetAttribute(logits_mma_kernel,
                         cudaFuncAttributeMaxDynamicSharedMemorySize, LOG_SMEM);

    prep_kernel<<<(G4 * HID) / 256, 256>>>(ot, emb, Wih, Whh, h0);
    split_w_kernel<<<(VOCAB * HID / 4 + 255) / 256, 256>>>(Wout);
    pre_mma_kernel<<<dim3(63, 32), 256, PRE_SMEM>>>(bih, bhh);
    lstm_persistent_kernel<<<NBLK, 256, LSTM_SMEM>>>(c0);
    logits_mma_kernel<<<dim3(63, 250), 256, LOG_SMEM>>>(bout, ot);
    reduce_rows_kernel<<<4032, 128>>>(out);
    finalize_kernel<<<1, 64>>>(ot, out);
}

// round 10
// speedup vs baseline: 5.9729x; 1.3771x over previous
#include <cuda_runtime.h>
#include <cuda_fp16.h>
#include <math.h>
#include <stdint.h>

#define T_STEPS 64
#define BATCH   64
#define HID     1024
#define EMB     512
#define VOCAB   32000
#define G4      4096
#define M_ROWS  4032
#define NCHUNK  125
#define NBLK    128

#define SCALE_A 256.0f
#define SCALE_B 1024.0f
#define INV_SCALE (1.0f / (256.0f * 1024.0f))
#define SWZ(x) ((x) ^ (((x) >> 3) & 0x70))
#define HB_STEP_BYTES  262144
#define HB_CHUNK_BYTES 16384

__device__ __align__(16) float  g_pre  [M_ROWS * G4];
__device__ __half g_Xh   [M_ROWS * EMB];
__device__ __half g_Xl   [M_ROWS * EMB];
__device__ __half g_Wih_h[G4 * EMB];
__device__ __half g_Wih_l[G4 * EMB];
__device__ __align__(16) __half g_Hb  [63 * 131072];
__device__ __align__(16) __half g_H0b [131072];
__device__ __half g_Whh_h[G4 * HID];
__device__ __half g_Whh_l[G4 * HID];
__device__ __half g_Bh   [VOCAB * HID];
__device__ __half g_Bl   [VOCAB * HID];
__device__ float  g_pmax [M_ROWS * NCHUNK];
__device__ int    g_parg [M_ROWS * NCHUNK];
__device__ float  g_psum [M_ROWS * NCHUNK];
__device__ float  g_plab [M_ROWS * NCHUNK];
__device__ float  g_nll  [M_ROWS];
__device__ unsigned g_bar;

__device__ __forceinline__ void cp16(void* dst, const void* src) {
    uint32_t d = (uint32_t)__cvta_generic_to_shared(dst);
    asm volatile("cp.async.cg.shared.global [%0], [%1], 16;\n" :: "r"(d), "l"(src));
}
__device__ __forceinline__ void cp16s(uint32_t dst, const void* src) {
    asm volatile("cp.async.cg.shared.global [%0], [%1], 16;\n" :: "r"(dst), "l"(src));
}
__device__ __forceinline__ void cp_commit() { asm volatile("cp.async.commit_group;\n"); }
template <int N>
__device__ __forceinline__ void cp_wait() {
    asm volatile("cp.async.wait_group %0;\n" :: "n"(N));
}
__device__ __forceinline__ void bulkcp(uint32_t dst_smem, const void* src,
                                       uint32_t bytes, uint32_t mbar) {
    asm volatile(
        "cp.async.bulk.shared::cluster.global.mbarrier::complete_tx::bytes [%0], [%1], %2, [%3];"
        :: "r"(dst_smem), "l"(src), "r"(bytes), "r"(mbar) : "memory");
}
#define MBAR_INIT(mb, cnt) \
    asm volatile("mbarrier.init.shared.b64 [%0], %1;" :: "r"(mb), "r"((uint32_t)(cnt)) : "memory")
#define MBAR_EXPECT(mb, n) \
    asm volatile("mbarrier.arrive.expect_tx.shared.b64 _, [%0], %1;" :: "r"(mb), "r"((uint32_t)(n)) : "memory")
#define MBAR_ARRIVE(mb) \
    asm volatile("mbarrier.arrive.shared.b64 _, [%0];" :: "r"(mb) : "memory")
#define MBAR_WAIT(mb, par) do { \
    asm volatile( \
        "{\n\t.reg .pred P1;\n\t" \
        "WAIT_LOOP_%=:\n\t" \
        "mbarrier.try_wait.parity.acquire.cta.shared::cta.b64 P1, [%0], %1, 0x989680;\n\t" \
        "@P1 bra.uni WAIT_DONE_%=;\n\t" \
        "bra.uni WAIT_LOOP_%=;\n\t" \
        "WAIT_DONE_%=:\n\t}" \
        :: "r"(mb), "r"((uint32_t)(par)) : "memory"); \
} while (0)

__device__ __forceinline__ void ldm4(uint32_t& r0, uint32_t& r1, uint32_t& r2, uint32_t& r3,
                                     const void* p) {
    uint32_t a = (uint32_t)__cvta_generic_to_shared(p);
    asm volatile("ldmatrix.sync.aligned.m8n8.x4.shared.b16 {%0,%1,%2,%3}, [%4];\n"
                 : "=r"(r0), "=r"(r1), "=r"(r2), "=r"(r3) : "r"(a));
}
__device__ __forceinline__ void ldm4s(uint32_t& r0, uint32_t& r1, uint32_t& r2, uint32_t& r3,
                                      uint32_t a) {
    asm volatile("ldmatrix.sync.aligned.m8n8.x4.shared.b16 {%0,%1,%2,%3}, [%4];\n"
                 : "=r"(r0), "=r"(r1), "=r"(r2), "=r"(r3) : "r"(a));
}
__device__ __forceinline__ void mma16816(float* c, const uint32_t* a, const uint32_t* b) {
    asm volatile("mma.sync.aligned.m16n8k16.row.col.f32.f16.f16.f32 "
                 "{%0,%1,%2,%3}, {%4,%5,%6,%7}, {%8,%9}, {%0,%1,%2,%3};\n"
                 : "+f"(c[0]), "+f"(c[1]), "+f"(c[2]), "+f"(c[3])
                 : "r"(a[0]), "r"(a[1]), "r"(a[2]), "r"(a[3]), "r"(b[0]), "r"(b[1]));
}

// ---- P0: fused prep ----
__global__ void prep_kernel(const int* __restrict__ ot, const float* __restrict__ emb,
                            const float* __restrict__ Wih, const float* __restrict__ Whh,
                            const float* __restrict__ h0) {
    const int T = blockIdx.x * blockDim.x + threadIdx.x;
    if (T == 0) g_bar = 0u;
    if (T < BATCH * HID) {
        const int b = T >> 10, col = T & 1023;
        const int c = col >> 6, inner = col & 63;
        float a = h0[T] * SCALE_A;
        __half hh = __float2half_rn(a);
        __half hl = __float2half_rn(a - __half2float(hh));
        char* base = (char*)g_H0b + (size_t)c * HB_CHUNK_BYTES;
        const uint32_t off = SWZ((uint32_t)(b * 128 + inner * 2));
        *(__half*)(base + off)        = hh;
        *(__half*)(base + 8192 + off) = hl;
    }
    if (T < M_ROWS * EMB) {
        const int m = T >> 9, e = T & 511;
        float a = emb[(long)ot[m] * EMB + e] * SCALE_A;
        __half h = __float2half_rn(a);
        g_Xh[T] = h;
        g_Xl[T] = __float2half_rn(a - __half2float(h));
    }
    if (T < G4 * EMB) {
        float a = Wih[T] * SCALE_B;
        __half h = __float2half_rn(a);
        g_Wih_h[T] = h;
        g_Wih_l[T] = __float2half_rn(a - __half2float(h));
    }
    if (T < G4 * HID) {
        float a = Whh[T] * SCALE_B;
        __half h = __float2half_rn(a);
        g_Whh_h[T] = h;
        g_Whh_l[T] = __float2half_rn(a - __half2float(h));
    }
}

__global__ void split_w_kernel(const float* __restrict__ Wout) {
    size_t i4 = ((size_t)blockIdx.x * blockDim.x + threadIdx.x) * 4;
    if (i4 < (size_t)VOCAB * HID) {
        float4 v = *(const float4*)(Wout + i4);
        float a0 = v.x * SCALE_B, a1 = v.y * SCALE_B, a2 = v.z * SCALE_B, a3 = v.w * SCALE_B;
        __half h0 = __float2half_rn(a0), h1 = __float2half_rn(a1);
        __half h2 = __float2half_rn(a2), h3 = __float2half_rn(a3);
        __half hs[4] = {h0, h1, h2, h3};
        __half ls[4] = {__float2half_rn(a0 - __half2float(h0)),
                        __float2half_rn(a1 - __half2float(h1)),
                        __float2half_rn(a2 - __half2float(h2)),
                        __float2half_rn(a3 - __half2float(h3))};
        *(uint2*)(g_Bh + i4) = *(uint2*)hs;
        *(uint2*)(g_Bl + i4) = *(uint2*)ls;
    }
}

// ---- K1: pre-gates GEMM (fp16 split, 3 products) -> blocked g_pre ----
#define PRE_SMEM (3 * (1536 + 1536 + 3072 + 3072) * 2)
__global__ __launch_bounds__(256, 2)
void pre_mma_kernel(const float* __restrict__ bih, const float* __restrict__ bhh) {
    extern __shared__ __align__(16) char dsm[];
    __half* As_h = (__half*)dsm;
    __half* As_l = As_h + 3 * 1536;
    __half* Bs_h = As_l + 3 * 1536;
    __half* Bs_l = Bs_h + 3 * 3072;

    const int tid  = threadIdx.x;
    const int lane = tid & 31;
    const int warp = tid >> 5;
    const int wm   = warp >> 2;
    const int wn   = warp & 3;
    const int mblk = blockIdx.x * 64;
    const int nblk = blockIdx.y * 128;

    const __half* src[3];
    __half* arrb[3];
    int off3[3], strd[3];
#pragma unroll
    for (int s = 0; s < 3; s++) {
        int c = tid + s * 256;
        if (c < 128) {
            int row = c >> 1, col = (c & 1) * 8;
            src[s] = g_Xh + (long)(mblk + row) * EMB + col;
            arrb[s] = As_h; off3[s] = row * 24 + col; strd[s] = 1536;
        } else if (c < 256) {
            int r = c - 128, row = r >> 1, col = (r & 1) * 8;
            src[s] = g_Xl + (long)(mblk + row) * EMB + col;
            arrb[s] = As_l; off3[s] = row * 24 + col; strd[s] = 1536;
        } else if (c < 512) {
            int r = c - 256, row = r >> 1, col = (r & 1) * 8;
            src[s] = g_Wih_h + (long)(nblk + row) * EMB + col;
            arrb[s] = Bs_h; off3[s] = row * 24 + col; strd[s] = 3072;
        } else {
            int r = c - 512, row = r >> 1, col = (r & 1) * 8;
            src[s] = g_Wih_l + (long)(nblk + row) * EMB + col;
            arrb[s] = Bs_l; off3[s] = row * 24 + col; strd[s] = 3072;
        }
    }

    const int q = lane >> 3, r8 = lane & 7;
    const int rowA = (q & 1) * 8 + r8;
    const int colA = (q >> 1) * 8;
    const int rowB = (q >> 1) * 8 + r8;
    const int colB = (q & 1) * 8;

    float acc[2][4][4];
#pragma unroll
    for (int i = 0; i < 2; i++)
#pragma unroll
        for (int j = 0; j < 4; j++)
#pragma unroll
            for (int k = 0; k < 4; k++) acc[i][j][k] = 0.f;

#pragma unroll
    for (int p = 0; p < 2; p++) {
#pragma unroll
        for (int s = 0; s < 3; s++)
            cp16(arrb[s] + p * strd[s] + off3[s], src[s] + p * 16);
        cp_commit();
    }

    for (int kk = 0; kk < 32; kk++) {
        if (kk < 31) cp_wait<1>(); else cp_wait<0>();
        __syncthreads();
        if (kk + 2 < 32) {
            const int stg = (kk + 2) % 3;
#pragma unroll
            for (int s = 0; s < 3; s++)
                cp16(arrb[s] + stg * strd[s] + off3[s], src[s] + (kk + 2) * 16);
            cp_commit();
        }
        const int st = kk % 3;

        uint32_t aH[2][4], aL[2][4], bH[4][2], bL[4][2];
#pragma unroll
        for (int i = 0; i < 2; i++) {
            ldm4(aH[i][0], aH[i][1], aH[i][2], aH[i][3],
                 As_h + st * 1536 + (wm * 32 + i * 16 + rowA) * 24 + colA);
            ldm4(aL[i][0], aL[i][1], aL[i][2], aL[i][3],
                 As_l + st * 1536 + (wm * 32 + i * 16 + rowA) * 24 + colA);
        }
#pragma unroll
        for (int j2 = 0; j2 < 2; j2++) {
            ldm4(bH[j2 * 2][0], bH[j2 * 2][1], bH[j2 * 2 + 1][0], bH[j2 * 2 + 1][1],
                 Bs_h + st * 3072 + (wn * 32 + j2 * 16 + rowB) * 24 + colB);
            ldm4(bL[j2 * 2][0], bL[j2 * 2][1], bL[j2 * 2 + 1][0], bL[j2 * 2 + 1][1],
                 Bs_l + st * 3072 + (wn * 32 + j2 * 16 + rowB) * 24 + colB);
        }
#pragma unroll
        for (int i = 0; i < 2; i++)
#pragma unroll
            for (int j = 0; j < 4; j++) {
                mma16816(acc[i][j], aH[i], bH[j]);
                mma16816(acc[i][j], aH[i], bL[j]);
                mma16816(acc[i][j], aL[i], bH[j]);
            }
    }

    const int groupRow = lane >> 2;
    const int colPos   = lane & 3;
#pragma unroll
    for (int j = 0; j < 4; j++) {
        const int col  = nblk + wn * 32 + j * 8 + colPos * 2;
        const int gate = col >> 10;
        const int r10  = col & 1023;
        const int blk2 = r10 >> 3;
        const int u    = r10 & 7;
        const float bb0 = bih[col] + bhh[col];
        const float bb1 = bih[col + 1] + bhh[col + 1];
#pragma unroll
        for (int i = 0; i < 2; i++) {
#pragma unroll
            for (int half = 0; half < 2; half++) {
                const int m = mblk + wm * 32 + i * 16 + groupRow + half * 8;
                const int t = m >> 6, b = m & 63;
                float2 v;
                v.x = acc[i][j][half * 2]     * INV_SCALE + bb0;
                v.y = acc[i][j][half * 2 + 1] * INV_SCALE + bb1;
                *(float2*)(g_pre + (((size_t)(t * 128 + blk2) * 64 + b) * 32 + gate * 8 + u)) = v;
            }
        }
    }
}

// ---- K2: persistent LSTM (R9, passing, 8.9us/step) ----
#define LSTM_SMEM 216400
__global__ __launch_bounds__(256, 1)
void lstm_persistent_kernel(const float* __restrict__ c0) {
    extern __shared__ __align__(16) char smem[];
    __half* Ws_h = (__half*)smem;
    __half* Ws_l = Ws_h + 32 * 1032;
    float*  Gs   = (float*)(smem + 197632);
    float*  Cs   = (float*)(smem + 206080);
    float*  Ps   = (float*)(smem + 208128);
    const uint32_t sb  = (uint32_t)__cvta_generic_to_shared(smem);
    const uint32_t HS  = sb + 132096;
    const uint32_t PSA = sb + 208128;
    const uint32_t MBF = sb + 216320;
    const uint32_t MBP = sb + 216352;
    const uint32_t MBC = sb + 216360;

    const int tid  = threadIdx.x;
    const int lane = tid & 31;
    const int warp = tid >> 5;
    const int mw   = warp & 3;
    const int nh   = warp >> 2;
    const int blk  = blockIdx.x;

    for (int c = tid; c < 8192; c += 256) {
        const int split = c >> 12;
        const int rr    = (c >> 7) & 31;
        const int seg   = c & 127;
        const long nglob = (long)((rr >> 3) * 1024 + blk * 8 + (rr & 7));
        const __half* srcp = (split ? g_Whh_l : g_Whh_h) + nglob * HID + seg * 8;
        float4 v = *(const float4*)srcp;
        *(float4*)((split ? Ws_l : Ws_h) + rr * 1032 + seg * 8) = v;
    }
    for (int cell = tid; cell < 512; cell += 256) {
        const int b = cell >> 3, u = cell & 7;
        Cs[cell] = c0[b * HID + blk * 8 + u];
    }
    if (tid == 0) {
#pragma unroll
        for (int s = 0; s < 4; s++) MBAR_INIT(MBF + s * 8, 1);
        MBAR_INIT(MBP, 1);
#pragma unroll
        for (int s = 0; s < 4; s++) MBAR_INIT(MBC + s * 8, 8);
    }
    __syncthreads();

    const int q = lane >> 3, r8 = lane & 7;
    const int rowA = (q & 1) * 8 + r8;
    const int colA = (q >> 1) * 8;
    const int rowB = (q >> 1) * 8 + r8;
    const int colB = (q & 1) * 8;
    const int groupRow = lane >> 2;
    const int colPos   = lane & 3;

    const uint32_t aRowByte = (uint32_t)((mw * 16 + rowA) * 128 + colA * 2);
    const int c2 = blk >> 3;

    for (int t = 0; t < 63; t++) {
        const char* hsrc = t ? ((const char*)g_Hb + (size_t)(t - 1) * HB_STEP_BYTES)
                             : (const char*)g_H0b;

        if (tid == 0) {
#pragma unroll
            for (int m = 0; m < 3; m++) {
                const int F = t * 4;
                if (F) MBAR_WAIT(MBC + m * 8, (F - 1) & 1);
                MBAR_EXPECT(MBF + m * 8, HB_CHUNK_BYTES);
                bulkcp(HS + m * 16384, hsrc + (size_t)m * HB_CHUNK_BYTES,
                       HB_CHUNK_BYTES, MBF + m * 8);
            }
            MBAR_EXPECT(MBP, 8192);
            bulkcp(PSA, (const char*)g_pre + ((size_t)t * 128 + blk) * 8192, 8192, MBP);
        }

        float aHH[2][4], aHL[2][4], aLH[2][4];
#pragma unroll
        for (int j = 0; j < 2; j++)
#pragma unroll
            for (int k = 0; k < 4; k++) { aHH[j][k] = 0.f; aHL[j][k] = 0.f; aLH[j][k] = 0.f; }

        for (int c = 0; c < 16; c++) {
            if (tid == 0 && c + 3 < 16) {
                const int m = c + 3;
                const int s = m & 3;
                const int F = t * 4 + (m >> 2);
                if (F) MBAR_WAIT(MBC + s * 8, (F - 1) & 1);
                MBAR_EXPECT(MBF + s * 8, HB_CHUNK_BYTES);
                bulkcp(HS + s * 16384, hsrc + (size_t)m * HB_CHUNK_BYTES,
                       HB_CHUNK_BYTES, MBF + s * 8);
            }
            MBAR_WAIT(MBF + (c & 3) * 8, (c >> 2) & 1);
            __syncwarp();
            const uint32_t hb = HS + (c & 3) * 16384;

#pragma unroll
            for (int k16 = 0; k16 < 4; k16++) {
                uint32_t aH[4], aL[4], bH[2][2], bL[2][2];
                const uint32_t aoff = SWZ(aRowByte + (uint32_t)(k16 * 32));
                ldm4s(aH[0], aH[1], aH[2], aH[3], hb + aoff);
                ldm4s(aL[0], aL[1], aL[2], aL[3], hb + 8192 + aoff);
                ldm4(bH[0][0], bH[0][1], bH[1][0], bH[1][1],
                     Ws_h + (nh * 16 + rowB) * 1032 + c * 64 + k16 * 16 + colB);
                ldm4(bL[0][0], bL[0][1], bL[1][0], bL[1][1],
                     Ws_l + (nh * 16 + rowB) * 1032 + c * 64 + k16 * 16 + colB);
#pragma unroll
                for (int j = 0; j < 2; j++) {
                    mma16816(aHH[j], aH, bH[j]);
                    mma16816(aHL[j], aH, bL[j]);
                    mma16816(aLH[j], aL, bH[j]);
                }
            }
            __syncwarp();
            if (lane == 0) MBAR_ARRIVE(MBC + (c & 3) * 8);
        }

#pragma unroll
        for (int j = 0; j < 2; j++) {
            const int col = nh * 16 + j * 8 + colPos * 2;
            Gs[(mw * 16 + groupRow) * 33 + col]         = aHH[j][0] + aHL[j][0] + aLH[j][0];
            Gs[(mw * 16 + groupRow) * 33 + col + 1]     = aHH[j][1] + aHL[j][1] + aLH[j][1];
            Gs[(mw * 16 + groupRow + 8) * 33 + col]     = aHH[j][2] + aHL[j][2] + aLH[j][2];
            Gs[(mw * 16 + groupRow + 8) * 33 + col + 1] = aHH[j][3] + aHL[j][3] + aLH[j][3];
        }
        __syncthreads();
        MBAR_WAIT(MBP, t & 1);

        char* hdst = (char*)g_Hb + (size_t)t * HB_STEP_BYTES + (size_t)c2 * HB_CHUNK_BYTES;
        for (int cell = tid; cell < 512; cell += 256) {
            const int b = cell >> 3, u = cell & 7;
            const float gi = Gs[b * 33 + u]      * INV_SCALE + Ps[b * 32 + u];
            const float gf = Gs[b * 33 + 8 + u]  * INV_SCALE + Ps[b * 32 + 8 + u];
            const float gg = Gs[b * 33 + 16 + u] * INV_SCALE + Ps[b * 32 + 16 + u];
            const float go = Gs[b * 33 + 24 + u] * INV_SCALE + Ps[b * 32 + 24 + u];

            const float i_ = 1.f / (1.f + expf(-gi));
            const float f_ = 1.f / (1.f + expf(-gf));
            const float g_ = tanhf(gg);
            const float o_ = 1.f / (1.f + expf(-go));

            const float cN = f_ * Cs[cell] + i_ * g_;
            Cs[cell] = cN;
            const float h = o_ * tanhf(cN);

            const float a = h * SCALE_A;
            const __half hh = __float2half_rn(a);
            const __half hl = __float2half_rn(a - __half2float(hh));
            const int inner = (blk & 7) * 8 + u;
            const uint32_t off = SWZ((uint32_t)(b * 128 + inner * 2));
            *(__half*)(hdst + off)        = hh;
            *(__half*)(hdst + 8192 + off) = hl;
        }

        __syncthreads();
        if (tid == 0) {
            asm volatile("fence.proxy.async;" ::: "memory");
            __threadfence();
            atomicAdd(&g_bar, 1u);
            volatile unsigned* p = &g_bar;
            const unsigned target = (unsigned)(t + 1) * NBLK;
            while (*p < target) { __nanosleep(64); }
            __threadfence();
            asm volatile("fence.proxy.async;" ::: "memory");
        }
        __syncthreads();
    }
}

// =======================================================================
// K3: logits GEMM, 128M x 256N tile, 512 threads (16 warps = 4M x 4N),
// K-chunk 64, 2 stages (96KB each), 3-product fp16 split, fused stats.
// Stage layout: A[2 sub][2 split][8KB swz blocks], B[2 split][256 x 128B swz].
// =======================================================================
#define LOG_STG   98304
#define LOG_TAIL  196608
#define LOG_SMEM  (LOG_TAIL + 1024 + 512 + 4 * 2048 + 512)
__global__ __launch_bounds__(512, 1)
void logits_mma_kernel(const float* __restrict__ bout, const int* __restrict__ ot) {
    extern __shared__ __align__(16) char dsm[];
    const uint32_t sb = (uint32_t)__cvta_generic_to_shared(dsm);
    float* bout_s    = (float*)(dsm + LOG_TAIL);            // 256 f
    int*   labels_s  = (int*)(dsm + LOG_TAIL + 1024);       // 128 i
    float* wmax      = (float*)(dsm + LOG_TAIL + 1536);     // [128][4]
    int*   warg      = (int*)(dsm + LOG_TAIL + 1536 + 2048);
    float* wsum      = (float*)(dsm + LOG_TAIL + 1536 + 4096);
    float* wlab      = (float*)(dsm + LOG_TAIL + 1536 + 6144);
    float* rowmax_s  = (float*)(dsm + LOG_TAIL + 1536 + 8192); // 128 f

    const int tid  = threadIdx.x;
    const int lane = tid & 31;
    const int warp = tid >> 5;
    const int wm   = warp >> 2;          // 0..3  (32-row group)
    const int wn   = warp & 3;           // 0..3  (64-col group)
    const int mblk = blockIdx.x * 128;
    const int nblk = blockIdx.y * 256;

    if (tid < 256) bout_s[tid] = bout[nblk + tid];
    if (tid < 128) labels_s[tid] = (mblk + tid < M_ROWS) ? ot[64 + mblk + tid] : -1;

    // ---- loader addressing ----
    // A: 4 chunks/thread. group g = tid>>7: sub = g>>1, split = g&1.
    const int ag    = tid >> 7;
    const int aSub  = ag >> 1;
    const int aSpl  = ag & 1;
    int stepA = blockIdx.x * 2 + aSub;
    if (stepA > 62) stepA = 62;
    const char* aSrc0 = (const char*)g_Hb + (size_t)stepA * HB_STEP_BYTES
                        + aSpl * 8192 + (tid & 127) * 16;
    const uint32_t aDst0 = sb + aSub * 16384 + aSpl * 8192 + (tid & 127) * 16;
    // B: 8 chunks/thread: r=0..7: split=r>>2, rr=r&3; row=(tid>>3)+64*rr, seg=tid&7
    const __half* bSrcH = g_Bh + (size_t)(nblk + (tid >> 3)) * HID + (tid & 7) * 8;
    const __half* bSrcL = g_Bl + (size_t)(nblk + (tid >> 3)) * HID + (tid & 7) * 8;
    const uint32_t bDst0 = sb + 32768 + SWZ((uint32_t)((tid >> 3) * 128 + (tid & 7) * 16));

    const int q = lane >> 3, r8 = lane & 7;
    const int rowA = (q & 1) * 8 + r8;
    const int colA = (q >> 1) * 8;
    const int rowB = (q >> 1) * 8 + r8;
    const int colB = (q & 1) * 8;

    // per-warp ldmatrix bases
    const uint32_t aStageBase = sb + (wm >> 1) * 16384;
    const uint32_t aRowByte   = (uint32_t)(((wm & 1) * 32 + rowA) * 128 + colA * 2);
    const uint32_t bRowByteBase = (uint32_t)((wn * 64 + rowB) * 128 + colB * 2);

    float acc[2][8][4];
#pragma unroll
    for (int i = 0; i < 2; i++)
#pragma unroll
        for (int j = 0; j < 8; j++)
#pragma unroll
            for (int k = 0; k < 4; k++) acc[i][j][k] = 0.f;

    // ---- fill helper (inlined twice in prologue, once in loop) ----
#define LOG_FILL(stgbase, c) do { \
    const char* asrc = aSrc0 + (size_t)(c) * HB_CHUNK_BYTES; \
    _Pragma("unroll") \
    for (int r = 0; r < 4; r++) \
        cp16s((stgbase) + aDst0 - sb + r * 2048, asrc + r * 2048); \
    _Pragma("unroll") \
    for (int r = 0; r < 8; r++) { \
        const __half* bs = ((r >> 2) ? bSrcL : bSrcH) + (size_t)(r & 3) * 65536 + (c) * 64; \
        cp16s((stgbase) + bDst0 - sb + (r >> 2) * 32768 + (r & 3) * 8192, bs); \
    } \
    cp_commit(); \
} while (0)

    LOG_FILL(sb, 0);
    LOG_FILL(sb + LOG_STG, 1);

    for (int c = 0; c < 16; c++) {
        if (c < 15) cp_wait<1>(); else cp_wait<0>();
        __syncthreads();
        const uint32_t stg = sb + (c & 1) * LOG_STG;
        const uint32_t aBaseS = stg + (aStageBase - sb);
        const uint32_t bBaseS = stg + 32768;

#pragma unroll
        for (int k16 = 0; k16 < 4; k16++) {
            uint32_t aH[2][4], aL[2][4];
#pragma unroll
            for (int i = 0; i < 2; i++) {
                const uint32_t ao = SWZ(aRowByte + (uint32_t)(i * 16 * 128 + k16 * 32));
                ldm4s(aH[i][0], aH[i][1], aH[i][2], aH[i][3], aBaseS + ao);
                ldm4s(aL[i][0], aL[i][1], aL[i][2], aL[i][3], aBaseS + 8192 + ao);
            }
#pragma unroll
            for (int j2 = 0; j2 < 4; j2++) {
                uint32_t bH[2][2], bL[2][2];
                const uint32_t bo = SWZ(bRowByteBase + (uint32_t)(j2 * 16 * 128 + k16 * 32));
                ldm4s(bH[0][0], bH[0][1], bH[1][0], bH[1][1], bBaseS + bo);
                ldm4s(bL[0][0], bL[0][1], bL[1][0], bL[1][1], bBaseS + 32768 + bo);
#pragma unroll
                for (int i = 0; i < 2; i++)
#pragma unroll
                    for (int jj = 0; jj < 2; jj++) {
                        mma16816(acc[i][j2 * 2 + jj], aH[i], bH[jj]);
                        mma16816(acc[i][j2 * 2 + jj], aH[i], bL[jj]);
                        mma16816(acc[i][j2 * 2 + jj], aL[i], bH[jj]);
                    }
            }
        }
        __syncthreads();
        if (c + 2 < 16) LOG_FILL(sb + (c & 1) * LOG_STG, c + 2);
    }

    // ---- epilogue: fused softmax stats ----
    const int groupRow = lane >> 2;
    const int colPos   = lane & 3;

#pragma unroll
    for (int i = 0; i < 2; i++) {
#pragma unroll
        for (int half = 0; half < 2; half++) {
            const int row_local = wm * 32 + i * 16 + groupRow + half * 8;
            const int lbl = labels_s[row_local];
            float mv = -1e30f; int ma = 0x7fffffff; float lv = -1e30f;
#pragma unroll
            for (int j = 0; j < 8; j++) {
#pragma unroll
                for (int kb = 0; kb < 2; kb++) {
                    const int cl = wn * 64 + j * 8 + colPos * 2 + kb;
                    const float v = acc[i][j][half * 2 + kb] * INV_SCALE + bout_s[cl];
                    const int colg = nblk + cl;
                    if (v > mv) { mv = v; ma = colg; }
                    if (colg == lbl) lv = v;
                }
            }
#pragma unroll
            for (int m = 1; m < 4; m <<= 1) {
                const float ov = __shfl_xor_sync(0xffffffffu, mv, m);
                const int   oa = __shfl_xor_sync(0xffffffffu, ma, m);
                const float ol = __shfl_xor_sync(0xffffffffu, lv, m);
                if (ov > mv || (ov == mv && oa < ma)) { mv = ov; ma = oa; }
                lv = fmaxf(lv, ol);
            }
            if (colPos == 0) {
                wmax[row_local * 4 + wn] = mv;
                warg[row_local * 4 + wn] = ma;
                wlab[row_local * 4 + wn] = lv;
            }
        }
    }
    __syncthreads();

    if (tid < 128) {
        float mv = wmax[tid * 4]; int ma = warg[tid * 4]; float lv = wlab[tid * 4];
#pragma unroll
        for (int x = 1; x < 4; x++) {
            const float v = wmax[tid * 4 + x]; const int a = warg[tid * 4 + x];
            if (v > mv || (v == mv && a < ma)) { mv = v; ma = a; }
            lv = fmaxf(lv, wlab[tid * 4 + x]);
        }
        rowmax_s[tid] = mv;
        if (mblk + tid < M_ROWS) {
            const long p = (long)(mblk + tid) * NCHUNK + blockIdx.y;
            g_pmax[p] = mv;
            g_parg[p] = ma;
            g_plab[p] = lv;
        }
    }
    __syncthreads();

#pragma unroll
    for (int i = 0; i < 2; i++) {
#pragma unroll
        for (int half = 0; half < 2; half++) {
            const int row_local = wm * 32 + i * 16 + groupRow + half * 8;
            const float rm = rowmax_s[row_local];
            float s = 0.f;
#pragma unroll
            for (int j = 0; j < 8; j++)
#pragma unroll
                for (int kb = 0; kb < 2; kb++) {
                    const int cl = wn * 64 + j * 8 + colPos * 2 + kb;
                    s += expf(acc[i][j][half * 2 + kb] * INV_SCALE + bout_s[cl] - rm);
                }
#pragma unroll
            for (int m = 1; m < 4; m <<= 1)
                s += __shfl_xor_sync(0xffffffffu, s, m);
            if (colPos == 0) wsum[row_local * 4 + wn] = s;
        }
    }
    __syncthreads();

    if (tid < 128 && mblk + tid < M_ROWS) {
        float s = wsum[tid * 4] + wsum[tid * 4 + 1] + wsum[tid * 4 + 2] + wsum[tid * 4 + 3];
        g_psum[(long)(mblk + tid) * NCHUNK + blockIdx.y] = s;
    }
}

// ---- K4: per-row cross-chunk reduction ----
__global__ void reduce_rows_kernel(float* __restrict__ out) {
    const int m = blockIdx.x;
    const int tid = threadIdx.x;
    const long base = (long)m * NCHUNK;

    float mv = -1e30f; int ma = 0x7fffffff;
    for (int c = tid; c < NCHUNK; c += 128) {
        const float v = g_pmax[base + c];
        const int   a = g_parg[base + c];
        if (v > mv || (v == mv && a < ma)) { mv = v; ma = a; }
    }
    __shared__ float sv[128]; __shared__ int sa[128];
    sv[tid] = mv; sa[tid] = ma;
    __syncthreads();
    for (int off = 64; off > 0; off >>= 1) {
        if (tid < off) {
            const float v = sv[tid + off]; const int a = sa[tid + off];
            if (v > sv[tid] || (v == sv[tid] && a < sa[tid])) { sv[tid] = v; sa[tid] = a; }
        }
        __syncthreads();
    }
    const float gmax = sv[0];
    const int   garg = sa[0];
    __syncthreads();

    float ssum = 0.f, lab = -1e30f;
    for (int c = tid; c < NCHUNK; c += 128) {
        ssum += g_psum[base + c] * expf(g_pmax[base + c] - gmax);
        lab = fmaxf(lab, g_plab[base + c]);
    }
    __shared__ float s2[128]; __shared__ float s3[128];
    s2[tid] = ssum; s3[tid] = lab;
    __syncthreads();
    for (int off = 64; off > 0; off >>= 1) {
        if (tid < off) {
            s2[tid] += s2[tid + off];
            s3[tid] = fmaxf(s3[tid], s3[tid + off]);
        }
        __syncthreads();
    }

    if (tid == 0) {
        const float lse = gmax + logf(s2[0]);
        g_nll[m] = lse - s3[0];
        out[65 + m] = (float)garg;
    }
}

// ---- K5: loss assembly + first result row ----
__global__ void finalize_kernel(const int* __restrict__ ot, float* __restrict__ out) {
    const int tid = threadIdx.x;
    __shared__ float ps[64];
    if (tid < 64) out[1 + tid] = 1.0f;
    if (tid < 63) {
        float s = 0.f, cnt = 0.f;
        for (int b = 0; b < 64; b++) {
            const int lbl = ot[(tid + 1) * 64 + b];
            if (lbl != 0) { s += g_nll[tid * 64 + b]; cnt += 1.f; }
        }
        ps[tid] = s / fmaxf(cnt, 1.f);
    }
    __syncthreads();
    if (tid == 0) {
        float loss = 0.f;
        for (int t = 0; t < 63; t++) loss += ps[t];
        out[0] = loss;
    }
}

// ---- entry point ----
extern "C" void kernel_launch(void* const* d_in, const int* in_sizes, int n_in,
                              void* d_out, int out_size) {
    const int*   ot   = (const int*)  d_in[0];
    const float* h0   = (const float*)d_in[3];
    const float* c0   = (const float*)d_in[4];
    const float* emb  = (const float*)d_in[5];
    const float* Wih  = (const float*)d_in[6];
    const float* Whh  = (const float*)d_in[7];
    const float* bih  = (const float*)d_in[8];
    const float* bhh  = (const float*)d_in[9];
    const float* Wout = (const float*)d_in[10];
    const float* bout = (const float*)d_in[11];
    float* out = (float*)d_out;

    cudaFuncSetAttribute(lstm_persistent_kernel,
                         cudaFuncAttributeMaxDynamicSharedMemorySize, LSTM_SMEM);
    cudaFuncSetAttribute(pre_mma_kernel,
                         cudaFuncAttributeMaxDynamicSharedMemorySize, PRE_SMEM);
    cudaFuncSetAttribute(logits_mma_kernel,
                         cudaFuncAttributeMaxDynamicSharedMemorySize, LOG_SMEM);

    prep_kernel<<<(G4 * HID) / 256, 256>>>(ot, emb, Wih, Whh, h0);
    split_w_kernel<<<(VOCAB * HID / 4 + 255) / 256, 256>>>(Wout);
    pre_mma_kernel<<<dim3(63, 32), 256, PRE_SMEM>>>(bih, bhh);
    lstm_persistent_kernel<<<NBLK, 256, LSTM_SMEM>>>(c0);
    logits_mma_kernel<<<dim3(32, 125), 512, LOG_SMEM>>>(bout, ot);
    reduce_rows_kernel<<<4032, 128>>>(out);
    finalize_kernel<<<1, 64>>>(ot, out);
}

// round 11
// speedup vs baseline: 6.4476x; 1.0795x over previous
#include <cuda_runtime.h>
#include <cuda_fp16.h>
#include <math.h>
#include <stdint.h>

#define BATCH   64
#define HID     1024
#define EMB     512
#define VOCAB   32000
#define G4      4096
#define M_ROWS  4032
#define NCHUNK  125
#define NBLK    128

#define SCALE_A 256.0f
#define SCALE_B 1024.0f
#define INV_SCALE (1.0f / (256.0f * 1024.0f))
#define SWZ(x) ((x) ^ (((x) >> 3) & 0x70))
#define HB_STEP_BYTES  262144
#define HB_CHUNK_BYTES 16384

__device__ __align__(16) float  g_pre  [M_ROWS * G4];
__device__ __half g_Xh   [M_ROWS * EMB];
__device__ __half g_Xl   [M_ROWS * EMB];
__device__ __half g_Wih_h[G4 * EMB];
__device__ __half g_Wih_l[G4 * EMB];
__device__ __align__(16) __half g_Hb  [63 * 131072];
__device__ __align__(16) __half g_H0b [131072];
__device__ __half g_Whh_h[G4 * HID];
__device__ __half g_Whh_l[G4 * HID];
__device__ __align__(16) __half g_Bb  [(size_t)125 * 16 * 32768];  // blocked+swizzled W_out splits
__device__ float  g_pmax [M_ROWS * NCHUNK];
__device__ int    g_parg [M_ROWS * NCHUNK];
__device__ float  g_psum [M_ROWS * NCHUNK];
__device__ float  g_plab [M_ROWS * NCHUNK];
__device__ float  g_nll  [M_ROWS];
__device__ unsigned g_bar;

__device__ __forceinline__ void cp16(void* dst, const void* src) {
    uint32_t d = (uint32_t)__cvta_generic_to_shared(dst);
    asm volatile("cp.async.cg.shared.global [%0], [%1], 16;\n" :: "r"(d), "l"(src));
}
__device__ __forceinline__ void cp_commit() { asm volatile("cp.async.commit_group;\n"); }
template <int N>
__device__ __forceinline__ void cp_wait() {
    asm volatile("cp.async.wait_group %0;\n" :: "n"(N));
}
__device__ __forceinline__ void bulkcp(uint32_t dst_smem, const void* src,
                                       uint32_t bytes, uint32_t mbar) {
    asm volatile(
        "cp.async.bulk.shared::cluster.global.mbarrier::complete_tx::bytes [%0], [%1], %2, [%3];"
        :: "r"(dst_smem), "l"(src), "r"(bytes), "r"(mbar) : "memory");
}
#define MBAR_INIT(mb, cnt) \
    asm volatile("mbarrier.init.shared.b64 [%0], %1;" :: "r"(mb), "r"((uint32_t)(cnt)) : "memory")
#define MBAR_EXPECT(mb, n) \
    asm volatile("mbarrier.arrive.expect_tx.shared.b64 _, [%0], %1;" :: "r"(mb), "r"((uint32_t)(n)) : "memory")
#define MBAR_ARRIVE(mb) \
    asm volatile("mbarrier.arrive.shared.b64 _, [%0];" :: "r"(mb) : "memory")
#define MBAR_WAIT(mb, par) do { \
    asm volatile( \
        "{\n\t.reg .pred P1;\n\t" \
        "WAIT_LOOP_%=:\n\t" \
        "mbarrier.try_wait.parity.acquire.cta.shared::cta.b64 P1, [%0], %1, 0x989680;\n\t" \
        "@P1 bra.uni WAIT_DONE_%=;\n\t" \
        "bra.uni WAIT_LOOP_%=;\n\t" \
        "WAIT_DONE_%=:\n\t}" \
        :: "r"(mb), "r"((uint32_t)(par)) : "memory"); \
} while (0)

__device__ __forceinline__ void ldm4(uint32_t& r0, uint32_t& r1, uint32_t& r2, uint32_t& r3,
                                     const void* p) {
    uint32_t a = (uint32_t)__cvta_generic_to_shared(p);
    asm volatile("ldmatrix.sync.aligned.m8n8.x4.shared.b16 {%0,%1,%2,%3}, [%4];\n"
                 : "=r"(r0), "=r"(r1), "=r"(r2), "=r"(r3) : "r"(a));
}
__device__ __forceinline__ void ldm4s(uint32_t& r0, uint32_t& r1, uint32_t& r2, uint32_t& r3,
                                      uint32_t a) {
    asm volatile("ldmatrix.sync.aligned.m8n8.x4.shared.b16 {%0,%1,%2,%3}, [%4];\n"
                 : "=r"(r0), "=r"(r1), "=r"(r2), "=r"(r3) : "r"(a));
}
__device__ __forceinline__ void mma16816(float* c, const uint32_t* a, const uint32_t* b) {
    asm volatile("mma.sync.aligned.m16n8k16.row.col.f32.f16.f16.f32 "
                 "{%0,%1,%2,%3}, {%4,%5,%6,%7}, {%8,%9}, {%0,%1,%2,%3};\n"
                 : "+f"(c[0]), "+f"(c[1]), "+f"(c[2]), "+f"(c[3])
                 : "r"(a[0]), "r"(a[1]), "r"(a[2]), "r"(a[3]), "r"(b[0]), "r"(b[1]));
}

// ---- P0: fused prep (barrier, h0 split, x gather+split, Wih/Whh splits, W_out block) --
__global__ void prep_all_kernel(const int* __restrict__ ot, const float* __restrict__ emb,
                                const float* __restrict__ Wih, const float* __restrict__ Whh,
                                const float* __restrict__ h0, const float* __restrict__ Wout) {
    const int T = blockIdx.x * blockDim.x + threadIdx.x;
    if (T == 0) g_bar = 0u;
    if (T < BATCH * HID) {
        const int b = T >> 10, col = T & 1023;
        const int c = col >> 6, inner = col & 63;
        float a = h0[T] * SCALE_A;
        __half hh = __float2half_rn(a);
        __half hl = __float2half_rn(a - __half2float(hh));
        char* base = (char*)g_H0b + (size_t)c * HB_CHUNK_BYTES;
        const uint32_t off = SWZ((uint32_t)(b * 128 + inner * 2));
        *(__half*)(base + off)        = hh;
        *(__half*)(base + 8192 + off) = hl;
    }
    if (T < M_ROWS * EMB) {
        const int m = T >> 9, e = T & 511;
        float a = emb[(long)ot[m] * EMB + e] * SCALE_A;
        __half h = __float2half_rn(a);
        g_Xh[T] = h;
        g_Xl[T] = __float2half_rn(a - __half2float(h));
    }
    if (T < G4 * EMB) {
        float a = Wih[T] * SCALE_B;
        __half h = __float2half_rn(a);
        g_Wih_h[T] = h;
        g_Wih_l[T] = __float2half_rn(a - __half2float(h));
    }
    if (T < G4 * HID) {
        float a = Whh[T] * SCALE_B;
        __half h = __float2half_rn(a);
        g_Whh_h[T] = h;
        g_Whh_l[T] = __float2half_rn(a - __half2float(h));
    }
    // W_out split into blocked layout: block(tile,chunk)=64KB [split][rr(4)][64rows x 128B swz]
    const size_t i4 = (size_t)T * 4;
    if (i4 < (size_t)VOCAB * HID) {
        const int v = (int)(i4 >> 10), k = (int)(i4 & 1023);
        float4 w = *(const float4*)(Wout + i4);
        float a0 = w.x * SCALE_B, a1 = w.y * SCALE_B, a2 = w.z * SCALE_B, a3 = w.w * SCALE_B;
        __half h0v = __float2half_rn(a0), h1 = __float2half_rn(a1);
        __half h2 = __float2half_rn(a2), h3 = __float2half_rn(a3);
        __half hs[4] = {h0v, h1, h2, h3};
        __half ls[4] = {__float2half_rn(a0 - __half2float(h0v)),
                        __float2half_rn(a1 - __half2float(h1)),
                        __float2half_rn(a2 - __half2float(h2)),
                        __float2half_rn(a3 - __half2float(h3))};
        const int tile = v >> 8, rl = v & 255, chunk = k >> 6, kin = k & 63;
        char* blk = (char*)g_Bb + ((size_t)(tile * 16 + chunk)) * 65536;
        const uint32_t off = (uint32_t)((rl >> 6) * 8192) + SWZ((uint32_t)((rl & 63) * 128 + kin * 2));
        *(uint2*)(blk + off)         = *(uint2*)hs;
        *(uint2*)(blk + 32768 + off) = *(uint2*)ls;
    }
}

// ---- K1: pre-gates GEMM (fp16 split, 3 products) -> blocked g_pre ----
#define PRE_SMEM (3 * (1536 + 1536 + 3072 + 3072) * 2)
__global__ __launch_bounds__(256, 2)
void pre_mma_kernel(const float* __restrict__ bih, const float* __restrict__ bhh) {
    extern __shared__ __align__(16) char dsm[];
    __half* As_h = (__half*)dsm;
    __half* As_l = As_h + 3 * 1536;
    __half* Bs_h = As_l + 3 * 1536;
    __half* Bs_l = Bs_h + 3 * 3072;

    const int tid  = threadIdx.x;
    const int lane = tid & 31;
    const int warp = tid >> 5;
    const int wm   = warp >> 2;
    const int wn   = warp & 3;
    const int mblk = blockIdx.x * 64;
    const int nblk = blockIdx.y * 128;

    const __half* src[3];
    __half* arrb[3];
    int off3[3], strd[3];
#pragma unroll
    for (int s = 0; s < 3; s++) {
        int c = tid + s * 256;
        if (c < 128) {
            int row = c >> 1, col = (c & 1) * 8;
            src[s] = g_Xh + (long)(mblk + row) * EMB + col;
            arrb[s] = As_h; off3[s] = row * 24 + col; strd[s] = 1536;
        } else if (c < 256) {
            int r = c - 128, row = r >> 1, col = (r & 1) * 8;
            src[s] = g_Xl + (long)(mblk + row) * EMB + col;
            arrb[s] = As_l; off3[s] = row * 24 + col; strd[s] = 1536;
        } else if (c < 512) {
            int r = c - 256, row = r >> 1, col = (r & 1) * 8;
            src[s] = g_Wih_h + (long)(nblk + row) * EMB + col;
            arrb[s] = Bs_h; off3[s] = row * 24 + col; strd[s] = 3072;
        } else {
            int r = c - 512, row = r >> 1, col = (r & 1) * 8;
            src[s] = g_Wih_l + (long)(nblk + row) * EMB + col;
            arrb[s] = Bs_l; off3[s] = row * 24 + col; strd[s] = 3072;
        }
    }

    const int q = lane >> 3, r8 = lane & 7;
    const int rowA = (q & 1) * 8 + r8;
    const int colA = (q >> 1) * 8;
    const int rowB = (q >> 1) * 8 + r8;
    const int colB = (q & 1) * 8;

    float acc[2][4][4];
#pragma unroll
    for (int i = 0; i < 2; i++)
#pragma unroll
        for (int j = 0; j < 4; j++)
#pragma unroll
            for (int k = 0; k < 4; k++) acc[i][j][k] = 0.f;

#pragma unroll
    for (int p = 0; p < 2; p++) {
#pragma unroll
        for (int s = 0; s < 3; s++)
            cp16(arrb[s] + p * strd[s] + off3[s], src[s] + p * 16);
        cp_commit();
    }

    for (int kk = 0; kk < 32; kk++) {
        if (kk < 31) cp_wait<1>(); else cp_wait<0>();
        __syncthreads();
        if (kk + 2 < 32) {
            const int stg = (kk + 2) % 3;
#pragma unroll
            for (int s = 0; s < 3; s++)
                cp16(arrb[s] + stg * strd[s] + off3[s], src[s] + (kk + 2) * 16);
            cp_commit();
        }
        const int st = kk % 3;

        uint32_t aH[2][4], aL[2][4], bH[4][2], bL[4][2];
#pragma unroll
        for (int i = 0; i < 2; i++) {
            ldm4(aH[i][0], aH[i][1], aH[i][2], aH[i][3],
                 As_h + st * 1536 + (wm * 32 + i * 16 + rowA) * 24 + colA);
            ldm4(aL[i][0], aL[i][1], aL[i][2], aL[i][3],
                 As_l + st * 1536 + (wm * 32 + i * 16 + rowA) * 24 + colA);
        }
#pragma unroll
        for (int j2 = 0; j2 < 2; j2++) {
            ldm4(bH[j2 * 2][0], bH[j2 * 2][1], bH[j2 * 2 + 1][0], bH[j2 * 2 + 1][1],
                 Bs_h + st * 3072 + (wn * 32 + j2 * 16 + rowB) * 24 + colB);
            ldm4(bL[j2 * 2][0], bL[j2 * 2][1], bL[j2 * 2 + 1][0], bL[j2 * 2 + 1][1],
                 Bs_l + st * 3072 + (wn * 32 + j2 * 16 + rowB) * 24 + colB);
        }
#pragma unroll
        for (int i = 0; i < 2; i++)
#pragma unroll
            for (int j = 0; j < 4; j++) {
                mma16816(acc[i][j], aH[i], bH[j]);
                mma16816(acc[i][j], aH[i], bL[j]);
                mma16816(acc[i][j], aL[i], bH[j]);
            }
    }

    const int groupRow = lane >> 2;
    const int colPos   = lane & 3;
#pragma unroll
    for (int j = 0; j < 4; j++) {
        const int col  = nblk + wn * 32 + j * 8 + colPos * 2;
        const int gate = col >> 10;
        const int r10  = col & 1023;
        const int blk2 = r10 >> 3;
        const int u    = r10 & 7;
        const float bb0 = bih[col] + bhh[col];
        const float bb1 = bih[col + 1] + bhh[col + 1];
#pragma unroll
        for (int i = 0; i < 2; i++) {
#pragma unroll
            for (int half = 0; half < 2; half++) {
                const int m = mblk + wm * 32 + i * 16 + groupRow + half * 8;
                const int t = m >> 6, b = m & 63;
                float2 v;
                v.x = acc[i][j][half * 2]     * INV_SCALE + bb0;
                v.y = acc[i][j][half * 2 + 1] * INV_SCALE + bb1;
                *(float2*)(g_pre + (((size_t)(t * 128 + blk2) * 64 + b) * 32 + gate * 8 + u)) = v;
            }
        }
    }
}

// ---- K2: persistent LSTM (R9/R10 passing version, 8.9us/step) ----
#define LSTM_SMEM 216400
__global__ __launch_bounds__(256, 1)
void lstm_persistent_kernel(const float* __restrict__ c0) {
    extern __shared__ __align__(16) char smem[];
    __half* Ws_h = (__half*)smem;
    __half* Ws_l = Ws_h + 32 * 1032;
    float*  Gs   = (float*)(smem + 197632);
    float*  Cs   = (float*)(smem + 206080);
    float*  Ps   = (float*)(smem + 208128);
    const uint32_t sb  = (uint32_t)__cvta_generic_to_shared(smem);
    const uint32_t HS  = sb + 132096;
    const uint32_t PSA = sb + 208128;
    const uint32_t MBF = sb + 216320;
    const uint32_t MBP = sb + 216352;
    const uint32_t MBC = sb + 216360;

    const int tid  = threadIdx.x;
    const int lane = tid & 31;
    const int warp = tid >> 5;
    const int mw   = warp & 3;
    const int nh   = warp >> 2;
    const int blk  = blockIdx.x;

    for (int c = tid; c < 8192; c += 256) {
        const int split = c >> 12;
        const int rr    = (c >> 7) & 31;
        const int seg   = c & 127;
        const long nglob = (long)((rr >> 3) * 1024 + blk * 8 + (rr & 7));
        const __half* srcp = (split ? g_Whh_l : g_Whh_h) + nglob * HID + seg * 8;
        float4 v = *(const float4*)srcp;
        *(float4*)((split ? Ws_l : Ws_h) + rr * 1032 + seg * 8) = v;
    }
    for (int cell = tid; cell < 512; cell += 256) {
        const int b = cell >> 3, u = cell & 7;
        Cs[cell] = c0[b * HID + blk * 8 + u];
    }
    if (tid == 0) {
#pragma unroll
        for (int s = 0; s < 4; s++) MBAR_INIT(MBF + s * 8, 1);
        MBAR_INIT(MBP, 1);
#pragma unroll
        for (int s = 0; s < 4; s++) MBAR_INIT(MBC + s * 8, 8);
    }
    __syncthreads();

    const int q = lane >> 3, r8 = lane & 7;
    const int rowA = (q & 1) * 8 + r8;
    const int colA = (q >> 1) * 8;
    const int rowB = (q >> 1) * 8 + r8;
    const int colB = (q & 1) * 8;
    const int groupRow = lane >> 2;
    const int colPos   = lane & 3;

    const uint32_t aRowByte = (uint32_t)((mw * 16 + rowA) * 128 + colA * 2);
    const int c2 = blk >> 3;

    for (int t = 0; t < 63; t++) {
        const char* hsrc = t ? ((const char*)g_Hb + (size_t)(t - 1) * HB_STEP_BYTES)
                             : (const char*)g_H0b;

        if (tid == 0) {
#pragma unroll
            for (int m = 0; m < 3; m++) {
                const int F = t * 4;
                if (F) MBAR_WAIT(MBC + m * 8, (F - 1) & 1);
                MBAR_EXPECT(MBF + m * 8, HB_CHUNK_BYTES);
                bulkcp(HS + m * 16384, hsrc + (size_t)m * HB_CHUNK_BYTES,
                       HB_CHUNK_BYTES, MBF + m * 8);
            }
            MBAR_EXPECT(MBP, 8192);
            bulkcp(PSA, (const char*)g_pre + ((size_t)t * 128 + blk) * 8192, 8192, MBP);
        }

        float aHH[2][4], aHL[2][4], aLH[2][4];
#pragma unroll
        for (int j = 0; j < 2; j++)
#pragma unroll
            for (int k = 0; k < 4; k++) { aHH[j][k] = 0.f; aHL[j][k] = 0.f; aLH[j][k] = 0.f; }

        for (int c = 0; c < 16; c++) {
            if (tid == 0 && c + 3 < 16) {
                const int m = c + 3;
                const int s = m & 3;
                const int F = t * 4 + (m >> 2);
                if (F) MBAR_WAIT(MBC + s * 8, (F - 1) & 1);
                MBAR_EXPECT(MBF + s * 8, HB_CHUNK_BYTES);
                bulkcp(HS + s * 16384, hsrc + (size_t)m * HB_CHUNK_BYTES,
                       HB_CHUNK_BYTES, MBF + s * 8);
            }
            MBAR_WAIT(MBF + (c & 3) * 8, (c >> 2) & 1);
            __syncwarp();
            const uint32_t hb = HS + (c & 3) * 16384;

#pragma unroll
            for (int k16 = 0; k16 < 4; k16++) {
                uint32_t aH[4], aL[4], bH[2][2], bL[2][2];
                const uint32_t aoff = SWZ(aRowByte + (uint32_t)(k16 * 32));
                ldm4s(aH[0], aH[1], aH[2], aH[3], hb + aoff);
                ldm4s(aL[0], aL[1], aL[2], aL[3], hb + 8192 + aoff);
                ldm4(bH[0][0], bH[0][1], bH[1][0], bH[1][1],
                     Ws_h + (nh * 16 + rowB) * 1032 + c * 64 + k16 * 16 + colB);
                ldm4(bL[0][0], bL[0][1], bL[1][0], bL[1][1],
                     Ws_l + (nh * 16 + rowB) * 1032 + c * 64 + k16 * 16 + colB);
#pragma unroll
                for (int j = 0; j < 2; j++) {
                    mma16816(aHH[j], aH, bH[j]);
                    mma16816(aHL[j], aH, bL[j]);
                    mma16816(aLH[j], aL, bH[j]);
                }
            }
            __syncwarp();
            if (lane == 0) MBAR_ARRIVE(MBC + (c & 3) * 8);
        }

#pragma unroll
        for (int j = 0; j < 2; j++) {
            const int col = nh * 16 + j * 8 + colPos * 2;
            Gs[(mw * 16 + groupRow) * 33 + col]         = aHH[j][0] + aHL[j][0] + aLH[j][0];
            Gs[(mw * 16 + groupRow) * 33 + col + 1]     = aHH[j][1] + aHL[j][1] + aLH[j][1];
            Gs[(mw * 16 + groupRow + 8) * 33 + col]     = aHH[j][2] + aHL[j][2] + aLH[j][2];
            Gs[(mw * 16 + groupRow + 8) * 33 + col + 1] = aHH[j][3] + aHL[j][3] + aLH[j][3];
        }
        __syncthreads();
        MBAR_WAIT(MBP, t & 1);

        char* hdst = (char*)g_Hb + (size_t)t * HB_STEP_BYTES + (size_t)c2 * HB_CHUNK_BYTES;
        for (int cell = tid; cell < 512; cell += 256) {
            const int b = cell >> 3, u = cell & 7;
            const float gi = Gs[b * 33 + u]      * INV_SCALE + Ps[b * 32 + u];
            const float gf = Gs[b * 33 + 8 + u]  * INV_SCALE + Ps[b * 32 + 8 + u];
            const float gg = Gs[b * 33 + 16 + u] * INV_SCALE + Ps[b * 32 + 16 + u];
            const float go = Gs[b * 33 + 24 + u] * INV_SCALE + Ps[b * 32 + 24 + u];

            const float i_ = 1.f / (1.f + expf(-gi));
            const float f_ = 1.f / (1.f + expf(-gf));
            const float g_ = tanhf(gg);
            const float o_ = 1.f / (1.f + expf(-go));

            const float cN = f_ * Cs[cell] + i_ * g_;
            Cs[cell] = cN;
            const float h = o_ * tanhf(cN);

            const float a = h * SCALE_A;
            const __half hh = __float2half_rn(a);
            const __half hl = __float2half_rn(a - __half2float(hh));
            const int inner = (blk & 7) * 8 + u;
            const uint32_t off = SWZ((uint32_t)(b * 128 + inner * 2));
            *(__half*)(hdst + off)        = hh;
            *(__half*)(hdst + 8192 + off) = hl;
        }

        __syncthreads();
        if (tid == 0) {
            asm volatile("fence.proxy.async;" ::: "memory");
            __threadfence();
            atomicAdd(&g_bar, 1u);
            volatile unsigned* p = &g_bar;
            const unsigned target = (unsigned)(t + 1) * NBLK;
            while (*p < target) { __nanosleep(64); }
            __threadfence();
            asm volatile("fence.proxy.async;" ::: "memory");
        }
        __syncthreads();
    }
}

// =======================================================================
// K3: logits GEMM 128x256, 512 thr, bulkcp producer/consumer pipeline.
// Stage (96KB): A sub0 16KB | A sub1 16KB | B 64KB ([split][rr(4)][8KB swz]).
// No __syncthreads / per-thread cp.async in the main loop.
// =======================================================================
#define LOG_STG   98304
#define LOG_TAIL  196608
#define LOG_SMEM  (LOG_TAIL + 1024 + 512 + 4 * 2048 + 512 + 64)
__global__ __launch_bounds__(512, 1)
void logits_mma_kernel(const float* __restrict__ bout, const int* __restrict__ ot) {
    extern __shared__ __align__(16) char dsm[];
    const uint32_t sb = (uint32_t)__cvta_generic_to_shared(dsm);
    float* bout_s    = (float*)(dsm + LOG_TAIL);
    int*   labels_s  = (int*)(dsm + LOG_TAIL + 1024);
    float* wmax      = (float*)(dsm + LOG_TAIL + 1536);
    int*   warg      = (int*)(dsm + LOG_TAIL + 1536 + 2048);
    float* wsum      = (float*)(dsm + LOG_TAIL + 1536 + 4096);
    float* wlab      = (float*)(dsm + LOG_TAIL + 1536 + 6144);
    float* rowmax_s  = (float*)(dsm + LOG_TAIL + 1536 + 8192);
    const uint32_t MBFL = sb + LOG_TAIL + 1536 + 8192 + 512;   // full[2]
    const uint32_t MBCN = MBFL + 16;                            // consumed[2]

    const int tid  = threadIdx.x;
    const int lane = tid & 31;
    const int warp = tid >> 5;
    const int wm   = warp >> 2;
    const int wn   = warp & 3;
    const int mblk = blockIdx.x * 128;
    const int nblk = blockIdx.y * 256;

    if (tid < 256) bout_s[tid] = bout[nblk + tid];
    if (tid < 128) labels_s[tid] = (mblk + tid < M_ROWS) ? ot[64 + mblk + tid] : -1;
    if (tid == 0) {
        MBAR_INIT(MBFL, 1);     MBAR_INIT(MBFL + 8, 1);
        MBAR_INIT(MBCN, 16);    MBAR_INIT(MBCN + 8, 16);
    }
    __syncthreads();

    // producer source pointers
    int s0 = blockIdx.x * 2;     if (s0 > 62) s0 = 62;
    int s1 = blockIdx.x * 2 + 1; if (s1 > 62) s1 = 62;
    const char* a0 = (const char*)g_Hb + (size_t)s0 * HB_STEP_BYTES;
    const char* a1 = (const char*)g_Hb + (size_t)s1 * HB_STEP_BYTES;
    const char* bb = (const char*)g_Bb + (size_t)(blockIdx.y * 16) * 65536;

    if (tid == 0) {
#pragma unroll
        for (int p = 0; p < 2; p++) {
            const uint32_t stg = sb + p * LOG_STG;
            MBAR_EXPECT(MBFL + p * 8, 98304);
            bulkcp(stg,         a0 + (size_t)p * HB_CHUNK_BYTES, 16384, MBFL + p * 8);
            bulkcp(stg + 16384, a1 + (size_t)p * HB_CHUNK_BYTES, 16384, MBFL + p * 8);
            bulkcp(stg + 32768, bb + (size_t)p * 65536,          65536, MBFL + p * 8);
        }
    }

    const int q = lane >> 3, r8 = lane & 7;
    const int rowA = (q & 1) * 8 + r8;
    const int colA = (q >> 1) * 8;
    const int rowB = (q >> 1) * 8 + r8;
    const int colB = (q & 1) * 8;

    const uint32_t aStageOff  = (uint32_t)((wm >> 1) * 16384);
    const uint32_t aRowByte   = (uint32_t)(((wm & 1) * 32 + rowA) * 128 + colA * 2);
    const uint32_t bRowByteBase = (uint32_t)((wn * 64 + rowB) * 128 + colB * 2);

    float acc[2][8][4];
#pragma unroll
    for (int i = 0; i < 2; i++)
#pragma unroll
        for (int j = 0; j < 8; j++)
#pragma unroll
            for (int k = 0; k < 4; k++) acc[i][j][k] = 0.f;

    for (int c = 0; c < 16; c++) {
        MBAR_WAIT(MBFL + (c & 1) * 8, (c >> 1) & 1);
        __syncwarp();
        const uint32_t stg = sb + (c & 1) * LOG_STG;
        const uint32_t aBaseS = stg + aStageOff;
        const uint32_t bBaseS = stg + 32768;

#pragma unroll
        for (int k16 = 0; k16 < 4; k16++) {
            uint32_t aH[2][4], aL[2][4];
#pragma unroll
            for (int i = 0; i < 2; i++) {
                const uint32_t ao = SWZ(aRowByte + (uint32_t)(i * 16 * 128 + k16 * 32));
                ldm4s(aH[i][0], aH[i][1], aH[i][2], aH[i][3], aBaseS + ao);
                ldm4s(aL[i][0], aL[i][1], aL[i][2], aL[i][3], aBaseS + 8192 + ao);
            }
#pragma unroll
            for (int j2 = 0; j2 < 4; j2++) {
                uint32_t bH[2][2], bL[2][2];
                const uint32_t bo = SWZ(bRowByteBase + (uint32_t)(j2 * 16 * 128 + k16 * 32));
                ldm4s(bH[0][0], bH[0][1], bH[1][0], bH[1][1], bBaseS + bo);
                ldm4s(bL[0][0], bL[0][1], bL[1][0], bL[1][1], bBaseS + 32768 + bo);
#pragma unroll
                for (int i = 0; i < 2; i++)
#pragma unroll
                    for (int jj = 0; jj < 2; jj++) {
                        mma16816(acc[i][j2 * 2 + jj], aH[i], bH[jj]);
                        mma16816(acc[i][j2 * 2 + jj], aH[i], bL[jj]);
                        mma16816(acc[i][j2 * 2 + jj], aL[i], bH[jj]);
                    }
            }
        }
        __syncwarp();
        if (lane == 0) MBAR_ARRIVE(MBCN + (c & 1) * 8);
        if (tid == 0 && c + 2 < 16) {
            MBAR_WAIT(MBCN + (c & 1) * 8, (c >> 1) & 1);
            const uint32_t stg2 = sb + (c & 1) * LOG_STG;
            MBAR_EXPECT(MBFL + (c & 1) * 8, 98304);
            bulkcp(stg2,         a0 + (size_t)(c + 2) * HB_CHUNK_BYTES, 16384, MBFL + (c & 1) * 8);
            bulkcp(stg2 + 16384, a1 + (size_t)(c + 2) * HB_CHUNK_BYTES, 16384, MBFL + (c & 1) * 8);
            bulkcp(stg2 + 32768, bb + (size_t)(c + 2) * 65536,          65536, MBFL + (c & 1) * 8);
        }
    }

    // ---- epilogue (unchanged) ----
    const int groupRow = lane >> 2;
    const int colPos   = lane & 3;

#pragma unroll
    for (int i = 0; i < 2; i++) {
#pragma unroll
        for (int half = 0; half < 2; half++) {
            const int row_local = wm * 32 + i * 16 + groupRow + half * 8;
            const int lbl = labels_s[row_local];
            float mv = -1e30f; int ma = 0x7fffffff; float lv = -1e30f;
#pragma unroll
            for (int j = 0; j < 8; j++) {
#pragma unroll
                for (int kb = 0; kb < 2; kb++) {
                    const int cl = wn * 64 + j * 8 + colPos * 2 + kb;
                    const float v = acc[i][j][half * 2 + kb] * INV_SCALE + bout_s[cl];
                    const int colg = nblk + cl;
                    if (v > mv) { mv = v; ma = colg; }
                    if (colg == lbl) lv = v;
                }
            }
#pragma unroll
            for (int m = 1; m < 4; m <<= 1) {
                const float ov = __shfl_xor_sync(0xffffffffu, mv, m);
                const int   oa = __shfl_xor_sync(0xffffffffu, ma, m);
                const float ol = __shfl_xor_sync(0xffffffffu, lv, m);
                if (ov > mv || (ov == mv && oa < ma)) { mv = ov; ma = oa; }
                lv = fmaxf(lv, ol);
            }
            if (colPos == 0) {
                wmax[row_local * 4 + wn] = mv;
                warg[row_local * 4 + wn] = ma;
                wlab[row_local * 4 + wn] = lv;
            }
        }
    }
    __syncthreads();

    if (tid < 128) {
        float mv = wmax[tid * 4]; int ma = warg[tid * 4]; float lv = wlab[tid * 4];
#pragma unroll
        for (int x = 1; x < 4; x++) {
            const float v = wmax[tid * 4 + x]; const int a = warg[tid * 4 + x];
            if (v > mv || (v == mv && a < ma)) { mv = v; ma = a; }
            lv = fmaxf(lv, wlab[tid * 4 + x]);
        }
        rowmax_s[tid] = mv;
        if (mblk + tid < M_ROWS) {
            const long p = (long)(mblk + tid) * NCHUNK + blockIdx.y;
            g_pmax[p] = mv;
            g_parg[p] = ma;
            g_plab[p] = lv;
        }
    }
    __syncthreads();

#pragma unroll
    for (int i = 0; i < 2; i++) {
#pragma unroll
        for (int half = 0; half < 2; half++) {
            const int row_local = wm * 32 + i * 16 + groupRow + half * 8;
            const float rm = rowmax_s[row_local];
            float s = 0.f;
#pragma unroll
            for (int j = 0; j < 8; j++)
#pragma unroll
                for (int kb = 0; kb < 2; kb++) {
                    const int cl = wn * 64 + j * 8 + colPos * 2 + kb;
                    s += expf(acc[i][j][half * 2 + kb] * INV_SCALE + bout_s[cl] - rm);
                }
#pragma unroll
            for (int m = 1; m < 4; m <<= 1)
                s += __shfl_xor_sync(0xffffffffu, s, m);
            if (colPos == 0) wsum[row_local * 4 + wn] = s;
        }
    }
    __syncthreads();

    if (tid < 128 && mblk + tid < M_ROWS) {
        float s = wsum[tid * 4] + wsum[tid * 4 + 1] + wsum[tid * 4 + 2] + wsum[tid * 4 + 3];
        g_psum[(long)(mblk + tid) * NCHUNK + blockIdx.y] = s;
    }
}

// ---- K4: per-row cross-chunk reduction ----
__global__ void reduce_rows_kernel(float* __restrict__ out) {
    const int m = blockIdx.x;
    const int tid = threadIdx.x;
    const long base = (long)m * NCHUNK;

    float mv = -1e30f; int ma = 0x7fffffff;
    for (int c = tid; c < NCHUNK; c += 128) {
        const float v = g_pmax[base + c];
        const int   a = g_parg[base + c];
        if (v > mv || (v == mv && a < ma)) { mv = v; ma = a; }
    }
    __shared__ float sv[128]; __shared__ int sa[128];
    sv[tid] = mv; sa[tid] = ma;
    __syncthreads();
    for (int off = 64; off > 0; off >>= 1) {
        if (tid < off) {
            const float v = sv[tid + off]; const int a = sa[tid + off];
            if (v > sv[tid] || (v == sv[tid] && a < sa[tid])) { sv[tid] = v; sa[tid] = a; }
        }
        __syncthreads();
    }
    const float gmax = sv[0];
    const int   garg = sa[0];
    __syncthreads();

    float ssum = 0.f, lab = -1e30f;
    for (int c = tid; c < NCHUNK; c += 128) {
        ssum += g_psum[base + c] * expf(g_pmax[base + c] - gmax);
        lab = fmaxf(lab, g_plab[base + c]);
    }
    __shared__ float s2[128]; __shared__ float s3[128];
    s2[tid] = ssum; s3[tid] = lab;
    __syncthreads();
    for (int off = 64; off > 0; off >>= 1) {
        if (tid < off) {
            s2[tid] += s2[tid + off];
            s3[tid] = fmaxf(s3[tid], s3[tid + off]);
        }
        __syncthreads();
    }

    if (tid == 0) {
        const float lse = gmax + logf(s2[0]);
        g_nll[m] = lse - s3[0];
        out[65 + m] = (float)garg;
    }
}

// ---- K5: loss assembly + first result row ----
__global__ void finalize_kernel(const int* __restrict__ ot, float* __restrict__ out) {
    const int tid = threadIdx.x;
    __shared__ float ps[64];
    if (tid < 64) out[1 + tid] = 1.0f;
    if (tid < 63) {
        float s = 0.f, cnt = 0.f;
        for (int b = 0; b < 64; b++) {
            const int lbl = ot[(tid + 1) * 64 + b];
            if (lbl != 0) { s += g_nll[tid * 64 + b]; cnt += 1.f; }
        }
        ps[tid] = s / fmaxf(cnt, 1.f);
    }
    __syncthreads();
    if (tid == 0) {
        float loss = 0.f;
        for (int t = 0; t < 63; t++) loss += ps[t];
        out[0] = loss;
    }
}

// ---- entry point ----
extern "C" void kernel_launch(void* const* d_in, const int* in_sizes, int n_in,
                              void* d_out, int out_size) {
    const int*   ot   = (const int*)  d_in[0];
    const float* h0   = (const float*)d_in[3];
    const float* c0   = (const float*)d_in[4];
    const float* emb  = (const float*)d_in[5];
    const float* Wih  = (const float*)d_in[6];
    const float* Whh  = (const float*)d_in[7];
    const float* bih  = (const float*)d_in[8];
    const float* bhh  = (const float*)d_in[9];
    const float* Wout = (const float*)d_in[10];
    const float* bout = (const float*)d_in[11];
    float* out = (float*)d_out;

    cudaFuncSetAttribute(lstm_persistent_kernel,
                         cudaFuncAttributeMaxDynamicSharedMemorySize, LSTM_SMEM);
    cudaFuncSetAttribute(pre_mma_kernel,
                         cudaFuncAttributeMaxDynamicSharedMemorySize, PRE_SMEM);
    cudaFuncSetAttribute(logits_mma_kernel,
                         cudaFuncAttributeMaxDynamicSharedMemorySize, LOG_SMEM);

    prep_all_kernel<<<(VOCAB * HID / 4) / 256, 256>>>(ot, emb, Wih, Whh, h0, Wout);
    pre_mma_kernel<<<dim3(63, 32), 256, PRE_SMEM>>>(bih, bhh);
    lstm_persistent_kernel<<<NBLK, 256, LSTM_SMEM>>>(c0);
    logits_mma_kernel<<<dim3(32, 125), 512, LOG_SMEM>>>(bout, ot);
    reduce_rows_kernel<<<4032, 128>>>(out);
    finalize_kernel<<<1, 64>>>(ot, out);
}

// round 12
// speedup vs baseline: 6.4652x; 1.0027x over previous
#include <cuda_runtime.h>
#include <cuda_fp16.h>
#include <math.h>
#include <stdint.h>

#define BATCH   64
#define HID     1024
#define EMB     512
#define VOCAB   32000
#define G4      4096
#define M_ROWS  4032
#define NCHUNK  125
#define NBLK    128

#define SCALE_A 256.0f
#define SCALE_B 1024.0f
#define INV_SCALE (1.0f / (256.0f * 1024.0f))
#define SWZ(x) ((x) ^ (((x) >> 3) & 0x70))
#define HB_STEP_BYTES  262144
#define HB_CHUNK_BYTES 16384

__device__ __align__(16) float  g_pre  [M_ROWS * G4];
__device__ __half g_Xh   [M_ROWS * EMB];
__device__ __half g_Xl   [M_ROWS * EMB];
__device__ __half g_Wih_h[G4 * EMB];
__device__ __half g_Wih_l[G4 * EMB];
__device__ __align__(16) __half g_Hb  [63 * 131072];
__device__ __align__(16) __half g_H0b [131072];
__device__ __half g_Whh_h[G4 * HID];
__device__ __half g_Whh_l[G4 * HID];
__device__ __align__(16) __half g_Bb  [(size_t)125 * 16 * 32768];  // blocked+swizzled W_out splits
__device__ float  g_pmax [M_ROWS * NCHUNK];
__device__ int    g_parg [M_ROWS * NCHUNK];
__device__ float  g_psum [M_ROWS * NCHUNK];
__device__ float  g_plab [M_ROWS * NCHUNK];
__device__ float  g_nll  [M_ROWS];
__device__ unsigned g_bar;

__device__ __forceinline__ void cp16(void* dst, const void* src) {
    uint32_t d = (uint32_t)__cvta_generic_to_shared(dst);
    asm volatile("cp.async.cg.shared.global [%0], [%1], 16;\n" :: "r"(d), "l"(src));
}
__device__ __forceinline__ void cp_commit() { asm volatile("cp.async.commit_group;\n"); }
template <int N>
__device__ __forceinline__ void cp_wait() {
    asm volatile("cp.async.wait_group %0;\n" :: "n"(N));
}
__device__ __forceinline__ void bulkcp(uint32_t dst_smem, const void* src,
                                       uint32_t bytes, uint32_t mbar) {
    asm volatile(
        "cp.async.bulk.shared::cluster.global.mbarrier::complete_tx::bytes [%0], [%1], %2, [%3];"
        :: "r"(dst_smem), "l"(src), "r"(bytes), "r"(mbar) : "memory");
}
#define MBAR_INIT(mb, cnt) \
    asm volatile("mbarrier.init.shared.b64 [%0], %1;" :: "r"(mb), "r"((uint32_t)(cnt)) : "memory")
#define MBAR_EXPECT(mb, n) \
    asm volatile("mbarrier.arrive.expect_tx.shared.b64 _, [%0], %1;" :: "r"(mb), "r"((uint32_t)(n)) : "memory")
#define MBAR_ARRIVE(mb) \
    asm volatile("mbarrier.arrive.shared.b64 _, [%0];" :: "r"(mb) : "memory")
#define MBAR_WAIT(mb, par) do { \
    asm volatile( \
        "{\n\t.reg .pred P1;\n\t" \
        "WAIT_LOOP_%=:\n\t" \
        "mbarrier.try_wait.parity.acquire.cta.shared::cta.b64 P1, [%0], %1, 0x989680;\n\t" \
        "@P1 bra.uni WAIT_DONE_%=;\n\t" \
        "bra.uni WAIT_LOOP_%=;\n\t" \
        "WAIT_DONE_%=:\n\t}" \
        :: "r"(mb), "r"((uint32_t)(par)) : "memory"); \
} while (0)

__device__ __forceinline__ void ldm4(uint32_t& r0, uint32_t& r1, uint32_t& r2, uint32_t& r3,
                                     const void* p) {
    uint32_t a = (uint32_t)__cvta_generic_to_shared(p);
    asm volatile("ldmatrix.sync.aligned.m8n8.x4.shared.b16 {%0,%1,%2,%3}, [%4];\n"
                 : "=r"(r0), "=r"(r1), "=r"(r2), "=r"(r3) : "r"(a));
}
__device__ __forceinline__ void ldm4s(uint32_t& r0, uint32_t& r1, uint32_t& r2, uint32_t& r3,
                                      uint32_t a) {
    asm volatile("ldmatrix.sync.aligned.m8n8.x4.shared.b16 {%0,%1,%2,%3}, [%4];\n"
                 : "=r"(r0), "=r"(r1), "=r"(r2), "=r"(r3) : "r"(a));
}
__device__ __forceinline__ void mma16816(float* c, const uint32_t* a, const uint32_t* b) {
    asm volatile("mma.sync.aligned.m16n8k16.row.col.f32.f16.f16.f32 "
                 "{%0,%1,%2,%3}, {%4,%5,%6,%7}, {%8,%9}, {%0,%1,%2,%3};\n"
                 : "+f"(c[0]), "+f"(c[1]), "+f"(c[2]), "+f"(c[3])
                 : "r"(a[0]), "r"(a[1]), "r"(a[2]), "r"(a[3]), "r"(b[0]), "r"(b[1]));
}

// ---- P0: fused prep (barrier, h0 split, x gather+split, Wih/Whh splits, W_out block) --
__global__ void prep_all_kernel(const int* __restrict__ ot, const float* __restrict__ emb,
                                const float* __restrict__ Wih, const float* __restrict__ Whh,
                                const float* __restrict__ h0, const float* __restrict__ Wout) {
    const int T = blockIdx.x * blockDim.x + threadIdx.x;
    if (T == 0) g_bar = 0u;
    if (T < BATCH * HID) {
        const int b = T >> 10, col = T & 1023;
        const int c = col >> 6, inner = col & 63;
        float a = h0[T] * SCALE_A;
        __half hh = __float2half_rn(a);
        __half hl = __float2half_rn(a - __half2float(hh));
        char* base = (char*)g_H0b + (size_t)c * HB_CHUNK_BYTES;
        const uint32_t off = SWZ((uint32_t)(b * 128 + inner * 2));
        *(__half*)(base + off)        = hh;
        *(__half*)(base + 8192 + off) = hl;
    }
    if (T < M_ROWS * EMB) {
        const int m = T >> 9, e = T & 511;
        float a = emb[(long)ot[m] * EMB + e] * SCALE_A;
        __half h = __float2half_rn(a);
        g_Xh[T] = h;
        g_Xl[T] = __float2half_rn(a - __half2float(h));
    }
    if (T < G4 * EMB) {
        float a = Wih[T] * SCALE_B;
        __half h = __float2half_rn(a);
        g_Wih_h[T] = h;
        g_Wih_l[T] = __float2half_rn(a - __half2float(h));
    }
    if (T < G4 * HID) {
        float a = Whh[T] * SCALE_B;
        __half h = __float2half_rn(a);
        g_Whh_h[T] = h;
        g_Whh_l[T] = __float2half_rn(a - __half2float(h));
    }
    const size_t i4 = (size_t)T * 4;
    if (i4 < (size_t)VOCAB * HID) {
        const int v = (int)(i4 >> 10), k = (int)(i4 & 1023);
        float4 w = *(const float4*)(Wout + i4);
        float a0 = w.x * SCALE_B, a1 = w.y * SCALE_B, a2 = w.z * SCALE_B, a3 = w.w * SCALE_B;
        __half h0v = __float2half_rn(a0), h1 = __float2half_rn(a1);
        __half h2 = __float2half_rn(a2), h3 = __float2half_rn(a3);
        __half hs[4] = {h0v, h1, h2, h3};
        __half ls[4] = {__float2half_rn(a0 - __half2float(h0v)),
                        __float2half_rn(a1 - __half2float(h1)),
                        __float2half_rn(a2 - __half2float(h2)),
                        __float2half_rn(a3 - __half2float(h3))};
        const int tile = v >> 8, rl = v & 255, chunk = k >> 6, kin = k & 63;
        char* blk = (char*)g_Bb + ((size_t)(tile * 16 + chunk)) * 65536;
        const uint32_t off = (uint32_t)((rl >> 6) * 8192) + SWZ((uint32_t)((rl & 63) * 128 + kin * 2));
        *(uint2*)(blk + off)         = *(uint2*)hs;
        *(uint2*)(blk + 32768 + off) = *(uint2*)ls;
    }
}

// ---- K1: pre-gates GEMM (fp16 split, 3 products) -> blocked g_pre ----
#define PRE_SMEM (3 * (1536 + 1536 + 3072 + 3072) * 2)
__global__ __launch_bounds__(256, 2)
void pre_mma_kernel(const float* __restrict__ bih, const float* __restrict__ bhh) {
    extern __shared__ __align__(16) char dsm[];
    __half* As_h = (__half*)dsm;
    __half* As_l = As_h + 3 * 1536;
    __half* Bs_h = As_l + 3 * 1536;
    __half* Bs_l = Bs_h + 3 * 3072;

    const int tid  = threadIdx.x;
    const int lane = tid & 31;
    const int warp = tid >> 5;
    const int wm   = warp >> 2;
    const int wn   = warp & 3;
    const int mblk = blockIdx.x * 64;
    const int nblk = blockIdx.y * 128;

    const __half* src[3];
    __half* arrb[3];
    int off3[3], strd[3];
#pragma unroll
    for (int s = 0; s < 3; s++) {
        int c = tid + s * 256;
        if (c < 128) {
            int row = c >> 1, col = (c & 1) * 8;
            src[s] = g_Xh + (long)(mblk + row) * EMB + col;
            arrb[s] = As_h; off3[s] = row * 24 + col; strd[s] = 1536;
        } else if (c < 256) {
            int r = c - 128, row = r >> 1, col = (r & 1) * 8;
            src[s] = g_Xl + (long)(mblk + row) * EMB + col;
            arrb[s] = As_l; off3[s] = row * 24 + col; strd[s] = 1536;
        } else if (c < 512) {
            int r = c - 256, row = r >> 1, col = (r & 1) * 8;
            src[s] = g_Wih_h + (long)(nblk + row) * EMB + col;
            arrb[s] = Bs_h; off3[s] = row * 24 + col; strd[s] = 3072;
        } else {
            int r = c - 512, row = r >> 1, col = (r & 1) * 8;
            src[s] = g_Wih_l + (long)(nblk + row) * EMB + col;
            arrb[s] = Bs_l; off3[s] = row * 24 + col; strd[s] = 3072;
        }
    }

    const int q = lane >> 3, r8 = lane & 7;
    const int rowA = (q & 1) * 8 + r8;
    const int colA = (q >> 1) * 8;
    const int rowB = (q >> 1) * 8 + r8;
    const int colB = (q & 1) * 8;

    float acc[2][4][4];
#pragma unroll
    for (int i = 0; i < 2; i++)
#pragma unroll
        for (int j = 0; j < 4; j++)
#pragma unroll
            for (int k = 0; k < 4; k++) acc[i][j][k] = 0.f;

#pragma unroll
    for (int p = 0; p < 2; p++) {
#pragma unroll
        for (int s = 0; s < 3; s++)
            cp16(arrb[s] + p * strd[s] + off3[s], src[s] + p * 16);
        cp_commit();
    }

    for (int kk = 0; kk < 32; kk++) {
        if (kk < 31) cp_wait<1>(); else cp_wait<0>();
        __syncthreads();
        if (kk + 2 < 32) {
            const int stg = (kk + 2) % 3;
#pragma unroll
            for (int s = 0; s < 3; s++)
                cp16(arrb[s] + stg * strd[s] + off3[s], src[s] + (kk + 2) * 16);
            cp_commit();
        }
        const int st = kk % 3;

        uint32_t aH[2][4], aL[2][4], bH[4][2], bL[4][2];
#pragma unroll
        for (int i = 0; i < 2; i++) {
            ldm4(aH[i][0], aH[i][1], aH[i][2], aH[i][3],
                 As_h + st * 1536 + (wm * 32 + i * 16 + rowA) * 24 + colA);
            ldm4(aL[i][0], aL[i][1], aL[i][2], aL[i][3],
                 As_l + st * 1536 + (wm * 32 + i * 16 + rowA) * 24 + colA);
        }
#pragma unroll
        for (int j2 = 0; j2 < 2; j2++) {
            ldm4(bH[j2 * 2][0], bH[j2 * 2][1], bH[j2 * 2 + 1][0], bH[j2 * 2 + 1][1],
                 Bs_h + st * 3072 + (wn * 32 + j2 * 16 + rowB) * 24 + colB);
            ldm4(bL[j2 * 2][0], bL[j2 * 2][1], bL[j2 * 2 + 1][0], bL[j2 * 2 + 1][1],
                 Bs_l + st * 3072 + (wn * 32 + j2 * 16 + rowB) * 24 + colB);
        }
#pragma unroll
        for (int i = 0; i < 2; i++)
#pragma unroll
            for (int j = 0; j < 4; j++) {
                mma16816(acc[i][j], aH[i], bH[j]);
                mma16816(acc[i][j], aH[i], bL[j]);
                mma16816(acc[i][j], aL[i], bH[j]);
            }
    }

    const int groupRow = lane >> 2;
    const int colPos   = lane & 3;
#pragma unroll
    for (int j = 0; j < 4; j++) {
        const int col  = nblk + wn * 32 + j * 8 + colPos * 2;
        const int gate = col >> 10;
        const int r10  = col & 1023;
        const int blk2 = r10 >> 3;
        const int u    = r10 & 7;
        const float bb0 = bih[col] + bhh[col];
        const float bb1 = bih[col + 1] + bhh[col + 1];
#pragma unroll
        for (int i = 0; i < 2; i++) {
#pragma unroll
            for (int half = 0; half < 2; half++) {
                const int m = mblk + wm * 32 + i * 16 + groupRow + half * 8;
                const int t = m >> 6, b = m & 63;
                float2 v;
                v.x = acc[i][j][half * 2]     * INV_SCALE + bb0;
                v.y = acc[i][j][half * 2 + 1] * INV_SCALE + bb1;
                *(float2*)(g_pre + (((size_t)(t * 128 + blk2) * 64 + b) * 32 + gate * 8 + u)) = v;
            }
        }
    }
}

// ---- K2: persistent LSTM (passing version, 8.9us/step) ----
#define LSTM_SMEM 216400
__global__ __launch_bounds__(256, 1)
void lstm_persistent_kernel(const float* __restrict__ c0) {
    extern __shared__ __align__(16) char smem[];
    __half* Ws_h = (__half*)smem;
    __half* Ws_l = Ws_h + 32 * 1032;
    float*  Gs   = (float*)(smem + 197632);
    float*  Cs   = (float*)(smem + 206080);
    float*  Ps   = (float*)(smem + 208128);
    const uint32_t sb  = (uint32_t)__cvta_generic_to_shared(smem);
    const uint32_t HS  = sb + 132096;
    const uint32_t PSA = sb + 208128;
    const uint32_t MBF = sb + 216320;
    const uint32_t MBP = sb + 216352;
    const uint32_t MBC = sb + 216360;

    const int tid  = threadIdx.x;
    const int lane = tid & 31;
    const int warp = tid >> 5;
    const int mw   = warp & 3;
    const int nh   = warp >> 2;
    const int blk  = blockIdx.x;

    for (int c = tid; c < 8192; c += 256) {
        const int split = c >> 12;
        const int rr    = (c >> 7) & 31;
        const int seg   = c & 127;
        const long nglob = (long)((rr >> 3) * 1024 + blk * 8 + (rr & 7));
        const __half* srcp = (split ? g_Whh_l : g_Whh_h) + nglob * HID + seg * 8;
        float4 v = *(const float4*)srcp;
        *(float4*)((split ? Ws_l : Ws_h) + rr * 1032 + seg * 8) = v;
    }
    for (int cell = tid; cell < 512; cell += 256) {
        const int b = cell >> 3, u = cell & 7;
        Cs[cell] = c0[b * HID + blk * 8 + u];
    }
    if (tid == 0) {
#pragma unroll
        for (int s = 0; s < 4; s++) MBAR_INIT(MBF + s * 8, 1);
        MBAR_INIT(MBP, 1);
#pragma unroll
        for (int s = 0; s < 4; s++) MBAR_INIT(MBC + s * 8, 8);
    }
    __syncthreads();

    const int q = lane >> 3, r8 = lane & 7;
    const int rowA = (q & 1) * 8 + r8;
    const int colA = (q >> 1) * 8;
    const int rowB = (q >> 1) * 8 + r8;
    const int colB = (q & 1) * 8;
    const int groupRow = lane >> 2;
    const int colPos   = lane & 3;

    const uint32_t aRowByte = (uint32_t)((mw * 16 + rowA) * 128 + colA * 2);
    const int c2 = blk >> 3;

    for (int t = 0; t < 63; t++) {
        const char* hsrc = t ? ((const char*)g_Hb + (size_t)(t - 1) * HB_STEP_BYTES)
                             : (const char*)g_H0b;

        if (tid == 0) {
#pragma unroll
            for (int m = 0; m < 3; m++) {
                const int F = t * 4;
                if (F) MBAR_WAIT(MBC + m * 8, (F - 1) & 1);
                MBAR_EXPECT(MBF + m * 8, HB_CHUNK_BYTES);
                bulkcp(HS + m * 16384, hsrc + (size_t)m * HB_CHUNK_BYTES,
                       HB_CHUNK_BYTES, MBF + m * 8);
            }
            MBAR_EXPECT(MBP, 8192);
            bulkcp(PSA, (const char*)g_pre + ((size_t)t * 128 + blk) * 8192, 8192, MBP);
        }

        float aHH[2][4], aHL[2][4], aLH[2][4];
#pragma unroll
        for (int j = 0; j < 2; j++)
#pragma unroll
            for (int k = 0; k < 4; k++) { aHH[j][k] = 0.f; aHL[j][k] = 0.f; aLH[j][k] = 0.f; }

        for (int c = 0; c < 16; c++) {
            if (tid == 0 && c + 3 < 16) {
                const int m = c + 3;
                const int s = m & 3;
                const int F = t * 4 + (m >> 2);
                if (F) MBAR_WAIT(MBC + s * 8, (F - 1) & 1);
                MBAR_EXPECT(MBF + s * 8, HB_CHUNK_BYTES);
                bulkcp(HS + s * 16384, hsrc + (size_t)m * HB_CHUNK_BYTES,
                       HB_CHUNK_BYTES, MBF + s * 8);
            }
            MBAR_WAIT(MBF + (c & 3) * 8, (c >> 2) & 1);
            __syncwarp();
            const uint32_t hb = HS + (c & 3) * 16384;

#pragma unroll
            for (int k16 = 0; k16 < 4; k16++) {
                uint32_t aH[4], aL[4], bH[2][2], bL[2][2];
                const uint32_t aoff = SWZ(aRowByte + (uint32_t)(k16 * 32));
                ldm4s(aH[0], aH[1], aH[2], aH[3], hb + aoff);
                ldm4s(aL[0], aL[1], aL[2], aL[3], hb + 8192 + aoff);
                ldm4(bH[0][0], bH[0][1], bH[1][0], bH[1][1],
                     Ws_h + (nh * 16 + rowB) * 1032 + c * 64 + k16 * 16 + colB);
                ldm4(bL[0][0], bL[0][1], bL[1][0], bL[1][1],
                     Ws_l + (nh * 16 + rowB) * 1032 + c * 64 + k16 * 16 + colB);
#pragma unroll
                for (int j = 0; j < 2; j++) {
                    mma16816(aHH[j], aH, bH[j]);
                    mma16816(aHL[j], aH, bL[j]);
                    mma16816(aLH[j], aL, bH[j]);
                }
            }
            __syncwarp();
            if (lane == 0) MBAR_ARRIVE(MBC + (c & 3) * 8);
        }

#pragma unroll
        for (int j = 0; j < 2; j++) {
            const int col = nh * 16 + j * 8 + colPos * 2;
            Gs[(mw * 16 + groupRow) * 33 + col]         = aHH[j][0] + aHL[j][0] + aLH[j][0];
            Gs[(mw * 16 + groupRow) * 33 + col + 1]     = aHH[j][1] + aHL[j][1] + aLH[j][1];
            Gs[(mw * 16 + groupRow + 8) * 33 + col]     = aHH[j][2] + aHL[j][2] + aLH[j][2];
            Gs[(mw * 16 + groupRow + 8) * 33 + col + 1] = aHH[j][3] + aHL[j][3] + aLH[j][3];
        }
        __syncthreads();
        MBAR_WAIT(MBP, t & 1);

        char* hdst = (char*)g_Hb + (size_t)t * HB_STEP_BYTES + (size_t)c2 * HB_CHUNK_BYTES;
        for (int cell = tid; cell < 512; cell += 256) {
            const int b = cell >> 3, u = cell & 7;
            const float gi = Gs[b * 33 + u]      * INV_SCALE + Ps[b * 32 + u];
            const float gf = Gs[b * 33 + 8 + u]  * INV_SCALE + Ps[b * 32 + 8 + u];
            const float gg = Gs[b * 33 + 16 + u] * INV_SCALE + Ps[b * 32 + 16 + u];
            const float go = Gs[b * 33 + 24 + u] * INV_SCALE + Ps[b * 32 + 24 + u];

            const float i_ = 1.f / (1.f + expf(-gi));
            const float f_ = 1.f / (1.f + expf(-gf));
            const float g_ = tanhf(gg);
            const float o_ = 1.f / (1.f + expf(-go));

            const float cN = f_ * Cs[cell] + i_ * g_;
            Cs[cell] = cN;
            const float h = o_ * tanhf(cN);

            const float a = h * SCALE_A;
            const __half hh = __float2half_rn(a);
            const __half hl = __float2half_rn(a - __half2float(hh));
            const int inner = (blk & 7) * 8 + u;
            const uint32_t off = SWZ((uint32_t)(b * 128 + inner * 2));
            *(__half*)(hdst + off)        = hh;
            *(__half*)(hdst + 8192 + off) = hl;
        }

        __syncthreads();
        if (tid == 0) {
            asm volatile("fence.proxy.async;" ::: "memory");
            __threadfence();
            atomicAdd(&g_bar, 1u);
            volatile unsigned* p = &g_bar;
            const unsigned target = (unsigned)(t + 1) * NBLK;
            while (*p < target) { __nanosleep(32); }
            __threadfence();
            asm volatile("fence.proxy.async;" ::: "memory");
        }
        __syncthreads();
    }
}

// ---- K3: logits GEMM 128x256, 512 thr, bulkcp producer/consumer pipeline ----
#define LOG_STG   98304
#define LOG_TAIL  196608
#define LOG_SMEM  (LOG_TAIL + 1024 + 512 + 4 * 2048 + 512 + 64)
__global__ __launch_bounds__(512, 1)
void logits_mma_kernel(const float* __restrict__ bout, const int* __restrict__ ot) {
    extern __shared__ __align__(16) char dsm[];
    const uint32_t sb = (uint32_t)__cvta_generic_to_shared(dsm);
    float* bout_s    = (float*)(dsm + LOG_TAIL);
    int*   labels_s  = (int*)(dsm + LOG_TAIL + 1024);
    float* wmax      = (float*)(dsm + LOG_TAIL + 1536);
    int*   warg      = (int*)(dsm + LOG_TAIL + 1536 + 2048);
    float* wsum      = (float*)(dsm + LOG_TAIL + 1536 + 4096);
    float* wlab      = (float*)(dsm + LOG_TAIL + 1536 + 6144);
    float* rowmax_s  = (float*)(dsm + LOG_TAIL + 1536 + 8192);
    const uint32_t MBFL = sb + LOG_TAIL + 1536 + 8192 + 512;
    const uint32_t MBCN = MBFL + 16;

    const int tid  = threadIdx.x;
    const int lane = tid & 31;
    const int warp = tid >> 5;
    const int wm   = warp >> 2;
    const int wn   = warp & 3;
    const int mblk = blockIdx.x * 128;
    const int nblk = blockIdx.y * 256;

    if (tid < 256) bout_s[tid] = bout[nblk + tid];
    if (tid < 128) labels_s[tid] = (mblk + tid < M_ROWS) ? ot[64 + mblk + tid] : -1;
    if (tid == 0) {
        MBAR_INIT(MBFL, 1);     MBAR_INIT(MBFL + 8, 1);
        MBAR_INIT(MBCN, 16);    MBAR_INIT(MBCN + 8, 16);
    }
    __syncthreads();

    int s0 = blockIdx.x * 2;     if (s0 > 62) s0 = 62;
    int s1 = blockIdx.x * 2 + 1; if (s1 > 62) s1 = 62;
    const char* a0 = (const char*)g_Hb + (size_t)s0 * HB_STEP_BYTES;
    const char* a1 = (const char*)g_Hb + (size_t)s1 * HB_STEP_BYTES;
    const char* bb = (const char*)g_Bb + (size_t)(blockIdx.y * 16) * 65536;

    if (tid == 0) {
#pragma unroll
        for (int p = 0; p < 2; p++) {
            const uint32_t stg = sb + p * LOG_STG;
            MBAR_EXPECT(MBFL + p * 8, 98304);
            bulkcp(stg,         a0 + (size_t)p * HB_CHUNK_BYTES, 16384, MBFL + p * 8);
            bulkcp(stg + 16384, a1 + (size_t)p * HB_CHUNK_BYTES, 16384, MBFL + p * 8);
            bulkcp(stg + 32768, bb + (size_t)p * 65536,          65536, MBFL + p * 8);
        }
    }

    const int q = lane >> 3, r8 = lane & 7;
    const int rowA = (q & 1) * 8 + r8;
    const int colA = (q >> 1) * 8;
    const int rowB = (q >> 1) * 8 + r8;
    const int colB = (q & 1) * 8;

    const uint32_t aStageOff  = (uint32_t)((wm >> 1) * 16384);
    const uint32_t aRowByte   = (uint32_t)(((wm & 1) * 32 + rowA) * 128 + colA * 2);
    const uint32_t bRowByteBase = (uint32_t)((wn * 64 + rowB) * 128 + colB * 2);

    float acc[2][8][4];
#pragma unroll
    for (int i = 0; i < 2; i++)
#pragma unroll
        for (int j = 0; j < 8; j++)
#pragma unroll
            for (int k = 0; k < 4; k++) acc[i][j][k] = 0.f;

    for (int c = 0; c < 16; c++) {
        MBAR_WAIT(MBFL + (c & 1) * 8, (c >> 1) & 1);
        __syncwarp();
        const uint32_t stg = sb + (c & 1) * LOG_STG;
        const uint32_t aBaseS = stg + aStageOff;
        const uint32_t bBaseS = stg + 32768;

#pragma unroll
        for (int k16 = 0; k16 < 4; k16++) {
            uint32_t aH[2][4], aL[2][4];
#pragma unroll
            for (int i = 0; i < 2; i++) {
                const uint32_t ao = SWZ(aRowByte + (uint32_t)(i * 16 * 128 + k16 * 32));
                ldm4s(aH[i][0], aH[i][1], aH[i][2], aH[i][3], aBaseS + ao);
                ldm4s(aL[i][0], aL[i][1], aL[i][2], aL[i][3], aBaseS + 8192 + ao);
            }
#pragma unroll
            for (int j2 = 0; j2 < 4; j2++) {
                uint32_t bH[2][2], bL[2][2];
                const uint32_t bo = SWZ(bRowByteBase + (uint32_t)(j2 * 16 * 128 + k16 * 32));
                ldm4s(bH[0][0], bH[0][1], bH[1][0], bH[1][1], bBaseS + bo);
                ldm4s(bL[0][0], bL[0][1], bL[1][0], bL[1][1], bBaseS + 32768 + bo);
#pragma unroll
                for (int i = 0; i < 2; i++)
#pragma unroll
                    for (int jj = 0; jj < 2; jj++) {
                        mma16816(acc[i][j2 * 2 + jj], aH[i], bH[jj]);
                        mma16816(acc[i][j2 * 2 + jj], aH[i], bL[jj]);
                        mma16816(acc[i][j2 * 2 + jj], aL[i], bH[jj]);
                    }
            }
        }
        __syncwarp();
        if (lane == 0) MBAR_ARRIVE(MBCN + (c & 1) * 8);
        if (tid == 0 && c + 2 < 16) {
            MBAR_WAIT(MBCN + (c & 1) * 8, (c >> 1) & 1);
            const uint32_t stg2 = sb + (c & 1) * LOG_STG;
            MBAR_EXPECT(MBFL + (c & 1) * 8, 98304);
            bulkcp(stg2,         a0 + (size_t)(c + 2) * HB_CHUNK_BYTES, 16384, MBFL + (c & 1) * 8);
            bulkcp(stg2 + 16384, a1 + (size_t)(c + 2) * HB_CHUNK_BYTES, 16384, MBFL + (c & 1) * 8);
            bulkcp(stg2 + 32768, bb + (size_t)(c + 2) * 65536,          65536, MBFL + (c & 1) * 8);
        }
    }

    const int groupRow = lane >> 2;
    const int colPos   = lane & 3;

#pragma unroll
    for (int i = 0; i < 2; i++) {
#pragma unroll
        for (int half = 0; half < 2; half++) {
            const int row_local = wm * 32 + i * 16 + groupRow + half * 8;
            const int lbl = labels_s[row_local];
            float mv = -1e30f; int ma = 0x7fffffff; float lv = -1e30f;
#pragma unroll
            for (int j = 0; j < 8; j++) {
#pragma unroll
                for (int kb = 0; kb < 2; kb++) {
                    const int cl = wn * 64 + j * 8 + colPos * 2 + kb;
                    const float v = acc[i][j][half * 2 + kb] * INV_SCALE + bout_s[cl];
                    const int colg = nblk + cl;
                    if (v > mv) { mv = v; ma = colg; }
                    if (colg == lbl) lv = v;
                }
            }
#pragma unroll
            for (int m = 1; m < 4; m <<= 1) {
                const float ov = __shfl_xor_sync(0xffffffffu, mv, m);
                const int   oa = __shfl_xor_sync(0xffffffffu, ma, m);
                const float ol = __shfl_xor_sync(0xffffffffu, lv, m);
                if (ov > mv || (ov == mv && oa < ma)) { mv = ov; ma = oa; }
                lv = fmaxf(lv, ol);
            }
            if (colPos == 0) {
                wmax[row_local * 4 + wn] = mv;
                warg[row_local * 4 + wn] = ma;
                wlab[row_local * 4 + wn] = lv;
            }
        }
    }
    __syncthreads();

    if (tid < 128) {
        float mv = wmax[tid * 4]; int ma = warg[tid * 4]; float lv = wlab[tid * 4];
#pragma unroll
        for (int x = 1; x < 4; x++) {
            const float v = wmax[tid * 4 + x]; const int a = warg[tid * 4 + x];
            if (v > mv || (v == mv && a < ma)) { mv = v; ma = a; }
            lv = fmaxf(lv, wlab[tid * 4 + x]);
        }
        rowmax_s[tid] = mv;
        if (mblk + tid < M_ROWS) {
            const long p = (long)(mblk + tid) * NCHUNK + blockIdx.y;
            g_pmax[p] = mv;
            g_parg[p] = ma;
            g_plab[p] = lv;
        }
    }
    __syncthreads();

#pragma unroll
    for (int i = 0; i < 2; i++) {
#pragma unroll
        for (int half = 0; half < 2; half++) {
            const int row_local = wm * 32 + i * 16 + groupRow + half * 8;
            const float rm = rowmax_s[row_local];
            float s = 0.f;
#pragma unroll
            for (int j = 0; j < 8; j++)
#pragma unroll
                for (int kb = 0; kb < 2; kb++) {
                    const int cl = wn * 64 + j * 8 + colPos * 2 + kb;
                    s += __expf(acc[i][j][half * 2 + kb] * INV_SCALE + bout_s[cl] - rm);
                }
#pragma unroll
            for (int m = 1; m < 4; m <<= 1)
                s += __shfl_xor_sync(0xffffffffu, s, m);
            if (colPos == 0) wsum[row_local * 4 + wn] = s;
        }
    }
    __syncthreads();

    if (tid < 128 && mblk + tid < M_ROWS) {
        float s = wsum[tid * 4] + wsum[tid * 4 + 1] + wsum[tid * 4 + 2] + wsum[tid * 4 + 3];
        g_psum[(long)(mblk + tid) * NCHUNK + blockIdx.y] = s;
    }
}

// ---- K4: per-row cross-chunk reduction ----
__global__ void reduce_rows_kernel(float* __restrict__ out) {
    const int m = blockIdx.x;
    const int tid = threadIdx.x;
    const long base = (long)m * NCHUNK;

    float mv = -1e30f; int ma = 0x7fffffff;
    for (int c = tid; c < NCHUNK; c += 128) {
        const float v = g_pmax[base + c];
        const int   a = g_parg[base + c];
        if (v > mv || (v == mv && a < ma)) { mv = v; ma = a; }
    }
    __shared__ float sv[128]; __shared__ int sa[128];
    sv[tid] = mv; sa[tid] = ma;
    __syncthreads();
    for (int off = 64; off > 0; off >>= 1) {
        if (tid < off) {
            const float v = sv[tid + off]; const int a = sa[tid + off];
            if (v > sv[tid] || (v == sv[tid] && a < sa[tid])) { sv[tid] = v; sa[tid] = a; }
        }
        __syncthreads();
    }
    const float gmax = sv[0];
    const int   garg = sa[0];
    __syncthreads();

    float ssum = 0.f, lab = -1e30f;
    for (int c = tid; c < NCHUNK; c += 128) {
        ssum += g_psum[base + c] * __expf(g_pmax[base + c] - gmax);
        lab = fmaxf(lab, g_plab[base + c]);
    }
    __shared__ float s2[128]; __shared__ float s3[128];
    s2[tid] = ssum; s3[tid] = lab;
    __syncthreads();
    for (int off = 64; off > 0; off >>= 1) {
        if (tid < off) {
            s2[tid] += s2[tid + off];
            s3[tid] = fmaxf(s3[tid], s3[tid + off]);
        }
        __syncthreads();
    }

    if (tid == 0) {
        const float lse = gmax + logf(s2[0]);
        g_nll[m] = lse - s3[0];
        out[65 + m] = (float)garg;
    }
}

// ---- K5: loss assembly + first result row ----
__global__ void finalize_kernel(const int* __restrict__ ot, float* __restrict__ out) {
    const int tid = threadIdx.x;
    __shared__ float ps[64];
    if (tid < 64) out[1 + tid] = 1.0f;
    if (tid < 63) {
        float s = 0.f, cnt = 0.f;
        for (int b = 0; b < 64; b++) {
            const int lbl = ot[(tid + 1) * 64 + b];
            if (lbl != 0) { s += g_nll[tid * 64 + b]; cnt += 1.f; }
        }
        ps[tid] = s / fmaxf(cnt, 1.f);
    }
    __syncthreads();
    if (tid == 0) {
        float loss = 0.f;
        for (int t = 0; t < 63; t++) loss += ps[t];
        out[0] = loss;
    }
}

// ---- entry point ----
extern "C" void kernel_launch(void* const* d_in, const int* in_sizes, int n_in,
                              void* d_out, int out_size) {
    const int*   ot   = (const int*)  d_in[0];
    const float* h0   = (const float*)d_in[3];
    const float* c0   = (const float*)d_in[4];
    const float* emb  = (const float*)d_in[5];
    const float* Wih  = (const float*)d_in[6];
    const float* Whh  = (const float*)d_in[7];
    const float* bih  = (const float*)d_in[8];
    const float* bhh  = (const float*)d_in[9];
    const float* Wout = (const float*)d_in[10];
    const float* bout = (const float*)d_in[11];
    float* out = (float*)d_out;

    cudaFuncSetAttribute(lstm_persistent_kernel,
                         cudaFuncAttributeMaxDynamicSharedMemorySize, LSTM_SMEM);
    cudaFuncSetAttribute(pre_mma_kernel,
                         cudaFuncAttributeMaxDynamicSharedMemorySize, PRE_SMEM);
    cudaFuncSetAttribute(logits_mma_kernel,
                         cudaFuncAttributeMaxDynamicSharedMemorySize, LOG_SMEM);

    prep_all_kernel<<<(VOCAB * HID / 4) / 256, 256>>>(ot, emb, Wih, Whh, h0, Wout);
    pre_mma_kernel<<<dim3(63, 32), 256, PRE_SMEM>>>(bih, bhh);
    lstm_persistent_kernel<<<NBLK, 256, LSTM_SMEM>>>(c0);
    logits_mma_kernel<<<dim3(32, 125), 512, LOG_SMEM>>>(bout, ot);
    reduce_rows_kernel<<<4032, 128>>>(out);
    finalize_kernel<<<1, 64>>>(ot, out);
}